// round 7
// baseline (speedup 1.0000x reference)
#include <cuda_runtime.h>
#include <float.h>
#include <stdint.h>

#define NODES 65536
#define HD 128
#define THREADS 256
#define TS 132                       // smem row stride (floats) for edge sT/sW
#define NTS 36                       // smem row stride (floats) for node GEMM chunks
#define MAXEDGES (1048576 + NODES)
#define GRID_EDGE 152

// persistent edge kernel smem map
#define TILE_BYTES (128 * TS * 4)    // 67584
#define SM_T0 2048
#define SM_T1 (2048 + TILE_BYTES)
#define SM_W  (2048 + 2 * TILE_BYTES)
#define EDGE_SMEM (2048 + 3 * TILE_BYTES)   // 204800 B

// node GEMM smem: 4 chunk buffers + bias
#define GEMM_SMEM (4 * 128 * NTS * 4 + 512)

// ---------------- scratch ----------------
__device__ float g_A[(size_t)NODES * HD];
__device__ float g_B[(size_t)NODES * HD];
__device__ float g_agg[(size_t)NODES * HD];
__device__ float g_h0[(size_t)NODES * HD];
__device__ float g_tmp[(size_t)NODES * HD];
__device__ float g_w2t[HD * HD];       // W2^T, tf32-rounded, [n][k]
__device__ float g_wth[256 * HD];      // node GEMM W^T hi split
__device__ float g_wtl[256 * HD];      // node GEMM W^T lo split
__device__ int g_cnt[NODES];
__device__ int g_next[NODES];
__device__ int g_ssrc[MAXEDGES];
__device__ int g_sdst[MAXEDGES];

__global__ __launch_bounds__(THREADS) void fill_kernel(float4* p, float v, int n4) {
    int i = blockIdx.x * blockDim.x + threadIdx.x;
    if (i < n4) p[i] = make_float4(v, v, v, v);
}

__global__ __launch_bounds__(THREADS) void zero_i32(int* p, int n) {
    int i = blockIdx.x * blockDim.x + threadIdx.x;
    if (i < n) p[i] = 0;
}

// ---------------- counting sort by dst (once per launch) ----------------
__global__ __launch_bounds__(THREADS) void hist_kernel(
    const int* __restrict__ ei, int* __restrict__ cnt, int E, int total)
{
    int e = blockIdx.x * blockDim.x + threadIdx.x;
    if (e < total) {
        int d = (e < E) ? ei[E + e] : (e - E);
        atomicAdd(&cnt[d], 1);
    }
}

#define SCAN_T 1024
#define CHUNK (NODES / SCAN_T)   // 64
__global__ __launch_bounds__(SCAN_T) void scan_kernel(
    const int* __restrict__ cnt, int* __restrict__ next)
{
    __shared__ int part[SCAN_T];
    int t = threadIdx.x;
    int base = t * CHUNK;
    int sum = 0;
#pragma unroll 4
    for (int i = 0; i < CHUNK; i++) sum += cnt[base + i];
    part[t] = sum;
    __syncthreads();
    for (int off = 1; off < SCAN_T; off <<= 1) {
        int v = (t >= off) ? part[t - off] : 0;
        __syncthreads();
        part[t] += v;
        __syncthreads();
    }
    int off = part[t] - sum;   // exclusive
#pragma unroll 4
    for (int i = 0; i < CHUNK; i++) {
        next[base + i] = off;
        off += cnt[base + i];
    }
}

__global__ __launch_bounds__(THREADS) void scatter_kernel(
    const int* __restrict__ ei, int* __restrict__ next,
    int* __restrict__ ssrc, int* __restrict__ sdst, int E, int total)
{
    int e = blockIdx.x * blockDim.x + threadIdx.x;
    if (e < total) {
        int s, d;
        if (e < E) { s = ei[e]; d = ei[E + e]; }
        else       { s = e - E; d = s; }
        int pos = atomicAdd(&next[d], 1);
        ssrc[pos] = s;
        sdst[pos] = d;
    }
}

// W2[k][n] -> W2T[n][k], tf32-rounded (edge kernel weight)
__global__ __launch_bounds__(HD) void prep_w2t_kernel(
    const float* __restrict__ W2, float* __restrict__ out)
{
    int n = blockIdx.x, k = threadIdx.x;
    float v = W2[k * HD + n];
    asm("cvt.rna.tf32.f32 %0, %0;" : "+f"(v));
    out[n * HD + k] = v;
}

// W[k][n] (Ktot x 128) -> WT_hi/lo[n][k], tf32 hi/lo split (node GEMM weights)
__global__ __launch_bounds__(HD) void prep_wt_kernel(
    const float* __restrict__ W, float* __restrict__ wth,
    float* __restrict__ wtl, int Ktot)
{
    int k = blockIdx.x, n = threadIdx.x;
    float v = W[k * HD + n];
    float hi = v;
    asm("cvt.rna.tf32.f32 %0, %0;" : "+f"(hi));
    float lo = v - hi;
    asm("cvt.rna.tf32.f32 %0, %0;" : "+f"(lo));
    wth[n * Ktot + k] = hi;
    wtl[n * Ktot + k] = lo;
}

// ---------------- mma helpers ----------------
__device__ __forceinline__ void mma_tf32(float* d, const uint32_t* a, const uint32_t* b) {
    asm volatile(
        "mma.sync.aligned.m16n8k8.row.col.f32.tf32.tf32.f32 "
        "{%0,%1,%2,%3}, {%4,%5,%6,%7}, {%8,%9}, {%0,%1,%2,%3};"
        : "+f"(d[0]), "+f"(d[1]), "+f"(d[2]), "+f"(d[3])
        : "r"(a[0]), "r"(a[1]), "r"(a[2]), "r"(a[3]), "r"(b[0]), "r"(b[1]));
}

__device__ __forceinline__ void atomic_fmax(float* p, float v) {
    if (v >= 0.f) atomicMax((int*)p, __float_as_int(v));
    else          atomicMin((unsigned int*)p, __float_as_uint(v));
}

// ---------------- node GEMM: tf32 split mma ----------------
// Out[M,128] = act( concat(In0,In1)[M,Ktot] @ W[Ktot,128] + bias )
// Weights pre-transposed+split in WTh/WTl [n][k]. fp32-level accuracy via
// 3-term split: hi*Whi + lo*Whi + hi*Wlo.
__global__ __launch_bounds__(THREADS) void gemm_mma_kernel(
    const float* __restrict__ In0, const float* __restrict__ In1,
    const float* __restrict__ WTh, const float* __restrict__ WTl,
    const float* __restrict__ bias, float* __restrict__ Out,
    int Ktot, int relu_out)
{
    extern __shared__ float sm[];
    float* sAh = sm;
    float* sAl = sm + 128 * NTS;
    float* sBh = sm + 2 * 128 * NTS;
    float* sBl = sm + 3 * 128 * NTS;
    float* sBias = sm + 4 * 128 * NTS;

    int tid = threadIdx.x;
    int lane = tid & 31, wid = tid >> 5;
    int rowBase = blockIdx.x * 128;

    if (tid < 128) sBias[tid] = bias ? bias[tid] : 0.f;

    int r = tid >> 1, h16 = tid & 1;
    int warpRow = (wid & 1) * 64;
    int warpCol = (wid >> 1) * 32;
    int g = lane >> 2, tg = lane & 3;

    // cp.async dst addresses (constant across chunks; single-buffered)
    uint32_t bh_dst, bl_dst;
    {
        uint32_t sb;
        asm("{ .reg .u64 t; cvta.to.shared.u64 t, %1; cvt.u32.u64 %0, t; }"
            : "=r"(sb) : "l"(sBh));
        bh_dst = sb + (uint32_t)(r * NTS + h16 * 16) * 4;
        asm("{ .reg .u64 t; cvta.to.shared.u64 t, %1; cvt.u32.u64 %0, t; }"
            : "=r"(sb) : "l"(sBl));
        bl_dst = sb + (uint32_t)(r * NTS + h16 * 16) * 4;
    }

    float acc[4][4][4];
#pragma unroll
    for (int i = 0; i < 4; i++)
#pragma unroll
        for (int j = 0; j < 4; j++)
#pragma unroll
            for (int q = 0; q < 4; q++) acc[i][j][q] = 0.f;

    int nchunks = Ktot >> 5;
    for (int c = 0; c < nchunks; c++) {
        int kk = c * 32;

        // B chunk: straight copy via cp.async (already split in global)
        {
            const float* srch = WTh + (size_t)r * Ktot + kk + h16 * 16;
            const float* srcl = WTl + (size_t)r * Ktot + kk + h16 * 16;
#pragma unroll
            for (int j = 0; j < 4; j++) {
                asm volatile("cp.async.cg.shared.global [%0], [%1], 16;"
                             :: "r"(bh_dst + j * 16), "l"(srch + j * 4));
                asm volatile("cp.async.cg.shared.global [%0], [%1], 16;"
                             :: "r"(bl_dst + j * 16), "l"(srcl + j * 4));
            }
            asm volatile("cp.async.commit_group;" ::: "memory");
        }

        // A chunk: LDG + hi/lo split + STS
        {
            const float* src = (kk < 128)
                ? (In0 + (size_t)(rowBase + r) * HD + kk + h16 * 16)
                : (In1 + (size_t)(rowBase + r) * HD + (kk - 128) + h16 * 16);
            float* dh = sAh + r * NTS + h16 * 16;
            float* dl = sAl + r * NTS + h16 * 16;
#pragma unroll
            for (int j = 0; j < 4; j++) {
                float4 v = *(const float4*)(src + j * 4);
                float4 hi = v, lo;
                asm("cvt.rna.tf32.f32 %0, %0;" : "+f"(hi.x));
                asm("cvt.rna.tf32.f32 %0, %0;" : "+f"(hi.y));
                asm("cvt.rna.tf32.f32 %0, %0;" : "+f"(hi.z));
                asm("cvt.rna.tf32.f32 %0, %0;" : "+f"(hi.w));
                lo.x = v.x - hi.x; lo.y = v.y - hi.y;
                lo.z = v.z - hi.z; lo.w = v.w - hi.w;
                asm("cvt.rna.tf32.f32 %0, %0;" : "+f"(lo.x));
                asm("cvt.rna.tf32.f32 %0, %0;" : "+f"(lo.y));
                asm("cvt.rna.tf32.f32 %0, %0;" : "+f"(lo.z));
                asm("cvt.rna.tf32.f32 %0, %0;" : "+f"(lo.w));
                *(float4*)(dh + j * 4) = hi;
                *(float4*)(dl + j * 4) = lo;
            }
        }

        asm volatile("cp.async.wait_group 0;" ::: "memory");
        __syncthreads();

        const uint32_t* sAhu = (const uint32_t*)sAh;
        const uint32_t* sAlu = (const uint32_t*)sAl;
        const uint32_t* sBhu = (const uint32_t*)sBh;
        const uint32_t* sBlu = (const uint32_t*)sBl;

#pragma unroll
        for (int ks = 0; ks < 4; ks++) {
            int k2 = ks * 8;
            uint32_t bh[4][2], bl[4][2];
#pragma unroll
            for (int nf = 0; nf < 4; nf++) {
                int n = warpCol + nf * 8 + g;
                bh[nf][0] = sBhu[n * NTS + k2 + tg];
                bh[nf][1] = sBhu[n * NTS + k2 + tg + 4];
                bl[nf][0] = sBlu[n * NTS + k2 + tg];
                bl[nf][1] = sBlu[n * NTS + k2 + tg + 4];
            }
            uint32_t ah[4][4], al[4][4];
#pragma unroll
            for (int mf = 0; mf < 4; mf++) {
                int rr = warpRow + mf * 16 + g;
                ah[mf][0] = sAhu[rr * NTS + k2 + tg];
                ah[mf][1] = sAhu[(rr + 8) * NTS + k2 + tg];
                ah[mf][2] = sAhu[rr * NTS + k2 + tg + 4];
                ah[mf][3] = sAhu[(rr + 8) * NTS + k2 + tg + 4];
                al[mf][0] = sAlu[rr * NTS + k2 + tg];
                al[mf][1] = sAlu[(rr + 8) * NTS + k2 + tg];
                al[mf][2] = sAlu[rr * NTS + k2 + tg + 4];
                al[mf][3] = sAlu[(rr + 8) * NTS + k2 + tg + 4];
            }
#pragma unroll
            for (int mf = 0; mf < 4; mf++)
#pragma unroll
                for (int nf = 0; nf < 4; nf++) {
                    mma_tf32(acc[mf][nf], ah[mf], bh[nf]);
                    mma_tf32(acc[mf][nf], al[mf], bh[nf]);
                    mma_tf32(acc[mf][nf], ah[mf], bl[nf]);
                }
        }
        __syncthreads();
    }

    // Epilogue: bias (+relu) and direct stores
#pragma unroll
    for (int mf = 0; mf < 4; mf++) {
        size_t r0 = (size_t)rowBase + warpRow + mf * 16 + g;
#pragma unroll
        for (int nf = 0; nf < 4; nf++) {
            int c0 = warpCol + nf * 8 + 2 * tg;
            float b0 = sBias[c0], b1 = sBias[c0 + 1];
            float o0 = acc[mf][nf][0] + b0, o1 = acc[mf][nf][1] + b1;
            float o2 = acc[mf][nf][2] + b0, o3 = acc[mf][nf][3] + b1;
            if (relu_out) {
                o0 = fmaxf(o0, 0.f); o1 = fmaxf(o1, 0.f);
                o2 = fmaxf(o2, 0.f); o3 = fmaxf(o3, 0.f);
            }
            *(float2*)(Out + r0 * HD + c0)       = make_float2(o0, o1);
            *(float2*)(Out + (r0 + 8) * HD + c0) = make_float2(o2, o3);
        }
    }
}

// ---------------- persistent edge kernel (unchanged from R6) ----------------
struct GReg {
    float4 a[8], b[8];
    int d, r;
    bool valid;
};

__device__ __forceinline__ void gather_issue(
    int eBase, int pass, GReg& G,
    const int* __restrict__ ssrc, const int* __restrict__ sdst,
    const float* __restrict__ A, const float* __restrict__ B,
    int total, int tid)
{
    int r = pass * 64 + (tid >> 2);
    int q = tid & 3;
    int e = eBase + r;
    G.valid = (e < total);
    int s = 0, d = 0;
    if (G.valid) { s = ssrc[e]; d = sdst[e]; }
    G.d = d; G.r = r;
    const float4* Ar = (const float4*)(A + (size_t)s * HD) + q;
    const float4* Br = (const float4*)(B + (size_t)d * HD) + q;
#pragma unroll
    for (int i = 0; i < 8; i++) {
        G.a[i] = Ar[i * 4];
        G.b[i] = Br[i * 4];
    }
}

__device__ __forceinline__ void gather_commit(
    const GReg& G, float* __restrict__ sTn, int* __restrict__ sDn, int tid)
{
    int q = tid & 3;
    if (q == 0) sDn[G.r] = G.valid ? G.d : -1;
    float* Tr = sTn + G.r * TS + q * 4;
#pragma unroll
    for (int i = 0; i < 8; i++) {
        float4 t;
        t.x = G.valid ? fmaxf(G.a[i].x - G.b[i].x, 0.f) : 0.f;
        t.y = G.valid ? fmaxf(G.a[i].y - G.b[i].y, 0.f) : 0.f;
        t.z = G.valid ? fmaxf(G.a[i].z - G.b[i].z, 0.f) : 0.f;
        t.w = G.valid ? fmaxf(G.a[i].w - G.b[i].w, 0.f) : 0.f;
        asm("cvt.rna.tf32.f32 %0, %0;" : "+f"(t.x));
        asm("cvt.rna.tf32.f32 %0, %0;" : "+f"(t.y));
        asm("cvt.rna.tf32.f32 %0, %0;" : "+f"(t.z));
        asm("cvt.rna.tf32.f32 %0, %0;" : "+f"(t.w));
        *(float4*)(Tr + i * 16) = t;
    }
}

__device__ __forceinline__ void mma_half(
    const float* __restrict__ sT, const float* __restrict__ sW,
    int kk0, float acc[4][4][4], int rowBase, int colBase, int g, int tg)
{
    const uint32_t* sTu = (const uint32_t*)sT;
    const uint32_t* sWu = (const uint32_t*)sW;
#pragma unroll
    for (int ks = 0; ks < 8; ks++) {
        int kk = kk0 + ks * 8;
        uint32_t b[4][2];
#pragma unroll
        for (int nf = 0; nf < 4; nf++) {
            int n = colBase + nf * 8 + g;
            b[nf][0] = sWu[n * TS + kk + tg];
            b[nf][1] = sWu[n * TS + kk + tg + 4];
        }
        uint32_t a[4][4];
#pragma unroll
        for (int mf = 0; mf < 4; mf++) {
            int r = rowBase + mf * 16 + g;
            a[mf][0] = sTu[r * TS + kk + tg];
            a[mf][1] = sTu[(r + 8) * TS + kk + tg];
            a[mf][2] = sTu[r * TS + kk + tg + 4];
            a[mf][3] = sTu[(r + 8) * TS + kk + tg + 4];
        }
#pragma unroll
        for (int mf = 0; mf < 4; mf++)
#pragma unroll
            for (int nf = 0; nf < 4; nf++)
                mma_tf32(acc[mf][nf], a[mf], b[nf]);
    }
}

__global__ __launch_bounds__(THREADS, 1) void edge_mma_kernel(
    const int* __restrict__ ssrc, const int* __restrict__ sdst,
    const float* __restrict__ A, const float* __restrict__ B,
    const float* __restrict__ W2T, const float* __restrict__ b2,
    float* __restrict__ agg, int total)
{
    extern __shared__ char smem[];
    int* sDst0 = (int*)smem;
    int* sDst1 = (int*)(smem + 512);
    float* sBias = (float*)(smem + 1024);
    float* sT0 = (float*)(smem + SM_T0);
    float* sT1 = (float*)(smem + SM_T1);
    float* sW  = (float*)(smem + SM_W);

    int tid = threadIdx.x;
    int lane = tid & 31, wid = tid >> 5;
    int ntiles = (total + 127) >> 7;

    {
        uint32_t sw_base;
        asm("{ .reg .u64 t; cvta.to.shared.u64 t, %1; cvt.u32.u64 %0, t; }"
            : "=r"(sw_base) : "l"(sW));
#pragma unroll
        for (int it = 0; it < 16; it++) {
            int linear = tid + it * THREADS;
            int n = linear >> 5, c4 = linear & 31;
            uint32_t dst = sw_base + (uint32_t)(n * TS + c4 * 4) * 4;
            asm volatile("cp.async.cg.shared.global [%0], [%1], 16;"
                         :: "r"(dst), "l"(W2T + (size_t)linear * 4));
        }
        asm volatile("cp.async.commit_group;" ::: "memory");
    }
    if (tid < 128) sBias[tid] = b2[tid];

    if (blockIdx.x < ntiles) {
        GReg G;
        gather_issue(blockIdx.x * 128, 0, G, ssrc, sdst, A, B, total, tid);
        gather_commit(G, sT0, sDst0, tid);
        gather_issue(blockIdx.x * 128, 1, G, ssrc, sdst, A, B, total, tid);
        gather_commit(G, sT0, sDst0, tid);
    }
    asm volatile("cp.async.wait_group 0;" ::: "memory");
    __syncthreads();

    int rowBase = (wid & 1) * 64;
    int colBase = (wid >> 1) * 32;
    int g = lane >> 2, tg = lane & 3;

    int buf = 0;
    for (int ti = blockIdx.x; ti < ntiles; ti += GRID_EDGE) {
        float* sTc = buf ? sT1 : sT0;
        float* sTn = buf ? sT0 : sT1;
        int* sDc = buf ? sDst1 : sDst0;
        int* sDn = buf ? sDst0 : sDst1;
        int tn = ti + GRID_EDGE;
        bool hn = tn < ntiles;

        float acc[4][4][4];
#pragma unroll
        for (int i = 0; i < 4; i++)
#pragma unroll
            for (int j = 0; j < 4; j++)
#pragma unroll
                for (int q = 0; q < 4; q++) acc[i][j][q] = 0.f;

        GReg G;
        if (hn) gather_issue(tn * 128, 0, G, ssrc, sdst, A, B, total, tid);
        mma_half(sTc, sW, 0, acc, rowBase, colBase, g, tg);
        if (hn) {
            gather_commit(G, sTn, sDn, tid);
            gather_issue(tn * 128, 1, G, ssrc, sdst, A, B, total, tid);
        }
        mma_half(sTc, sW, 64, acc, rowBase, colBase, g, tg);
        if (hn) gather_commit(G, sTn, sDn, tid);

        __syncthreads();

#pragma unroll
        for (int mf = 0; mf < 4; mf++) {
            int r0 = rowBase + mf * 16 + g;
#pragma unroll
            for (int nf = 0; nf < 4; nf++) {
                int c0 = colBase + nf * 8 + 2 * tg;
                float b0 = sBias[c0], b1 = sBias[c0 + 1];
                *(float2*)(sTc + r0 * TS + c0) =
                    make_float2(acc[mf][nf][0] + b0, acc[mf][nf][1] + b1);
                *(float2*)(sTc + (r0 + 8) * TS + c0) =
                    make_float2(acc[mf][nf][2] + b0, acc[mf][nf][3] + b1);
            }
        }
        __syncthreads();

        {
            int c = tid & 127;
            int h = tid >> 7;
            int rstart = h * 64, rend = rstart + 64;
            int prev = sDc[rstart];
            float m = -FLT_MAX;
            for (int r = rstart; r < rend; r++) {
                int d = sDc[r];
                if (d != prev) {
                    if (prev >= 0) atomic_fmax(agg + (size_t)prev * HD + c, m);
                    m = -FLT_MAX;
                    prev = d;
                }
                m = fmaxf(m, sTc[r * TS + c]);
            }
            if (prev >= 0) atomic_fmax(agg + (size_t)prev * HD + c, m);
        }
        __syncthreads();
        buf ^= 1;
    }
}

// ---------------- launch ----------------
extern "C" void kernel_launch(void* const* d_in, const int* in_sizes, int n_in,
                              void* d_out, int out_size)
{
    (void)n_in; (void)out_size;
    const float* x   = (const float*)d_in[0];
    const float* pos = (const float*)d_in[1];
    const int* ei    = (const int*)d_in[2];
    const float* p[16];
    for (int i = 0; i < 16; i++) p[i] = (const float*)d_in[3 + i];

    int E = in_sizes[2] / 2;
    int total = E + NODES;

    float *A, *B, *AGG, *H0, *TMP, *W2T, *WTH, *WTL;
    int *CNT, *NEXT, *SSRC, *SDST;
    cudaGetSymbolAddress((void**)&A, g_A);
    cudaGetSymbolAddress((void**)&B, g_B);
    cudaGetSymbolAddress((void**)&AGG, g_agg);
    cudaGetSymbolAddress((void**)&H0, g_h0);
    cudaGetSymbolAddress((void**)&TMP, g_tmp);
    cudaGetSymbolAddress((void**)&W2T, g_w2t);
    cudaGetSymbolAddress((void**)&WTH, g_wth);
    cudaGetSymbolAddress((void**)&WTL, g_wtl);
    cudaGetSymbolAddress((void**)&CNT, g_cnt);
    cudaGetSymbolAddress((void**)&NEXT, g_next);
    cudaGetSymbolAddress((void**)&SSRC, g_ssrc);
    cudaGetSymbolAddress((void**)&SDST, g_sdst);

    cudaFuncSetAttribute(edge_mma_kernel, cudaFuncAttributeMaxDynamicSharedMemorySize, EDGE_SMEM);
    cudaFuncSetAttribute(gemm_mma_kernel, cudaFuncAttributeMaxDynamicSharedMemorySize, GEMM_SMEM);

    int gemmBlocks = NODES / 128;              // 512
    int fillBlocks = (NODES * HD / 4 + THREADS - 1) / THREADS;
    int eBlocks = (total + THREADS - 1) / THREADS;

    // Build dst-sorted edge list once (layer-invariant)
    zero_i32<<<(NODES + THREADS - 1) / THREADS, THREADS>>>(CNT, NODES);
    hist_kernel<<<eBlocks, THREADS>>>(ei, CNT, E, total);
    scan_kernel<<<1, SCAN_T>>>(CNT, NEXT);
    scatter_kernel<<<eBlocks, THREADS>>>(ei, NEXT, SSRC, SDST, E, total);

    for (int layer = 0; layer < 2; layer++) {
        const float* lw1 = p[layer * 8 + 0];
        const float* lb1 = p[layer * 8 + 1];
        const float* lw2 = p[layer * 8 + 2];
        const float* lb2 = p[layer * 8 + 3];
        const float* gw1 = p[layer * 8 + 4];
        const float* gb1 = p[layer * 8 + 5];
        const float* gw2 = p[layer * 8 + 6];
        const float* gb2 = p[layer * 8 + 7];
        const float* inx = (layer == 0) ? x : H0;
        float* outp = (layer == 0) ? H0 : (float*)d_out;

        // B = pos @ Wp  (Wp = lw1 rows 128..255)
        prep_wt_kernel<<<HD, HD>>>(lw1 + 128 * HD, WTH, WTL, HD);
        gemm_mma_kernel<<<gemmBlocks, THREADS, GEMM_SMEM>>>(
            pos, nullptr, WTH, WTL, nullptr, B, HD, 0);

        // A = concat(inx, pos) @ lw1 + lb1   (K = 256)
        prep_wt_kernel<<<2 * HD, HD>>>(lw1, WTH, WTL, 2 * HD);
        gemm_mma_kernel<<<gemmBlocks, THREADS, GEMM_SMEM>>>(
            inx, pos, WTH, WTL, lb1, A, 2 * HD, 0);

        prep_w2t_kernel<<<HD, HD>>>(lw2, W2T);
        fill_kernel<<<fillBlocks, THREADS>>>((float4*)AGG, -FLT_MAX, NODES * HD / 4);
        edge_mma_kernel<<<GRID_EDGE, THREADS, EDGE_SMEM>>>(SSRC, SDST, A, B, W2T, lb2, AGG, total);

        // global_nn
        prep_wt_kernel<<<HD, HD>>>(gw1, WTH, WTL, HD);
        gemm_mma_kernel<<<gemmBlocks, THREADS, GEMM_SMEM>>>(
            AGG, nullptr, WTH, WTL, gb1, TMP, HD, 1);
        prep_wt_kernel<<<HD, HD>>>(gw2, WTH, WTL, HD);
        gemm_mma_kernel<<<gemmBlocks, THREADS, GEMM_SMEM>>>(
            TMP, nullptr, WTH, WTL, gb2, outp, HD, 0);
    }
}

// round 8
// speedup vs baseline: 1.1543x; 1.1543x over previous
#include <cuda_runtime.h>
#include <cuda_fp16.h>
#include <float.h>
#include <stdint.h>

#define NODES 65536
#define HD 128
#define THREADS 256
#define TSH 68                       // half2-word stride per row (64 data + 4 pad)
#define STG 132                      // fp32 staging stride
#define MAXEDGES (1048576 + NODES)
#define GRID_EDGE 152

// edge kernel smem map (bytes)
#define HBUF (128 * TSH * 4)         // 34816 per half2 tile buffer
#define SM_T0H 2048
#define SM_T1H (2048 + HBUF)
#define SM_WH  (2048 + 2 * HBUF)
#define SM_STAGE (2048 + 3 * HBUF)
#define EDGE_SMEM (SM_STAGE + 128 * STG * 4)   // 174080

// ---------------- scratch ----------------
__device__ float g_A[(size_t)NODES * HD];
__device__ float g_B[(size_t)NODES * HD];
__device__ float g_agg[(size_t)NODES * HD];
__device__ float g_h0[(size_t)NODES * HD];
__device__ float g_tmp[(size_t)NODES * HD];
__device__ __half g_w2t[HD * HD];    // W2^T fp16, [n][k]
__device__ int g_cnt[NODES];
__device__ int g_next[NODES];
__device__ int g_ssrc[MAXEDGES];
__device__ int g_sdst[MAXEDGES];

__global__ __launch_bounds__(THREADS) void fill_kernel(float4* p, float v, int n4) {
    int i = blockIdx.x * blockDim.x + threadIdx.x;
    if (i < n4) p[i] = make_float4(v, v, v, v);
}

__global__ __launch_bounds__(THREADS) void zero_i32(int* p, int n) {
    int i = blockIdx.x * blockDim.x + threadIdx.x;
    if (i < n) p[i] = 0;
}

// ---------------- counting sort by dst (once per launch) ----------------
__global__ __launch_bounds__(THREADS) void hist_kernel(
    const int* __restrict__ ei, int* __restrict__ cnt, int E, int total)
{
    int e = blockIdx.x * blockDim.x + threadIdx.x;
    if (e < total) {
        int d = (e < E) ? ei[E + e] : (e - E);
        atomicAdd(&cnt[d], 1);
    }
}

#define SCAN_T 1024
#define CHUNK (NODES / SCAN_T)   // 64
__global__ __launch_bounds__(SCAN_T) void scan_kernel(
    const int* __restrict__ cnt, int* __restrict__ next)
{
    __shared__ int part[SCAN_T];
    int t = threadIdx.x;
    int base = t * CHUNK;
    int sum = 0;
#pragma unroll 4
    for (int i = 0; i < CHUNK; i++) sum += cnt[base + i];
    part[t] = sum;
    __syncthreads();
    for (int off = 1; off < SCAN_T; off <<= 1) {
        int v = (t >= off) ? part[t - off] : 0;
        __syncthreads();
        part[t] += v;
        __syncthreads();
    }
    int off = part[t] - sum;   // exclusive
#pragma unroll 4
    for (int i = 0; i < CHUNK; i++) {
        next[base + i] = off;
        off += cnt[base + i];
    }
}

__global__ __launch_bounds__(THREADS) void scatter_kernel(
    const int* __restrict__ ei, int* __restrict__ next,
    int* __restrict__ ssrc, int* __restrict__ sdst, int E, int total)
{
    int e = blockIdx.x * blockDim.x + threadIdx.x;
    if (e < total) {
        int s, d;
        if (e < E) { s = ei[e]; d = ei[E + e]; }
        else       { s = e - E; d = s; }
        int pos = atomicAdd(&next[d], 1);
        ssrc[pos] = s;
        sdst[pos] = d;
    }
}

// W2[k][n] fp32 -> W2T[n][k] fp16
__global__ __launch_bounds__(HD) void prep_w2t_kernel(
    const float* __restrict__ W2, __half* __restrict__ out)
{
    int n = blockIdx.x, k = threadIdx.x;
    out[n * HD + k] = __float2half(W2[k * HD + n]);
}

// ---------------- node GEMM (fp32 FFMA, proven R6) ----------------
__global__ __launch_bounds__(THREADS) void gemm_kernel(
    const float* __restrict__ In, const float* __restrict__ W,
    const float* __restrict__ bias, const float* __restrict__ addend,
    float* __restrict__ Out, int relu_out)
{
    __shared__ float sIn[16 * 128];
    __shared__ float sW[16 * 128];

    int tid = threadIdx.x;
    int rowBase = blockIdx.x * 128;
    int tx = tid & 15, ty = tid >> 4;

    float acc[8][8];
#pragma unroll
    for (int i = 0; i < 8; i++)
#pragma unroll
        for (int j = 0; j < 8; j++) acc[i][j] = 0.f;

    for (int kk = 0; kk < HD; kk += 16) {
#pragma unroll
        for (int l = 0; l < 2; l++) {
            int idx = tid + l * THREADS;
            int r = idx >> 2, c4 = idx & 3;
            float4 v = *(const float4*)(In + (size_t)(rowBase + r) * HD + kk + c4 * 4);
            sIn[(c4 * 4 + 0) * 128 + r] = v.x;
            sIn[(c4 * 4 + 1) * 128 + r] = v.y;
            sIn[(c4 * 4 + 2) * 128 + r] = v.z;
            sIn[(c4 * 4 + 3) * 128 + r] = v.w;
        }
#pragma unroll
        for (int l = 0; l < 2; l++) {
            int idx = tid + l * THREADS;
            int k = idx >> 5, c = idx & 31;
            *(float4*)(sW + k * 128 + c * 4) =
                *(const float4*)(W + (size_t)(kk + k) * HD + c * 4);
        }
        __syncthreads();
#pragma unroll
        for (int k = 0; k < 16; k++) {
            float a[8], b[8];
            *(float4*)(a)     = *(const float4*)(sIn + k * 128 + ty * 8);
            *(float4*)(a + 4) = *(const float4*)(sIn + k * 128 + ty * 8 + 4);
            *(float4*)(b)     = *(const float4*)(sW + k * 128 + tx * 8);
            *(float4*)(b + 4) = *(const float4*)(sW + k * 128 + tx * 8 + 4);
#pragma unroll
            for (int i = 0; i < 8; i++)
#pragma unroll
                for (int j = 0; j < 8; j++) acc[i][j] += a[i] * b[j];
        }
        __syncthreads();
    }

    float bv[8];
    if (bias) {
        *(float4*)(bv)     = *(const float4*)(bias + tx * 8);
        *(float4*)(bv + 4) = *(const float4*)(bias + tx * 8 + 4);
    } else {
#pragma unroll
        for (int j = 0; j < 8; j++) bv[j] = 0.f;
    }
#pragma unroll
    for (int i = 0; i < 8; i++) {
        size_t row = (size_t)rowBase + ty * 8 + i;
        float o[8];
#pragma unroll
        for (int j = 0; j < 8; j++) o[j] = acc[i][j] + bv[j];
        if (addend) {
            float4 a0 = *(const float4*)(addend + row * HD + tx * 8);
            float4 a1 = *(const float4*)(addend + row * HD + tx * 8 + 4);
            o[0] += a0.x; o[1] += a0.y; o[2] += a0.z; o[3] += a0.w;
            o[4] += a1.x; o[5] += a1.y; o[6] += a1.z; o[7] += a1.w;
        }
        if (relu_out) {
#pragma unroll
            for (int j = 0; j < 8; j++) o[j] = fmaxf(o[j], 0.f);
        }
        *(float4*)(Out + row * HD + tx * 8)     = make_float4(o[0], o[1], o[2], o[3]);
        *(float4*)(Out + row * HD + tx * 8 + 4) = make_float4(o[4], o[5], o[6], o[7]);
    }
}

// ---------------- persistent edge kernel (fp16 mma) ----------------
__device__ __forceinline__ void mma_fp16(float* d, const uint32_t* a, const uint32_t* b) {
    asm volatile(
        "mma.sync.aligned.m16n8k16.row.col.f32.f16.f16.f32 "
        "{%0,%1,%2,%3}, {%4,%5,%6,%7}, {%8,%9}, {%0,%1,%2,%3};"
        : "+f"(d[0]), "+f"(d[1]), "+f"(d[2]), "+f"(d[3])
        : "r"(a[0]), "r"(a[1]), "r"(a[2]), "r"(a[3]), "r"(b[0]), "r"(b[1]));
}

__device__ __forceinline__ void atomic_fmax(float* p, float v) {
    if (v >= 0.f) atomicMax((int*)p, __float_as_int(v));
    else          atomicMin((unsigned int*)p, __float_as_uint(v));
}

struct GReg {
    float4 a[8], b[8];
    int d, r;
    bool valid;
};

__device__ __forceinline__ void gather_issue(
    int eBase, int pass, GReg& G,
    const int* __restrict__ ssrc, const int* __restrict__ sdst,
    const float* __restrict__ A, const float* __restrict__ B,
    int total, int tid)
{
    int r = pass * 64 + (tid >> 2);
    int q = tid & 3;
    int e = eBase + r;
    G.valid = (e < total);
    int s = 0, d = 0;
    if (G.valid) { s = ssrc[e]; d = sdst[e]; }
    G.d = d; G.r = r;
    const float4* Ar = (const float4*)(A + (size_t)s * HD) + q;
    const float4* Br = (const float4*)(B + (size_t)d * HD) + q;
#pragma unroll
    for (int i = 0; i < 8; i++) {
        G.a[i] = Ar[i * 4];
        G.b[i] = Br[i * 4];
    }
}

// commit: relu(A-B) -> half2 -> sTn (half2-word layout, stride TSH)
__device__ __forceinline__ void gather_commit(
    const GReg& G, uint32_t* __restrict__ sTn, int* __restrict__ sDn, int tid)
{
    int q = tid & 3;
    if (q == 0) sDn[G.r] = G.valid ? G.d : -1;
    uint32_t* Tr = sTn + G.r * TSH + q * 2;
#pragma unroll
    for (int i = 0; i < 8; i++) {
        float4 t;
        t.x = G.valid ? fmaxf(G.a[i].x - G.b[i].x, 0.f) : 0.f;
        t.y = G.valid ? fmaxf(G.a[i].y - G.b[i].y, 0.f) : 0.f;
        t.z = G.valid ? fmaxf(G.a[i].z - G.b[i].z, 0.f) : 0.f;
        t.w = G.valid ? fmaxf(G.a[i].w - G.b[i].w, 0.f) : 0.f;
        __half2 h01 = __floats2half2_rn(t.x, t.y);
        __half2 h23 = __floats2half2_rn(t.z, t.w);
        uint2 u = make_uint2(*(uint32_t*)&h01, *(uint32_t*)&h23);
        *(uint2*)(Tr + i * 8) = u;     // half2 words q*2 + 8i, q*2+8i+1
    }
}

// one K-half (4 ksteps of k16)
__device__ __forceinline__ void mma_half(
    const uint32_t* __restrict__ sT, const uint32_t* __restrict__ sW,
    int ks0, float acc[4][4][4], int rowBase, int colBase, int g, int tg)
{
#pragma unroll
    for (int ks = 0; ks < 4; ks++) {
        int base = (ks0 + ks) * 8;
        uint32_t b[4][2];
#pragma unroll
        for (int nf = 0; nf < 4; nf++) {
            int n = colBase + nf * 8 + g;
            b[nf][0] = sW[n * TSH + base + tg];
            b[nf][1] = sW[n * TSH + base + 4 + tg];
        }
        uint32_t a[4][4];
#pragma unroll
        for (int mf = 0; mf < 4; mf++) {
            int r = rowBase + mf * 16 + g;
            a[mf][0] = sT[r * TSH + base + tg];
            a[mf][1] = sT[(r + 8) * TSH + base + tg];
            a[mf][2] = sT[r * TSH + base + 4 + tg];
            a[mf][3] = sT[(r + 8) * TSH + base + 4 + tg];
        }
#pragma unroll
        for (int mf = 0; mf < 4; mf++)
#pragma unroll
            for (int nf = 0; nf < 4; nf++)
                mma_fp16(acc[mf][nf], a[mf], b[nf]);
    }
}

__global__ __launch_bounds__(THREADS, 1) void edge_mma_kernel(
    const int* __restrict__ ssrc, const int* __restrict__ sdst,
    const float* __restrict__ A, const float* __restrict__ B,
    const __half* __restrict__ W2T, const float* __restrict__ b2,
    float* __restrict__ agg, int total)
{
    extern __shared__ char smem[];
    int* sDst0 = (int*)smem;
    int* sDst1 = (int*)(smem + 512);
    float* sBias = (float*)(smem + 1024);
    uint32_t* sT0 = (uint32_t*)(smem + SM_T0H);
    uint32_t* sT1 = (uint32_t*)(smem + SM_T1H);
    uint32_t* sW  = (uint32_t*)(smem + SM_WH);
    float* sStage = (float*)(smem + SM_STAGE);

    int tid = threadIdx.x;
    int lane = tid & 31, wid = tid >> 5;
    int ntiles = (total + 127) >> 7;

    // One-time: stream W2T (fp16, 32KB) into sW rows (272B stride)
    {
        uint32_t sw_base;
        asm("{ .reg .u64 t; cvta.to.shared.u64 t, %1; cvt.u32.u64 %0, t; }"
            : "=r"(sw_base) : "l"(sW));
#pragma unroll
        for (int it = 0; it < 8; it++) {
            int linear = tid + it * THREADS;   // 16B-chunk index 0..2047
            int n = linear >> 4, c = linear & 15;
            uint32_t dst = sw_base + (uint32_t)(n * (TSH * 4) + c * 16);
            const char* src = (const char*)W2T + n * 256 + c * 16;
            asm volatile("cp.async.cg.shared.global [%0], [%1], 16;"
                         :: "r"(dst), "l"(src));
        }
        asm volatile("cp.async.commit_group;" ::: "memory");
    }
    if (tid < 128) sBias[tid] = b2[tid];

    // Prologue: gather first tile into buffer 0
    if (blockIdx.x < ntiles) {
        GReg G;
        gather_issue(blockIdx.x * 128, 0, G, ssrc, sdst, A, B, total, tid);
        gather_commit(G, sT0, sDst0, tid);
        gather_issue(blockIdx.x * 128, 1, G, ssrc, sdst, A, B, total, tid);
        gather_commit(G, sT0, sDst0, tid);
    }
    asm volatile("cp.async.wait_group 0;" ::: "memory");
    __syncthreads();

    int rowBase = (wid & 1) * 64;
    int colBase = (wid >> 1) * 32;
    int g = lane >> 2, tg = lane & 3;

    int buf = 0;
    for (int ti = blockIdx.x; ti < ntiles; ti += GRID_EDGE) {
        uint32_t* sTc = buf ? sT1 : sT0;
        uint32_t* sTn = buf ? sT0 : sT1;
        int* sDc = buf ? sDst1 : sDst0;
        int* sDn = buf ? sDst0 : sDst1;
        int tn = ti + GRID_EDGE;
        bool hn = tn < ntiles;

        float acc[4][4][4];
#pragma unroll
        for (int i = 0; i < 4; i++)
#pragma unroll
            for (int j = 0; j < 4; j++)
#pragma unroll
                for (int q = 0; q < 4; q++) acc[i][j][q] = 0.f;

        GReg G;
        if (hn) gather_issue(tn * 128, 0, G, ssrc, sdst, A, B, total, tid);
        mma_half(sTc, sW, 0, acc, rowBase, colBase, g, tg);
        if (hn) {
            gather_commit(G, sTn, sDn, tid);
            gather_issue(tn * 128, 1, G, ssrc, sdst, A, B, total, tid);
        }
        mma_half(sTc, sW, 4, acc, rowBase, colBase, g, tg);
        if (hn) gather_commit(G, sTn, sDn, tid);

        __syncthreads();   // MMA reads of sTc done; commit of sTn done

        // stage acc + bias -> sStage (fp32, stride STG)
#pragma unroll
        for (int mf = 0; mf < 4; mf++) {
            int r0 = rowBase + mf * 16 + g;
#pragma unroll
            for (int nf = 0; nf < 4; nf++) {
                int c0 = colBase + nf * 8 + 2 * tg;
                float b0 = sBias[c0], b1 = sBias[c0 + 1];
                *(float2*)(sStage + r0 * STG + c0) =
                    make_float2(acc[mf][nf][0] + b0, acc[mf][nf][1] + b1);
                *(float2*)(sStage + (r0 + 8) * STG + c0) =
                    make_float2(acc[mf][nf][2] + b0, acc[mf][nf][3] + b1);
            }
        }
        __syncthreads();

        // segmented column-max (rows sorted by dst); one atomic per (segment,col)
        {
            int c = tid & 127;
            int h = tid >> 7;
            int rstart = h * 64, rend = rstart + 64;
            int prev = sDc[rstart];
            float m = -FLT_MAX;
            for (int r = rstart; r < rend; r++) {
                int d = sDc[r];
                if (d != prev) {
                    if (prev >= 0) atomic_fmax(agg + (size_t)prev * HD + c, m);
                    m = -FLT_MAX;
                    prev = d;
                }
                m = fmaxf(m, sStage[r * STG + c]);
            }
            if (prev >= 0) atomic_fmax(agg + (size_t)prev * HD + c, m);
        }
        __syncthreads();
        buf ^= 1;
    }
}

// ---------------- launch ----------------
extern "C" void kernel_launch(void* const* d_in, const int* in_sizes, int n_in,
                              void* d_out, int out_size)
{
    (void)n_in; (void)out_size;
    const float* x   = (const float*)d_in[0];
    const float* pos = (const float*)d_in[1];
    const int* ei    = (const int*)d_in[2];
    const float* p[16];
    for (int i = 0; i < 16; i++) p[i] = (const float*)d_in[3 + i];

    int E = in_sizes[2] / 2;
    int total = E + NODES;

    float *A, *B, *AGG, *H0, *TMP;
    __half* W2T;
    int *CNT, *NEXT, *SSRC, *SDST;
    cudaGetSymbolAddress((void**)&A, g_A);
    cudaGetSymbolAddress((void**)&B, g_B);
    cudaGetSymbolAddress((void**)&AGG, g_agg);
    cudaGetSymbolAddress((void**)&H0, g_h0);
    cudaGetSymbolAddress((void**)&TMP, g_tmp);
    cudaGetSymbolAddress((void**)&W2T, g_w2t);
    cudaGetSymbolAddress((void**)&CNT, g_cnt);
    cudaGetSymbolAddress((void**)&NEXT, g_next);
    cudaGetSymbolAddress((void**)&SSRC, g_ssrc);
    cudaGetSymbolAddress((void**)&SDST, g_sdst);

    cudaFuncSetAttribute(edge_mma_kernel, cudaFuncAttributeMaxDynamicSharedMemorySize, EDGE_SMEM);

    int gemmBlocks = NODES / 128;              // 512
    int fillBlocks = (NODES * HD / 4 + THREADS - 1) / THREADS;
    int eBlocks = (total + THREADS - 1) / THREADS;

    // Build dst-sorted edge list once (layer-invariant)
    zero_i32<<<(NODES + THREADS - 1) / THREADS, THREADS>>>(CNT, NODES);
    hist_kernel<<<eBlocks, THREADS>>>(ei, CNT, E, total);
    scan_kernel<<<1, SCAN_T>>>(CNT, NEXT);
    scatter_kernel<<<eBlocks, THREADS>>>(ei, NEXT, SSRC, SDST, E, total);

    for (int layer = 0; layer < 2; layer++) {
        const float* lw1 = p[layer * 8 + 0];
        const float* lb1 = p[layer * 8 + 1];
        const float* lw2 = p[layer * 8 + 2];
        const float* lb2 = p[layer * 8 + 3];
        const float* gw1 = p[layer * 8 + 4];
        const float* gb1 = p[layer * 8 + 5];
        const float* gw2 = p[layer * 8 + 6];
        const float* gb2 = p[layer * 8 + 7];
        const float* inx = (layer == 0) ? x : H0;
        float* outp = (layer == 0) ? H0 : (float*)d_out;

        // B = pos @ Wp  (Wp = lw1 rows 128..255)
        gemm_kernel<<<gemmBlocks, THREADS>>>(pos, lw1 + 128 * HD, nullptr, nullptr, B, 0);
        // A = inx @ Wx + B + lb1
        gemm_kernel<<<gemmBlocks, THREADS>>>(inx, lw1, lb1, B, A, 0);
        prep_w2t_kernel<<<HD, HD>>>(lw2, W2T);
        fill_kernel<<<fillBlocks, THREADS>>>((float4*)AGG, -FLT_MAX, NODES * HD / 4);
        edge_mma_kernel<<<GRID_EDGE, THREADS, EDGE_SMEM>>>(SSRC, SDST, A, B, W2T, lb2, AGG, total);
        // global_nn
        gemm_kernel<<<gemmBlocks, THREADS>>>(AGG, gw1, gb1, nullptr, TMP, 1);
        gemm_kernel<<<gemmBlocks, THREADS>>>(TMP, gw2, gb2, nullptr, outp, 0);
    }
}

// round 10
// speedup vs baseline: 1.4907x; 1.2914x over previous
#include <cuda_runtime.h>
#include <cuda_fp16.h>
#include <float.h>
#include <stdint.h>

#define NODES 65536
#define HD 128
#define THREADS 256
#define TSH 68                       // uint32 (half2) stride per 128-half row
#define STG 132                      // fp32 staging stride (edge epilogue)
#define MAXEDGES (1048576 + NODES)
#define GRID_EDGE 152

// edge kernel smem map (bytes)
#define HBUF (128 * TSH * 4)         // 34816 per half tile buffer
#define SM_T0H 2048
#define SM_T1H (2048 + HBUF)
#define SM_WH  (2048 + 2 * HBUF)
#define SM_STAGE (2048 + 3 * HBUF)
#define EDGE_SMEM (SM_STAGE + 128 * STG * 4)   // 174080

// node GEMM smem: sA + sWh + sWl + bias
#define GH_SMEM (3 * HBUF + 512)               // 104960

// ---------------- scratch ----------------
__device__ __half g_Ah[(size_t)NODES * HD];
__device__ __half g_Bh[(size_t)NODES * HD];
__device__ float g_agg[(size_t)NODES * HD];
__device__ float g_h0[(size_t)NODES * HD];
__device__ float g_tmp[(size_t)NODES * HD];
__device__ __half g_w2t[HD * HD];    // W2^T fp16, [n][k]
__device__ __half g_wh[HD * HD];     // node W^T hi, [n][k]
__device__ __half g_wl[HD * HD];     // node W^T lo, [n][k]
__device__ int g_cnt[NODES];
__device__ int g_next[NODES];
__device__ int g_ssrc[MAXEDGES];
__device__ int g_sdst[MAXEDGES];

__global__ __launch_bounds__(THREADS) void fill_kernel(float4* p, float v, int n4) {
    int i = blockIdx.x * blockDim.x + threadIdx.x;
    if (i < n4) p[i] = make_float4(v, v, v, v);
}

__global__ __launch_bounds__(THREADS) void zero_i32(int* p, int n) {
    int i = blockIdx.x * blockDim.x + threadIdx.x;
    if (i < n) p[i] = 0;
}

// ---------------- counting sort by dst (once per launch) ----------------
__global__ __launch_bounds__(THREADS) void hist_kernel(
    const int* __restrict__ ei, int* __restrict__ cnt, int E, int total)
{
    int e = blockIdx.x * blockDim.x + threadIdx.x;
    if (e < total) {
        int d = (e < E) ? ei[E + e] : (e - E);
        atomicAdd(&cnt[d], 1);
    }
}

#define SCAN_T 1024
#define CHUNK (NODES / SCAN_T)   // 64
__global__ __launch_bounds__(SCAN_T) void scan_kernel(
    const int* __restrict__ cnt, int* __restrict__ next)
{
    __shared__ int part[SCAN_T];
    int t = threadIdx.x;
    int base = t * CHUNK;
    int sum = 0;
#pragma unroll 4
    for (int i = 0; i < CHUNK; i++) sum += cnt[base + i];
    part[t] = sum;
    __syncthreads();
    for (int off = 1; off < SCAN_T; off <<= 1) {
        int v = (t >= off) ? part[t - off] : 0;
        __syncthreads();
        part[t] += v;
        __syncthreads();
    }
    int off = part[t] - sum;   // exclusive
#pragma unroll 4
    for (int i = 0; i < CHUNK; i++) {
        next[base + i] = off;
        off += cnt[base + i];
    }
}

__global__ __launch_bounds__(THREADS) void scatter_kernel(
    const int* __restrict__ ei, int* __restrict__ next,
    int* __restrict__ ssrc, int* __restrict__ sdst, int E, int total)
{
    int e = blockIdx.x * blockDim.x + threadIdx.x;
    if (e < total) {
        int s, d;
        if (e < E) { s = ei[e]; d = ei[E + e]; }
        else       { s = e - E; d = s; }
        int pos = atomicAdd(&next[d], 1);
        ssrc[pos] = s;
        sdst[pos] = d;
    }
}

// W2[k][n] fp32 -> W2T[n][k] fp16
__global__ __launch_bounds__(HD) void prep_w2t_kernel(
    const float* __restrict__ W2, __half* __restrict__ out)
{
    int n = blockIdx.x, k = threadIdx.x;
    out[n * HD + k] = __float2half(W2[k * HD + n]);
}

// W[k][n] fp32 -> W^T hi/lo fp16 split, [n][k]
__global__ __launch_bounds__(HD) void prep_wh_kernel(
    const float* __restrict__ W, __half* __restrict__ wh, __half* __restrict__ wl)
{
    int k = blockIdx.x, n = threadIdx.x;
    float v = W[k * HD + n];
    __half h = __float2half_rn(v);
    wh[n * HD + k] = h;
    wl[n * HD + k] = __float2half_rn(v - __half2float(h));
}

// ---------------- mma helper ----------------
__device__ __forceinline__ void mma_fp16(float* d, const uint32_t* a, const uint32_t* b) {
    asm volatile(
        "mma.sync.aligned.m16n8k16.row.col.f32.f16.f16.f32 "
        "{%0,%1,%2,%3}, {%4,%5,%6,%7}, {%8,%9}, {%0,%1,%2,%3};"
        : "+f"(d[0]), "+f"(d[1]), "+f"(d[2]), "+f"(d[3])
        : "r"(a[0]), "r"(a[1]), "r"(a[2]), "r"(a[3]), "r"(b[0]), "r"(b[1]));
}

__device__ __forceinline__ void atomic_fmax(float* p, float v) {
    if (v >= 0.f) atomicMax((int*)p, __float_as_int(v));
    else          atomicMin((unsigned int*)p, __float_as_uint(v));
}

// ---------------- node GEMM: fp16 mma, hi/lo split weights ----------------
// Out[M,128] = act( In[M,128]@W + bias (+addend) ); In fp32, W pre-split fp16.
__global__ __launch_bounds__(THREADS) void gemm_h_kernel(
    const float* __restrict__ In,
    const __half* __restrict__ WTh, const __half* __restrict__ WTl,
    const float* __restrict__ bias, const __half* __restrict__ addend,
    float* __restrict__ OutF, __half* __restrict__ OutH, int relu_out)
{
    extern __shared__ char sm[];
    uint32_t* sA  = (uint32_t*)sm;
    uint32_t* sWh = (uint32_t*)(sm + HBUF);
    uint32_t* sWl = (uint32_t*)(sm + 2 * HBUF);
    float* sBias  = (float*)(sm + 3 * HBUF);

    int tid = threadIdx.x, lane = tid & 31, wid = tid >> 5;
    int rowBase = blockIdx.x * 128;

    // W tiles via cp.async (fp16, pre-split/pre-transposed)
    {
        uint32_t dh, dl;
        asm("{ .reg .u64 t; cvta.to.shared.u64 t, %1; cvt.u32.u64 %0, t; }"
            : "=r"(dh) : "l"(sWh));
        asm("{ .reg .u64 t; cvta.to.shared.u64 t, %1; cvt.u32.u64 %0, t; }"
            : "=r"(dl) : "l"(sWl));
#pragma unroll
        for (int it = 0; it < 8; it++) {
            int lin = tid + it * THREADS;      // 16B-chunk 0..2047
            int n = lin >> 4, c = lin & 15;
            uint32_t off = (uint32_t)(n * (TSH * 4) + c * 16);
            asm volatile("cp.async.cg.shared.global [%0], [%1], 16;"
                         :: "r"(dh + off), "l"(WTh + n * HD + c * 8));
            asm volatile("cp.async.cg.shared.global [%0], [%1], 16;"
                         :: "r"(dl + off), "l"(WTl + n * HD + c * 8));
        }
        asm volatile("cp.async.commit_group;" ::: "memory");
    }
    if (tid < 128) sBias[tid] = bias ? bias[tid] : 0.f;

    // A tile: fp32 -> fp16 (2 threads/row)
    {
        int r = tid >> 1, h = tid & 1;
        const float4* src = (const float4*)(In + (size_t)(rowBase + r) * HD + h * 64);
        uint32_t* dst = sA + r * TSH + h * 32;
#pragma unroll
        for (int j = 0; j < 8; j++) {
            float4 v0 = src[j * 2], v1 = src[j * 2 + 1];
            __half2 a = __floats2half2_rn(v0.x, v0.y);
            __half2 b = __floats2half2_rn(v0.z, v0.w);
            __half2 c = __floats2half2_rn(v1.x, v1.y);
            __half2 d = __floats2half2_rn(v1.z, v1.w);
            uint4 u = make_uint4(*(uint32_t*)&a, *(uint32_t*)&b,
                                 *(uint32_t*)&c, *(uint32_t*)&d);
            *(uint4*)(dst + j * 4) = u;
        }
    }
    asm volatile("cp.async.wait_group 0;" ::: "memory");
    __syncthreads();

    int warpRow = (wid & 1) * 64, warpCol = (wid >> 1) * 32;
    int g = lane >> 2, tg = lane & 3;

    float acc[4][4][4];
#pragma unroll
    for (int i = 0; i < 4; i++)
#pragma unroll
        for (int j = 0; j < 4; j++)
#pragma unroll
            for (int q = 0; q < 4; q++) acc[i][j][q] = 0.f;

#pragma unroll
    for (int ks = 0; ks < 8; ks++) {
        int base = ks * 8;
        uint32_t bh[4][2], bl[4][2];
#pragma unroll
        for (int nf = 0; nf < 4; nf++) {
            int n = warpCol + nf * 8 + g;
            bh[nf][0] = sWh[n * TSH + base + tg];
            bh[nf][1] = sWh[n * TSH + base + 4 + tg];
            bl[nf][0] = sWl[n * TSH + base + tg];
            bl[nf][1] = sWl[n * TSH + base + 4 + tg];
        }
        uint32_t a[4][4];
#pragma unroll
        for (int mf = 0; mf < 4; mf++) {
            int r = warpRow + mf * 16 + g;
            a[mf][0] = sA[r * TSH + base + tg];
            a[mf][1] = sA[(r + 8) * TSH + base + tg];
            a[mf][2] = sA[r * TSH + base + 4 + tg];
            a[mf][3] = sA[(r + 8) * TSH + base + 4 + tg];
        }
#pragma unroll
        for (int mf = 0; mf < 4; mf++)
#pragma unroll
            for (int nf = 0; nf < 4; nf++) {
                mma_fp16(acc[mf][nf], a[mf], bh[nf]);
                mma_fp16(acc[mf][nf], a[mf], bl[nf]);
            }
    }

    // Epilogue
#pragma unroll
    for (int mf = 0; mf < 4; mf++) {
        size_t r0 = (size_t)rowBase + warpRow + mf * 16 + g;
#pragma unroll
        for (int nf = 0; nf < 4; nf++) {
            int c0 = warpCol + nf * 8 + 2 * tg;
            float b0 = sBias[c0], b1 = sBias[c0 + 1];
            float o0 = acc[mf][nf][0] + b0, o1 = acc[mf][nf][1] + b1;
            float o2 = acc[mf][nf][2] + b0, o3 = acc[mf][nf][3] + b1;
            if (addend) {
                uint32_t u0 = *(const uint32_t*)(addend + r0 * HD + c0);
                uint32_t u1 = *(const uint32_t*)(addend + (r0 + 8) * HD + c0);
                __half2 h0 = *(__half2*)&u0, h1 = *(__half2*)&u1;
                o0 += __low2float(h0); o1 += __high2float(h0);
                o2 += __low2float(h1); o3 += __high2float(h1);
            }
            if (relu_out) {
                o0 = fmaxf(o0, 0.f); o1 = fmaxf(o1, 0.f);
                o2 = fmaxf(o2, 0.f); o3 = fmaxf(o3, 0.f);
            }
            if (OutH) {
                __half2 p0 = __floats2half2_rn(o0, o1);
                __half2 p1 = __floats2half2_rn(o2, o3);
                *(uint32_t*)(OutH + r0 * HD + c0)       = *(uint32_t*)&p0;
                *(uint32_t*)(OutH + (r0 + 8) * HD + c0) = *(uint32_t*)&p1;
            } else {
                *(float2*)(OutF + r0 * HD + c0)       = make_float2(o0, o1);
                *(float2*)(OutF + (r0 + 8) * HD + c0) = make_float2(o2, o3);
            }
        }
    }
}

// ---------------- persistent edge kernel (fp16 A/B in global) ----------------
struct GReg {
    uint4 a[4], b[4];
    int d, r;
    bool valid;
};

__device__ __forceinline__ void gather_issue(
    int eBase, int pass, GReg& G,
    const int* __restrict__ ssrc, const int* __restrict__ sdst,
    const __half* __restrict__ A, const __half* __restrict__ B,
    int total, int tid)
{
    int r = pass * 64 + (tid >> 2);
    int q = tid & 3;
    int e = eBase + r;
    G.valid = (e < total);
    int s = 0, d = 0;
    if (G.valid) { s = ssrc[e]; d = sdst[e]; }
    G.d = d; G.r = r;
    const uint4* Ar = (const uint4*)(A + (size_t)s * HD) + q * 4;
    const uint4* Br = (const uint4*)(B + (size_t)d * HD) + q * 4;
#pragma unroll
    for (int i = 0; i < 4; i++) { G.a[i] = Ar[i]; G.b[i] = Br[i]; }
}

__device__ __forceinline__ uint32_t hsubrelu(uint32_t a, uint32_t b) {
    __half2 r = __hmax2(__hsub2(*(__half2*)&a, *(__half2*)&b),
                        __float2half2_rn(0.f));
    return *(uint32_t*)&r;
}

__device__ __forceinline__ void gather_commit(
    const GReg& G, uint32_t* __restrict__ sTn, int* __restrict__ sDn, int tid)
{
    int q = tid & 3;
    if (q == 0) sDn[G.r] = G.valid ? G.d : -1;
    uint32_t* Tr = sTn + G.r * TSH + q * 16;
#pragma unroll
    for (int i = 0; i < 4; i++) {
        uint4 t;
        if (G.valid) {
            t.x = hsubrelu(G.a[i].x, G.b[i].x);
            t.y = hsubrelu(G.a[i].y, G.b[i].y);
            t.z = hsubrelu(G.a[i].z, G.b[i].z);
            t.w = hsubrelu(G.a[i].w, G.b[i].w);
        } else {
            t = make_uint4(0, 0, 0, 0);
        }
        *(uint4*)(Tr + i * 4) = t;
    }
}

// one K-half (4 ksteps of k16)
__device__ __forceinline__ void mma_half(
    const uint32_t* __restrict__ sT, const uint32_t* __restrict__ sW,
    int ks0, float acc[4][4][4], int rowBase, int colBase, int g, int tg)
{
#pragma unroll
    for (int ks = 0; ks < 4; ks++) {
        int base = (ks0 + ks) * 8;
        uint32_t b[4][2];
#pragma unroll
        for (int nf = 0; nf < 4; nf++) {
            int n = colBase + nf * 8 + g;
            b[nf][0] = sW[n * TSH + base + tg];
            b[nf][1] = sW[n * TSH + base + 4 + tg];
        }
        uint32_t a[4][4];
#pragma unroll
        for (int mf = 0; mf < 4; mf++) {
            int r = rowBase + mf * 16 + g;
            a[mf][0] = sT[r * TSH + base + tg];
            a[mf][1] = sT[(r + 8) * TSH + base + tg];
            a[mf][2] = sT[r * TSH + base + 4 + tg];
            a[mf][3] = sT[(r + 8) * TSH + base + 4 + tg];
        }
#pragma unroll
        for (int mf = 0; mf < 4; mf++)
#pragma unroll
            for (int nf = 0; nf < 4; nf++)
                mma_fp16(acc[mf][nf], a[mf], b[nf]);
    }
}

__global__ __launch_bounds__(THREADS, 1) void edge_mma_kernel(
    const int* __restrict__ ssrc, const int* __restrict__ sdst,
    const __half* __restrict__ A, const __half* __restrict__ B,
    const __half* __restrict__ W2T, const float* __restrict__ b2,
    float* __restrict__ agg, int total)
{
    extern __shared__ char smem[];
    int* sDst0 = (int*)smem;
    int* sDst1 = (int*)(smem + 512);
    float* sBias = (float*)(smem + 1024);
    uint32_t* sT0 = (uint32_t*)(smem + SM_T0H);
    uint32_t* sT1 = (uint32_t*)(smem + SM_T1H);
    uint32_t* sW  = (uint32_t*)(smem + SM_WH);
    float* sStage = (float*)(smem + SM_STAGE);

    int tid = threadIdx.x;
    int lane = tid & 31, wid = tid >> 5;
    int ntiles = (total + 127) >> 7;

    // One-time: stream W2T (fp16, 32KB) into sW rows
    {
        uint32_t sw_base;
        asm("{ .reg .u64 t; cvta.to.shared.u64 t, %1; cvt.u32.u64 %0, t; }"
            : "=r"(sw_base) : "l"(sW));
#pragma unroll
        for (int it = 0; it < 8; it++) {
            int linear = tid + it * THREADS;   // 16B-chunk index 0..2047
            int n = linear >> 4, c = linear & 15;
            uint32_t dst = sw_base + (uint32_t)(n * (TSH * 4) + c * 16);
            const char* src = (const char*)W2T + n * 256 + c * 16;
            asm volatile("cp.async.cg.shared.global [%0], [%1], 16;"
                         :: "r"(dst), "l"(src));
        }
        asm volatile("cp.async.commit_group;" ::: "memory");
    }
    if (tid < 128) sBias[tid] = b2[tid];

    // Prologue: gather first tile into buffer 0
    if (blockIdx.x < ntiles) {
        GReg G;
        gather_issue(blockIdx.x * 128, 0, G, ssrc, sdst, A, B, total, tid);
        gather_commit(G, sT0, sDst0, tid);
        gather_issue(blockIdx.x * 128, 1, G, ssrc, sdst, A, B, total, tid);
        gather_commit(G, sT0, sDst0, tid);
    }
    asm volatile("cp.async.wait_group 0;" ::: "memory");
    __syncthreads();

    int rowBase = (wid & 1) * 64;
    int colBase = (wid >> 1) * 32;
    int g = lane >> 2, tg = lane & 3;

    int buf = 0;
    for (int ti = blockIdx.x; ti < ntiles; ti += GRID_EDGE) {
        uint32_t* sTc = buf ? sT1 : sT0;
        uint32_t* sTn = buf ? sT0 : sT1;
        int* sDc = buf ? sDst1 : sDst0;
        int* sDn = buf ? sDst0 : sDst1;
        int tn = ti + GRID_EDGE;
        bool hn = tn < ntiles;

        float acc[4][4][4];
#pragma unroll
        for (int i = 0; i < 4; i++)
#pragma unroll
            for (int j = 0; j < 4; j++)
#pragma unroll
                for (int q = 0; q < 4; q++) acc[i][j][q] = 0.f;

        GReg G;
        if (hn) gather_issue(tn * 128, 0, G, ssrc, sdst, A, B, total, tid);
        mma_half(sTc, sW, 0, acc, rowBase, colBase, g, tg);
        if (hn) {
            gather_commit(G, sTn, sDn, tid);
            gather_issue(tn * 128, 1, G, ssrc, sdst, A, B, total, tid);
        }
        mma_half(sTc, sW, 4, acc, rowBase, colBase, g, tg);
        if (hn) gather_commit(G, sTn, sDn, tid);

        __syncthreads();   // MMA reads of sTc done; commit of sTn done

        // stage acc + bias -> sStage (fp32, stride STG)
#pragma unroll
        for (int mf = 0; mf < 4; mf++) {
            int r0 = rowBase + mf * 16 + g;
#pragma unroll
            for (int nf = 0; nf < 4; nf++) {
                int c0 = colBase + nf * 8 + 2 * tg;
                float b0 = sBias[c0], b1 = sBias[c0 + 1];
                *(float2*)(sStage + r0 * STG + c0) =
                    make_float2(acc[mf][nf][0] + b0, acc[mf][nf][1] + b1);
                *(float2*)(sStage + (r0 + 8) * STG + c0) =
                    make_float2(acc[mf][nf][2] + b0, acc[mf][nf][3] + b1);
            }
        }
        __syncthreads();

        // segmented column-max (rows sorted by dst); one atomic per (segment,col)
        {
            int c = tid & 127;
            int h = tid >> 7;
            int rstart = h * 64, rend = rstart + 64;
            int prev = sDc[rstart];
            float m = -FLT_MAX;
            for (int r = rstart; r < rend; r++) {
                int d = sDc[r];
                if (d != prev) {
                    if (prev >= 0) atomic_fmax(agg + (size_t)prev * HD + c, m);
                    m = -FLT_MAX;
                    prev = d;
                }
                m = fmaxf(m, sStage[r * STG + c]);
            }
            if (prev >= 0) atomic_fmax(agg + (size_t)prev * HD + c, m);
        }
        __syncthreads();
        buf ^= 1;
    }
}

// ---------------- launch ----------------
extern "C" void kernel_launch(void* const* d_in, const int* in_sizes, int n_in,
                              void* d_out, int out_size)
{
    (void)n_in; (void)out_size;
    const float* x   = (const float*)d_in[0];
    const float* pos = (const float*)d_in[1];
    const int* ei    = (const int*)d_in[2];
    const float* p[16];
    for (int i = 0; i < 16; i++) p[i] = (const float*)d_in[3 + i];

    int E = in_sizes[2] / 2;
    int total = E + NODES;

    float *AGG, *H0, *TMP;
    __half *AH, *BH, *W2T, *WH, *WL;
    int *CNT, *NEXT, *SSRC, *SDST;
    cudaGetSymbolAddress((void**)&AH, g_Ah);
    cudaGetSymbolAddress((void**)&BH, g_Bh);
    cudaGetSymbolAddress((void**)&AGG, g_agg);
    cudaGetSymbolAddress((void**)&H0, g_h0);
    cudaGetSymbolAddress((void**)&TMP, g_tmp);
    cudaGetSymbolAddress((void**)&W2T, g_w2t);
    cudaGetSymbolAddress((void**)&WH, g_wh);
    cudaGetSymbolAddress((void**)&WL, g_wl);
    cudaGetSymbolAddress((void**)&CNT, g_cnt);
    cudaGetSymbolAddress((void**)&NEXT, g_next);
    cudaGetSymbolAddress((void**)&SSRC, g_ssrc);
    cudaGetSymbolAddress((void**)&SDST, g_sdst);

    cudaFuncSetAttribute(edge_mma_kernel, cudaFuncAttributeMaxDynamicSharedMemorySize, EDGE_SMEM);
    cudaFuncSetAttribute(gemm_h_kernel, cudaFuncAttributeMaxDynamicSharedMemorySize, GH_SMEM);

    int gemmBlocks = NODES / 128;              // 512
    int fillBlocks = (NODES * HD / 4 + THREADS - 1) / THREADS;
    int eBlocks = (total + THREADS - 1) / THREADS;

    // Build dst-sorted edge list once (layer-invariant)
    zero_i32<<<(NODES + THREADS - 1) / THREADS, THREADS>>>(CNT, NODES);
    hist_kernel<<<eBlocks, THREADS>>>(ei, CNT, E, total);
    scan_kernel<<<1, SCAN_T>>>(CNT, NEXT);
    scatter_kernel<<<eBlocks, THREADS>>>(ei, NEXT, SSRC, SDST, E, total);

    for (int layer = 0; layer < 2; layer++) {
        const float* lw1 = p[layer * 8 + 0];
        const float* lb1 = p[layer * 8 + 1];
        const float* lw2 = p[layer * 8 + 2];
        const float* lb2 = p[layer * 8 + 3];
        const float* gw1 = p[layer * 8 + 4];
        const float* gb1 = p[layer * 8 + 5];
        const float* gw2 = p[layer * 8 + 6];
        const float* gb2 = p[layer * 8 + 7];
        const float* inx = (layer == 0) ? x : H0;
        float* outp = (layer == 0) ? H0 : (float*)d_out;

        // Bh = pos @ Wp (fp16 out)
        prep_wh_kernel<<<HD, HD>>>(lw1 + 128 * HD, WH, WL);
        gemm_h_kernel<<<gemmBlocks, THREADS, GH_SMEM>>>(
            pos, WH, WL, nullptr, nullptr, nullptr, BH, 0);
        // Ah = inx @ Wx + lb1 + Bh (fp16 out)
        prep_wh_kernel<<<HD, HD>>>(lw1, WH, WL);
        gemm_h_kernel<<<gemmBlocks, THREADS, GH_SMEM>>>(
            inx, WH, WL, lb1, BH, nullptr, AH, 0);

        prep_w2t_kernel<<<HD, HD>>>(lw2, W2T);
        fill_kernel<<<fillBlocks, THREADS>>>((float4*)AGG, -FLT_MAX, NODES * HD / 4);
        edge_mma_kernel<<<GRID_EDGE, THREADS, EDGE_SMEM>>>(
            SSRC, SDST, AH, BH, W2T, lb2, AGG, total);

        // global_nn (fp32 out)
        prep_wh_kernel<<<HD, HD>>>(gw1, WH, WL);
        gemm_h_kernel<<<gemmBlocks, THREADS, GH_SMEM>>>(
            AGG, WH, WL, gb1, nullptr, TMP, nullptr, 1);
        prep_wh_kernel<<<HD, HD>>>(gw2, WH, WL);
        gemm_h_kernel<<<gemmBlocks, THREADS, GH_SMEM>>>(
            TMP, WH, WL, gb2, nullptr, outp, nullptr, 0);
    }
}

// round 11
// speedup vs baseline: 1.5749x; 1.0565x over previous
#include <cuda_runtime.h>
#include <cuda_fp16.h>
#include <float.h>
#include <stdint.h>

#define NODES 65536
#define HD 128
#define THREADS 256
#define TSH 68                       // uint32 (half2) stride per 128-half row
#define STG 132                      // fp32 staging stride (edge epilogue)
#define MAXEDGES (1048576 + NODES)
#define GRID_EDGE 152

// edge kernel smem map (bytes)
#define HBUF (128 * TSH * 4)         // 34816 per half tile buffer
#define SM_T0H 2048
#define SM_T1H (2048 + HBUF)
#define SM_WH  (2048 + 2 * HBUF)
#define SM_STAGE (2048 + 3 * HBUF)
#define EDGE_SMEM (SM_STAGE + 128 * STG * 4)   // 174080

// fused node GEMM smem: header(1024) + sA + 4 W bufs
#define AB_SA  1024
#define AB_W0H (1024 + HBUF)
#define AB_W0L (1024 + 2 * HBUF)
#define AB_W1H (1024 + 3 * HBUF)
#define AB_W1L (1024 + 4 * HBUF)
#define AB_SMEM (1024 + 5 * HBUF)              // 175104

// ---------------- scratch ----------------
__device__ __half g_Ah[(size_t)NODES * HD];
__device__ __half g_Bh[(size_t)NODES * HD];
__device__ float g_agg[(size_t)NODES * HD];
__device__ float g_h0[(size_t)NODES * HD];
__device__ __half g_w2t[HD * HD];    // W2^T fp16, [n][k]
__device__ __half g_whA[HD * 256];   // concat local W^T hi, [n][k0..255]
__device__ __half g_wlA[HD * 256];   // concat local W^T lo
__device__ __half g_wh1[HD * HD];    // gw1^T hi/lo
__device__ __half g_wl1[HD * HD];
__device__ __half g_wh2[HD * HD];    // gw2^T hi/lo
__device__ __half g_wl2[HD * HD];
__device__ int g_cnt[NODES];
__device__ int g_next[NODES];
__device__ int g_ssrc[MAXEDGES];
__device__ int g_sdst[MAXEDGES];

__global__ __launch_bounds__(THREADS) void fill_kernel(float4* p, float v, int n4) {
    int i = blockIdx.x * blockDim.x + threadIdx.x;
    if (i < n4) p[i] = make_float4(v, v, v, v);
}

__global__ __launch_bounds__(THREADS) void zero_i32(int* p, int n) {
    int i = blockIdx.x * blockDim.x + threadIdx.x;
    if (i < n) p[i] = 0;
}

// ---------------- counting sort by dst (once per launch) ----------------
__global__ __launch_bounds__(THREADS) void hist_kernel(
    const int* __restrict__ ei, int* __restrict__ cnt, int E, int total)
{
    int e = blockIdx.x * blockDim.x + threadIdx.x;
    if (e < total) {
        int d = (e < E) ? ei[E + e] : (e - E);
        atomicAdd(&cnt[d], 1);
    }
}

#define SCAN_T 1024
#define CHUNK (NODES / SCAN_T)   // 64
__global__ __launch_bounds__(SCAN_T) void scan_kernel(
    const int* __restrict__ cnt, int* __restrict__ next)
{
    __shared__ int part[SCAN_T];
    int t = threadIdx.x;
    int base = t * CHUNK;
    int sum = 0;
#pragma unroll 4
    for (int i = 0; i < CHUNK; i++) sum += cnt[base + i];
    part[t] = sum;
    __syncthreads();
    for (int off = 1; off < SCAN_T; off <<= 1) {
        int v = (t >= off) ? part[t - off] : 0;
        __syncthreads();
        part[t] += v;
        __syncthreads();
    }
    int off = part[t] - sum;   // exclusive
#pragma unroll 4
    for (int i = 0; i < CHUNK; i++) {
        next[base + i] = off;
        off += cnt[base + i];
    }
}

__global__ __launch_bounds__(THREADS) void scatter_kernel(
    const int* __restrict__ ei, int* __restrict__ next,
    int* __restrict__ ssrc, int* __restrict__ sdst, int E, int total)
{
    int e = blockIdx.x * blockDim.x + threadIdx.x;
    if (e < total) {
        int s, d;
        if (e < E) { s = ei[e]; d = ei[E + e]; }
        else       { s = e - E; d = s; }
        int pos = atomicAdd(&next[d], 1);
        ssrc[pos] = s;
        sdst[pos] = d;
    }
}

// W2[k][n] fp32 -> W2T[n][k] fp16
__global__ __launch_bounds__(HD) void prep_w2t_kernel(
    const float* __restrict__ W2, __half* __restrict__ out)
{
    int n = blockIdx.x, k = threadIdx.x;
    out[n * HD + k] = __float2half(W2[k * HD + n]);
}

// W[k][n] (128x128) -> W^T hi/lo fp16 split, [n][k]
__global__ __launch_bounds__(HD) void prep_wh_kernel(
    const float* __restrict__ W, __half* __restrict__ wh, __half* __restrict__ wl)
{
    int k = blockIdx.x, n = threadIdx.x;
    float v = W[k * HD + n];
    __half h = __float2half_rn(v);
    wh[n * HD + k] = h;
    wl[n * HD + k] = __float2half_rn(v - __half2float(h));
}

// lw1[k][n] (256x128) -> concat W^T hi/lo, [n][k0..255]
__global__ __launch_bounds__(HD) void prep_whA_kernel(
    const float* __restrict__ W, __half* __restrict__ wh, __half* __restrict__ wl)
{
    int k = blockIdx.x, n = threadIdx.x;
    float v = W[k * HD + n];
    __half h = __float2half_rn(v);
    wh[n * 256 + k] = h;
    wl[n * 256 + k] = __float2half_rn(v - __half2float(h));
}

// ---------------- mma / ldmatrix helpers ----------------
__device__ __forceinline__ void mma_fp16(float* d, const uint32_t* a, const uint32_t* b) {
    asm volatile(
        "mma.sync.aligned.m16n8k16.row.col.f32.f16.f16.f32 "
        "{%0,%1,%2,%3}, {%4,%5,%6,%7}, {%8,%9}, {%0,%1,%2,%3};"
        : "+f"(d[0]), "+f"(d[1]), "+f"(d[2]), "+f"(d[3])
        : "r"(a[0]), "r"(a[1]), "r"(a[2]), "r"(a[3]), "r"(b[0]), "r"(b[1]));
}

__device__ __forceinline__ void ldsm_x4(uint32_t addr, uint32_t* r) {
    asm volatile(
        "ldmatrix.sync.aligned.m8n8.x4.shared.b16 {%0,%1,%2,%3}, [%4];"
        : "=r"(r[0]), "=r"(r[1]), "=r"(r[2]), "=r"(r[3]) : "r"(addr));
}

__device__ __forceinline__ void atomic_fmax(float* p, float v) {
    if (v >= 0.f) atomicMax((int*)p, __float_as_int(v));
    else          atomicMin((unsigned int*)p, __float_as_uint(v));
}

__device__ __forceinline__ uint32_t smem_u32(const void* p) {
    uint32_t a;
    asm("{ .reg .u64 t; cvta.to.shared.u64 t, %1; cvt.u32.u64 %0, t; }"
        : "=r"(a) : "l"(p));
    return a;
}

// Lane constants for ldmatrix fragment addressing
struct LaneC { int rA, kA, rB, kB; };
__device__ __forceinline__ LaneC lane_consts(int lane) {
    LaneC c;
    c.rA = lane & 15;
    c.kA = (lane >> 4) * 4;
    c.rB = (lane & 7) + ((lane >> 4) << 3);
    c.kB = ((lane >> 3) & 1) * 4;
    return c;
}

// 8-kstep MMA block with hi/lo split weights (node GEMMs)
__device__ __forceinline__ void mma_block_hl(
    uint32_t aSA, uint32_t aWH, uint32_t aWL,
    float acc[4][4][4], int warpRow, int warpCol, const LaneC& L)
{
#pragma unroll
    for (int ks = 0; ks < 8; ks++) {
        int base = ks * 8;
        uint32_t bh[4][2], bl[4][2];
#pragma unroll
        for (int p = 0; p < 2; p++) {
            uint32_t r[4];
            uint32_t off = (uint32_t)(((warpCol + p * 16 + L.rB) * TSH + base + L.kB) * 4);
            ldsm_x4(aWH + off, r);
            bh[2*p][0] = r[0]; bh[2*p][1] = r[1];
            bh[2*p+1][0] = r[2]; bh[2*p+1][1] = r[3];
            ldsm_x4(aWL + off, r);
            bl[2*p][0] = r[0]; bl[2*p][1] = r[1];
            bl[2*p+1][0] = r[2]; bl[2*p+1][1] = r[3];
        }
        uint32_t a[4][4];
#pragma unroll
        for (int mf = 0; mf < 4; mf++) {
            uint32_t off = (uint32_t)(((warpRow + mf * 16 + L.rA) * TSH + base + L.kA) * 4);
            ldsm_x4(aSA + off, a[mf]);
        }
#pragma unroll
        for (int mf = 0; mf < 4; mf++)
#pragma unroll
            for (int nf = 0; nf < 4; nf++) {
                mma_fp16(acc[mf][nf], a[mf], bh[nf]);
                mma_fp16(acc[mf][nf], a[mf], bl[nf]);
            }
    }
}

// async copy of one fp16 [128][srcStride->128 used] tile into padded smem rows
__device__ __forceinline__ void async_w_tile(
    uint32_t dstH, uint32_t dstL,
    const __half* __restrict__ srcH, const __half* __restrict__ srcL,
    int srcStride, int tid)
{
#pragma unroll
    for (int it = 0; it < 8; it++) {
        int lin = tid + it * THREADS;
        int n = lin >> 4, c = lin & 15;
        uint32_t off = (uint32_t)(n * (TSH * 4) + c * 16);
        asm volatile("cp.async.cg.shared.global [%0], [%1], 16;"
                     :: "r"(dstH + off), "l"(srcH + (size_t)n * srcStride + c * 8));
        asm volatile("cp.async.cg.shared.global [%0], [%1], 16;"
                     :: "r"(dstL + off), "l"(srcL + (size_t)n * srcStride + c * 8));
    }
    asm volatile("cp.async.commit_group;" ::: "memory");
}

// fp32 [128][128] input tile -> fp16 smem tile (2 threads/row)
__device__ __forceinline__ void load_in_tile(
    const float* __restrict__ In, int rowBase, uint32_t* sA, int tid)
{
    int r = tid >> 1, h = tid & 1;
    const float4* src = (const float4*)(In + (size_t)(rowBase + r) * HD + h * 64);
    uint32_t* dst = sA + r * TSH + h * 32;
#pragma unroll
    for (int j = 0; j < 8; j++) {
        float4 v0 = src[j * 2], v1 = src[j * 2 + 1];
        __half2 a = __floats2half2_rn(v0.x, v0.y);
        __half2 b = __floats2half2_rn(v0.z, v0.w);
        __half2 c = __floats2half2_rn(v1.x, v1.y);
        __half2 d = __floats2half2_rn(v1.z, v1.w);
        uint4 u = make_uint4(*(uint32_t*)&a, *(uint32_t*)&b,
                             *(uint32_t*)&c, *(uint32_t*)&d);
        *(uint4*)(dst + j * 4) = u;
    }
}

// ---------------- fused A/B node GEMM ----------------
// Bh = fp16(pos @ Wp); Ah = fp16(float(Bh) + inx @ Wx + lb1)
__global__ __launch_bounds__(THREADS) void gemm_ab_kernel(
    const float* __restrict__ pos, const float* __restrict__ inx,
    const __half* __restrict__ WHA, const __half* __restrict__ WLA,
    const float* __restrict__ lb1,
    __half* __restrict__ Ah, __half* __restrict__ Bh)
{
    extern __shared__ char sm[];
    float* sBias = (float*)sm;
    uint32_t sb = smem_u32(sm);
    uint32_t aSA = sb + AB_SA;
    uint32_t aW0H = sb + AB_W0H, aW0L = sb + AB_W0L;
    uint32_t aW1H = sb + AB_W1H, aW1L = sb + AB_W1L;
    uint32_t* sA = (uint32_t*)(sm + AB_SA);

    int tid = threadIdx.x, lane = tid & 31, wid = tid >> 5;
    int rowBase = blockIdx.x * 128;

    // group0: Wp (k 128..255); group1: Wx (k 0..127)
    async_w_tile(aW0H, aW0L, WHA + 128, WLA + 128, 256, tid);
    async_w_tile(aW1H, aW1L, WHA, WLA, 256, tid);

    if (tid < 128) sBias[tid] = lb1[tid];
    load_in_tile(pos, rowBase, sA, tid);

    asm volatile("cp.async.wait_group 1;" ::: "memory");
    __syncthreads();

    int warpRow = (wid & 1) * 64, warpCol = (wid >> 1) * 32;
    int g = lane >> 2, tg = lane & 3;
    LaneC L = lane_consts(lane);

    float acc[4][4][4];
#pragma unroll
    for (int i = 0; i < 4; i++)
#pragma unroll
        for (int j = 0; j < 4; j++)
#pragma unroll
            for (int q = 0; q < 4; q++) acc[i][j][q] = 0.f;

    mma_block_hl(aSA, aW0H, aW0L, acc, warpRow, warpCol, L);

    // snapshot Bh + requantize acc (preserves exact A-B cancellation)
#pragma unroll
    for (int mf = 0; mf < 4; mf++) {
        size_t r0 = (size_t)rowBase + warpRow + mf * 16 + g;
#pragma unroll
        for (int nf = 0; nf < 4; nf++) {
            int c0 = warpCol + nf * 8 + 2 * tg;
            __half2 p0 = __floats2half2_rn(acc[mf][nf][0], acc[mf][nf][1]);
            __half2 p1 = __floats2half2_rn(acc[mf][nf][2], acc[mf][nf][3]);
            *(uint32_t*)(Bh + r0 * HD + c0)       = *(uint32_t*)&p0;
            *(uint32_t*)(Bh + (r0 + 8) * HD + c0) = *(uint32_t*)&p1;
            acc[mf][nf][0] = __low2float(p0); acc[mf][nf][1] = __high2float(p0);
            acc[mf][nf][2] = __low2float(p1); acc[mf][nf][3] = __high2float(p1);
        }
    }

    __syncthreads();                       // mma reads of sA done
    load_in_tile(inx, rowBase, sA, tid);
    asm volatile("cp.async.wait_group 0;" ::: "memory");
    __syncthreads();

    mma_block_hl(aSA, aW1H, aW1L, acc, warpRow, warpCol, L);

#pragma unroll
    for (int mf = 0; mf < 4; mf++) {
        size_t r0 = (size_t)rowBase + warpRow + mf * 16 + g;
#pragma unroll
        for (int nf = 0; nf < 4; nf++) {
            int c0 = warpCol + nf * 8 + 2 * tg;
            float b0 = sBias[c0], b1 = sBias[c0 + 1];
            __half2 p0 = __floats2half2_rn(acc[mf][nf][0] + b0, acc[mf][nf][1] + b1);
            __half2 p1 = __floats2half2_rn(acc[mf][nf][2] + b0, acc[mf][nf][3] + b1);
            *(uint32_t*)(Ah + r0 * HD + c0)       = *(uint32_t*)&p0;
            *(uint32_t*)(Ah + (r0 + 8) * HD + c0) = *(uint32_t*)&p1;
        }
    }
}

// ---------------- fused global_nn double GEMM ----------------
// Out = relu(AGG @ gw1 + gb1) @ gw2 + gb2  (fp32 out)
__global__ __launch_bounds__(THREADS) void gemm_gg_kernel(
    const float* __restrict__ AGG,
    const __half* __restrict__ WH1, const __half* __restrict__ WL1,
    const __half* __restrict__ WH2, const __half* __restrict__ WL2,
    const float* __restrict__ gb1, const float* __restrict__ gb2,
    float* __restrict__ Out)
{
    extern __shared__ char sm[];
    float* sBias1 = (float*)sm;
    float* sBias2 = (float*)(sm + 512);
    uint32_t sb = smem_u32(sm);
    uint32_t aSA = sb + AB_SA;
    uint32_t aW0H = sb + AB_W0H, aW0L = sb + AB_W0L;
    uint32_t aW1H = sb + AB_W1H, aW1L = sb + AB_W1L;
    uint32_t* sA = (uint32_t*)(sm + AB_SA);

    int tid = threadIdx.x, lane = tid & 31, wid = tid >> 5;
    int rowBase = blockIdx.x * 128;

    async_w_tile(aW0H, aW0L, WH1, WL1, HD, tid);
    async_w_tile(aW1H, aW1L, WH2, WL2, HD, tid);

    if (tid < 128) { sBias1[tid] = gb1[tid]; sBias2[tid] = gb2[tid]; }
    load_in_tile(AGG, rowBase, sA, tid);

    asm volatile("cp.async.wait_group 1;" ::: "memory");
    __syncthreads();

    int warpRow = (wid & 1) * 64, warpCol = (wid >> 1) * 32;
    int g = lane >> 2, tg = lane & 3;
    LaneC L = lane_consts(lane);

    float acc[4][4][4];
#pragma unroll
    for (int i = 0; i < 4; i++)
#pragma unroll
        for (int j = 0; j < 4; j++)
#pragma unroll
            for (int q = 0; q < 4; q++) acc[i][j][q] = 0.f;

    mma_block_hl(aSA, aW0H, aW0L, acc, warpRow, warpCol, L);

    __syncthreads();                       // all mma reads of sA done

    // relu(acc + gb1) -> fp16 back into sA
#pragma unroll
    for (int mf = 0; mf < 4; mf++) {
        int r0 = warpRow + mf * 16 + g;
#pragma unroll
        for (int nf = 0; nf < 4; nf++) {
            int c0 = warpCol + nf * 8 + 2 * tg;
            float b0 = sBias1[c0], b1 = sBias1[c0 + 1];
            float o0 = fmaxf(acc[mf][nf][0] + b0, 0.f);
            float o1 = fmaxf(acc[mf][nf][1] + b1, 0.f);
            float o2 = fmaxf(acc[mf][nf][2] + b0, 0.f);
            float o3 = fmaxf(acc[mf][nf][3] + b1, 0.f);
            __half2 p0 = __floats2half2_rn(o0, o1);
            __half2 p1 = __floats2half2_rn(o2, o3);
            sA[r0 * TSH + (c0 >> 1)]       = *(uint32_t*)&p0;
            sA[(r0 + 8) * TSH + (c0 >> 1)] = *(uint32_t*)&p1;
            acc[mf][nf][0] = 0.f; acc[mf][nf][1] = 0.f;
            acc[mf][nf][2] = 0.f; acc[mf][nf][3] = 0.f;
        }
    }
    asm volatile("cp.async.wait_group 0;" ::: "memory");
    __syncthreads();

    mma_block_hl(aSA, aW1H, aW1L, acc, warpRow, warpCol, L);

#pragma unroll
    for (int mf = 0; mf < 4; mf++) {
        size_t r0 = (size_t)rowBase + warpRow + mf * 16 + g;
#pragma unroll
        for (int nf = 0; nf < 4; nf++) {
            int c0 = warpCol + nf * 8 + 2 * tg;
            float b0 = sBias2[c0], b1 = sBias2[c0 + 1];
            *(float2*)(Out + r0 * HD + c0) =
                make_float2(acc[mf][nf][0] + b0, acc[mf][nf][1] + b1);
            *(float2*)(Out + (r0 + 8) * HD + c0) =
                make_float2(acc[mf][nf][2] + b0, acc[mf][nf][3] + b1);
        }
    }
}

// ---------------- persistent edge kernel (fp16 A/B, ldmatrix) ----------------
struct GReg {
    uint4 a[4], b[4];
    int d, r;
    bool valid;
};

__device__ __forceinline__ void gather_issue(
    int eBase, int pass, GReg& G,
    const int* __restrict__ ssrc, const int* __restrict__ sdst,
    const __half* __restrict__ A, const __half* __restrict__ B,
    int total, int tid)
{
    int r = pass * 64 + (tid >> 2);
    int q = tid & 3;
    int e = eBase + r;
    G.valid = (e < total);
    int s = 0, d = 0;
    if (G.valid) { s = ssrc[e]; d = sdst[e]; }
    G.d = d; G.r = r;
    const uint4* Ar = (const uint4*)(A + (size_t)s * HD) + q * 4;
    const uint4* Br = (const uint4*)(B + (size_t)d * HD) + q * 4;
#pragma unroll
    for (int i = 0; i < 4; i++) { G.a[i] = Ar[i]; G.b[i] = Br[i]; }
}

__device__ __forceinline__ uint32_t hsubrelu(uint32_t a, uint32_t b) {
    __half2 r = __hmax2(__hsub2(*(__half2*)&a, *(__half2*)&b),
                        __float2half2_rn(0.f));
    return *(uint32_t*)&r;
}

__device__ __forceinline__ void gather_commit(
    const GReg& G, uint32_t* __restrict__ sTn, int* __restrict__ sDn, int tid)
{
    int q = tid & 3;
    if (q == 0) sDn[G.r] = G.valid ? G.d : -1;
    uint32_t* Tr = sTn + G.r * TSH + q * 16;
#pragma unroll
    for (int i = 0; i < 4; i++) {
        uint4 t;
        if (G.valid) {
            t.x = hsubrelu(G.a[i].x, G.b[i].x);
            t.y = hsubrelu(G.a[i].y, G.b[i].y);
            t.z = hsubrelu(G.a[i].z, G.b[i].z);
            t.w = hsubrelu(G.a[i].w, G.b[i].w);
        } else {
            t = make_uint4(0, 0, 0, 0);
        }
        *(uint4*)(Tr + i * 4) = t;
    }
}

// one K-half (4 ksteps of k16), single (non-split) W, ldmatrix fragments
__device__ __forceinline__ void mma_half(
    uint32_t aST, uint32_t aSW,
    int ks0, float acc[4][4][4], int rowBase, int colBase, const LaneC& L)
{
#pragma unroll
    for (int ks = 0; ks < 4; ks++) {
        int base = (ks0 + ks) * 8;
        uint32_t b[4][2];
#pragma unroll
        for (int p = 0; p < 2; p++) {
            uint32_t r[4];
            uint32_t off = (uint32_t)(((colBase + p * 16 + L.rB) * TSH + base + L.kB) * 4);
            ldsm_x4(aSW + off, r);
            b[2*p][0] = r[0]; b[2*p][1] = r[1];
            b[2*p+1][0] = r[2]; b[2*p+1][1] = r[3];
        }
        uint32_t a[4][4];
#pragma unroll
        for (int mf = 0; mf < 4; mf++) {
            uint32_t off = (uint32_t)(((rowBase + mf * 16 + L.rA) * TSH + base + L.kA) * 4);
            ldsm_x4(aST + off, a[mf]);
        }
#pragma unroll
        for (int mf = 0; mf < 4; mf++)
#pragma unroll
            for (int nf = 0; nf < 4; nf++)
                mma_fp16(acc[mf][nf], a[mf], b[nf]);
    }
}

__global__ __launch_bounds__(THREADS, 1) void edge_mma_kernel(
    const int* __restrict__ ssrc, const int* __restrict__ sdst,
    const __half* __restrict__ A, const __half* __restrict__ B,
    const __half* __restrict__ W2T, const float* __restrict__ b2,
    float* __restrict__ agg, int total)
{
    extern __shared__ char smem[];
    int* sDst0 = (int*)smem;
    int* sDst1 = (int*)(smem + 512);
    float* sBias = (float*)(smem + 1024);
    uint32_t* sT0 = (uint32_t*)(smem + SM_T0H);
    uint32_t* sT1 = (uint32_t*)(smem + SM_T1H);
    float* sStage = (float*)(smem + SM_STAGE);

    uint32_t sb = smem_u32(smem);
    uint32_t aT0 = sb + SM_T0H, aT1 = sb + SM_T1H, aW = sb + SM_WH;

    int tid = threadIdx.x;
    int lane = tid & 31, wid = tid >> 5;
    int ntiles = (total + 127) >> 7;

    // One-time: stream W2T (fp16, 32KB) into sW rows
    {
#pragma unroll
        for (int it = 0; it < 8; it++) {
            int linear = tid + it * THREADS;   // 16B-chunk index 0..2047
            int n = linear >> 4, c = linear & 15;
            uint32_t dst = aW + (uint32_t)(n * (TSH * 4) + c * 16);
            const char* src = (const char*)W2T + n * 256 + c * 16;
            asm volatile("cp.async.cg.shared.global [%0], [%1], 16;"
                         :: "r"(dst), "l"(src));
        }
        asm volatile("cp.async.commit_group;" ::: "memory");
    }
    if (tid < 128) sBias[tid] = b2[tid];

    // Prologue: gather first tile into buffer 0
    if (blockIdx.x < ntiles) {
        GReg G;
        gather_issue(blockIdx.x * 128, 0, G, ssrc, sdst, A, B, total, tid);
        gather_commit(G, sT0, sDst0, tid);
        gather_issue(blockIdx.x * 128, 1, G, ssrc, sdst, A, B, total, tid);
        gather_commit(G, sT0, sDst0, tid);
    }
    asm volatile("cp.async.wait_group 0;" ::: "memory");
    __syncthreads();

    int rowBase = (wid & 1) * 64;
    int colBase = (wid >> 1) * 32;
    int g = lane >> 2, tg = lane & 3;
    LaneC L = lane_consts(lane);

    int buf = 0;
    for (int ti = blockIdx.x; ti < ntiles; ti += GRID_EDGE) {
        uint32_t aTc = buf ? aT1 : aT0;
        uint32_t* sTn = buf ? sT0 : sT1;
        int* sDc = buf ? sDst1 : sDst0;
        int* sDn = buf ? sDst0 : sDst1;
        int tn = ti + GRID_EDGE;
        bool hn = tn < ntiles;

        float acc[4][4][4];
#pragma unroll
        for (int i = 0; i < 4; i++)
#pragma unroll
            for (int j = 0; j < 4; j++)
#pragma unroll
                for (int q = 0; q < 4; q++) acc[i][j][q] = 0.f;

        GReg G;
        if (hn) gather_issue(tn * 128, 0, G, ssrc, sdst, A, B, total, tid);
        mma_half(aTc, aW, 0, acc, rowBase, colBase, L);
        if (hn) {
            gather_commit(G, sTn, sDn, tid);
            gather_issue(tn * 128, 1, G, ssrc, sdst, A, B, total, tid);
        }
        mma_half(aTc, aW, 4, acc, rowBase, colBase, L);
        if (hn) gather_commit(G, sTn, sDn, tid);

        __syncthreads();   // MMA reads of sTc done; commit of sTn done

        // stage acc + bias -> sStage (fp32, stride STG)
#pragma unroll
        for (int mf = 0; mf < 4; mf++) {
            int r0 = rowBase + mf * 16 + g;
#pragma unroll
            for (int nf = 0; nf < 4; nf++) {
                int c0 = colBase + nf * 8 + 2 * tg;
                float b0 = sBias[c0], b1 = sBias[c0 + 1];
                *(float2*)(sStage + r0 * STG + c0) =
                    make_float2(acc[mf][nf][0] + b0, acc[mf][nf][1] + b1);
                *(float2*)(sStage + (r0 + 8) * STG + c0) =
                    make_float2(acc[mf][nf][2] + b0, acc[mf][nf][3] + b1);
            }
        }
        __syncthreads();

        // segmented column-max (rows sorted by dst); one atomic per (segment,col)
        {
            int c = tid & 127;
            int h = tid >> 7;
            int rstart = h * 64, rend = rstart + 64;
            int prev = sDc[rstart];
            float m = -FLT_MAX;
            for (int r = rstart; r < rend; r++) {
                int d = sDc[r];
                if (d != prev) {
                    if (prev >= 0) atomic_fmax(agg + (size_t)prev * HD + c, m);
                    m = -FLT_MAX;
                    prev = d;
                }
                m = fmaxf(m, sStage[r * STG + c]);
            }
            if (prev >= 0) atomic_fmax(agg + (size_t)prev * HD + c, m);
        }
        __syncthreads();
        buf ^= 1;
    }
}

// ---------------- launch ----------------
extern "C" void kernel_launch(void* const* d_in, const int* in_sizes, int n_in,
                              void* d_out, int out_size)
{
    (void)n_in; (void)out_size;
    const float* x   = (const float*)d_in[0];
    const float* pos = (const float*)d_in[1];
    const int* ei    = (const int*)d_in[2];
    const float* p[16];
    for (int i = 0; i < 16; i++) p[i] = (const float*)d_in[3 + i];

    int E = in_sizes[2] / 2;
    int total = E + NODES;

    float *AGG, *H0;
    __half *AH, *BH, *W2T, *WHA, *WLA, *WH1, *WL1, *WH2, *WL2;
    int *CNT, *NEXT, *SSRC, *SDST;
    cudaGetSymbolAddress((void**)&AH, g_Ah);
    cudaGetSymbolAddress((void**)&BH, g_Bh);
    cudaGetSymbolAddress((void**)&AGG, g_agg);
    cudaGetSymbolAddress((void**)&H0, g_h0);
    cudaGetSymbolAddress((void**)&W2T, g_w2t);
    cudaGetSymbolAddress((void**)&WHA, g_whA);
    cudaGetSymbolAddress((void**)&WLA, g_wlA);
    cudaGetSymbolAddress((void**)&WH1, g_wh1);
    cudaGetSymbolAddress((void**)&WL1, g_wl1);
    cudaGetSymbolAddress((void**)&WH2, g_wh2);
    cudaGetSymbolAddress((void**)&WL2, g_wl2);
    cudaGetSymbolAddress((void**)&CNT, g_cnt);
    cudaGetSymbolAddress((void**)&NEXT, g_next);
    cudaGetSymbolAddress((void**)&SSRC, g_ssrc);
    cudaGetSymbolAddress((void**)&SDST, g_sdst);

    cudaFuncSetAttribute(edge_mma_kernel, cudaFuncAttributeMaxDynamicSharedMemorySize, EDGE_SMEM);
    cudaFuncSetAttribute(gemm_ab_kernel, cudaFuncAttributeMaxDynamicSharedMemorySize, AB_SMEM);
    cudaFuncSetAttribute(gemm_gg_kernel, cudaFuncAttributeMaxDynamicSharedMemorySize, AB_SMEM);

    int gemmBlocks = NODES / 128;              // 512
    int fillBlocks = (NODES * HD / 4 + THREADS - 1) / THREADS;
    int eBlocks = (total + THREADS - 1) / THREADS;

    // Build dst-sorted edge list once (layer-invariant)
    zero_i32<<<(NODES + THREADS - 1) / THREADS, THREADS>>>(CNT, NODES);
    hist_kernel<<<eBlocks, THREADS>>>(ei, CNT, E, total);
    scan_kernel<<<1, SCAN_T>>>(CNT, NEXT);
    scatter_kernel<<<eBlocks, THREADS>>>(ei, NEXT, SSRC, SDST, E, total);

    for (int layer = 0; layer < 2; layer++) {
        const float* lw1 = p[layer * 8 + 0];
        const float* lb1 = p[layer * 8 + 1];
        const float* lw2 = p[layer * 8 + 2];
        const float* lb2 = p[layer * 8 + 3];
        const float* gw1 = p[layer * 8 + 4];
        const float* gb1 = p[layer * 8 + 5];
        const float* gw2 = p[layer * 8 + 6];
        const float* gb2 = p[layer * 8 + 7];
        const float* inx = (layer == 0) ? x : H0;
        float* outp = (layer == 0) ? H0 : (float*)d_out;

        prep_whA_kernel<<<2 * HD, HD>>>(lw1, WHA, WLA);
        prep_w2t_kernel<<<HD, HD>>>(lw2, W2T);
        prep_wh_kernel<<<HD, HD>>>(gw1, WH1, WL1);
        prep_wh_kernel<<<HD, HD>>>(gw2, WH2, WL2);

        gemm_ab_kernel<<<gemmBlocks, THREADS, AB_SMEM>>>(
            pos, inx, WHA, WLA, lb1, AH, BH);

        fill_kernel<<<fillBlocks, THREADS>>>((float4*)AGG, -FLT_MAX, NODES * HD / 4);
        edge_mma_kernel<<<GRID_EDGE, THREADS, EDGE_SMEM>>>(
            SSRC, SDST, AH, BH, W2T, lb2, AGG, total);

        gemm_gg_kernel<<<gemmBlocks, THREADS, AB_SMEM>>>(
            AGG, WH1, WL1, WH2, WL2, gb1, gb2, outp);
    }
}

// round 12
// speedup vs baseline: 2.0046x; 1.2728x over previous
#include <cuda_runtime.h>
#include <cuda_fp16.h>
#include <float.h>
#include <stdint.h>

#define NODES 65536
#define HD 128
#define THREADS 256
#define TSH 68                       // uint32 (half2) stride per 128-half row
#define STG 132                      // fp32 staging stride (edge epilogue)
#define MAXEDGES (1048576 + NODES)
#define GRID_EDGE 304

// edge kernel smem map (bytes): header 2048 | T (tile / stage reuse) | W
#define HBUF (128 * TSH * 4)         // 34816
#define SM_T 2048
#define SM_W (2048 + HBUF)
#define EDGE_SMEM (2048 + 2 * HBUF)  // 71680 -> 2 CTAs/SM

// fused node GEMM smem: header(1024) + sA + 4 W bufs
#define AB_SA  1024
#define AB_W0H (1024 + HBUF)
#define AB_W0L (1024 + 2 * HBUF)
#define AB_W1H (1024 + 3 * HBUF)
#define AB_W1L (1024 + 4 * HBUF)
#define AB_SMEM (1024 + 5 * HBUF)    // 175104

// ---------------- scratch ----------------
__device__ __half g_Ah[(size_t)NODES * HD];
__device__ __half g_Bh[(size_t)NODES * HD];
__device__ float g_agg[(size_t)NODES * HD];
__device__ float g_h0[(size_t)NODES * HD];
__device__ __half g_w2t[HD * HD];
__device__ __half g_whA[HD * 256];
__device__ __half g_wlA[HD * 256];
__device__ __half g_wh1[HD * HD];
__device__ __half g_wl1[HD * HD];
__device__ __half g_wh2[HD * HD];
__device__ __half g_wl2[HD * HD];
__device__ int g_cnt[NODES];
__device__ int g_next[NODES];
__device__ int g_ssrc[MAXEDGES];
__device__ int g_sdst[MAXEDGES];

__global__ __launch_bounds__(THREADS) void fill_kernel(float4* p, float v, int n4) {
    int i = blockIdx.x * blockDim.x + threadIdx.x;
    if (i < n4) p[i] = make_float4(v, v, v, v);
}

__global__ __launch_bounds__(THREADS) void zero_i32(int* p, int n) {
    int i = blockIdx.x * blockDim.x + threadIdx.x;
    if (i < n) p[i] = 0;
}

// ---------------- counting sort by dst (once per launch) ----------------
__global__ __launch_bounds__(THREADS) void hist_kernel(
    const int* __restrict__ ei, int* __restrict__ cnt, int E, int total)
{
    int e = blockIdx.x * blockDim.x + threadIdx.x;
    if (e < total) {
        int d = (e < E) ? ei[E + e] : (e - E);
        atomicAdd(&cnt[d], 1);
    }
}

#define SCAN_T 1024
#define CHUNK (NODES / SCAN_T)   // 64
__global__ __launch_bounds__(SCAN_T) void scan_kernel(
    const int* __restrict__ cnt, int* __restrict__ next)
{
    __shared__ int part[SCAN_T];
    int t = threadIdx.x;
    int base = t * CHUNK;
    int sum = 0;
#pragma unroll 4
    for (int i = 0; i < CHUNK; i++) sum += cnt[base + i];
    part[t] = sum;
    __syncthreads();
    for (int off = 1; off < SCAN_T; off <<= 1) {
        int v = (t >= off) ? part[t - off] : 0;
        __syncthreads();
        part[t] += v;
        __syncthreads();
    }
    int off = part[t] - sum;   // exclusive
#pragma unroll 4
    for (int i = 0; i < CHUNK; i++) {
        next[base + i] = off;
        off += cnt[base + i];
    }
}

__global__ __launch_bounds__(THREADS) void scatter_kernel(
    const int* __restrict__ ei, int* __restrict__ next,
    int* __restrict__ ssrc, int* __restrict__ sdst, int E, int total)
{
    int e = blockIdx.x * blockDim.x + threadIdx.x;
    if (e < total) {
        int s, d;
        if (e < E) { s = ei[e]; d = ei[E + e]; }
        else       { s = e - E; d = s; }
        int pos = atomicAdd(&next[d], 1);
        ssrc[pos] = s;
        sdst[pos] = d;
    }
}

// W2[k][n] fp32 -> W2T[n][k] fp16
__global__ __launch_bounds__(HD) void prep_w2t_kernel(
    const float* __restrict__ W2, __half* __restrict__ out)
{
    int n = blockIdx.x, k = threadIdx.x;
    out[n * HD + k] = __float2half(W2[k * HD + n]);
}

// W[k][n] (128x128) -> W^T hi/lo fp16 split, [n][k]
__global__ __launch_bounds__(HD) void prep_wh_kernel(
    const float* __restrict__ W, __half* __restrict__ wh, __half* __restrict__ wl)
{
    int k = blockIdx.x, n = threadIdx.x;
    float v = W[k * HD + n];
    __half h = __float2half_rn(v);
    wh[n * HD + k] = h;
    wl[n * HD + k] = __float2half_rn(v - __half2float(h));
}

// lw1[k][n] (256x128) -> concat W^T hi/lo, [n][k0..255]
__global__ __launch_bounds__(HD) void prep_whA_kernel(
    const float* __restrict__ W, __half* __restrict__ wh, __half* __restrict__ wl)
{
    int k = blockIdx.x, n = threadIdx.x;
    float v = W[k * HD + n];
    __half h = __float2half_rn(v);
    wh[n * 256 + k] = h;
    wl[n * 256 + k] = __float2half_rn(v - __half2float(h));
}

// ---------------- mma / ldmatrix helpers ----------------
__device__ __forceinline__ void mma_fp16(float* d, const uint32_t* a, const uint32_t* b) {
    asm volatile(
        "mma.sync.aligned.m16n8k16.row.col.f32.f16.f16.f32 "
        "{%0,%1,%2,%3}, {%4,%5,%6,%7}, {%8,%9}, {%0,%1,%2,%3};"
        : "+f"(d[0]), "+f"(d[1]), "+f"(d[2]), "+f"(d[3])
        : "r"(a[0]), "r"(a[1]), "r"(a[2]), "r"(a[3]), "r"(b[0]), "r"(b[1]));
}

__device__ __forceinline__ void ldsm_x4(uint32_t addr, uint32_t* r) {
    asm volatile(
        "ldmatrix.sync.aligned.m8n8.x4.shared.b16 {%0,%1,%2,%3}, [%4];"
        : "=r"(r[0]), "=r"(r[1]), "=r"(r[2]), "=r"(r[3]) : "r"(addr));
}

__device__ __forceinline__ void atomic_fmax(float* p, float v) {
    if (v >= 0.f) atomicMax((int*)p, __float_as_int(v));
    else          atomicMin((unsigned int*)p, __float_as_uint(v));
}

__device__ __forceinline__ uint32_t smem_u32(const void* p) {
    uint32_t a;
    asm("{ .reg .u64 t; cvta.to.shared.u64 t, %1; cvt.u32.u64 %0, t; }"
        : "=r"(a) : "l"(p));
    return a;
}

struct LaneC { int rA, kA, rB, kB; };
__device__ __forceinline__ LaneC lane_consts(int lane) {
    LaneC c;
    c.rA = lane & 15;
    c.kA = (lane >> 4) * 4;
    c.rB = (lane & 7) + ((lane >> 4) << 3);
    c.kB = ((lane >> 3) & 1) * 4;
    return c;
}

// 8-kstep MMA block with hi/lo split weights (node GEMMs)
__device__ __forceinline__ void mma_block_hl(
    uint32_t aSA, uint32_t aWH, uint32_t aWL,
    float acc[4][4][4], int warpRow, int warpCol, const LaneC& L)
{
#pragma unroll
    for (int ks = 0; ks < 8; ks++) {
        int base = ks * 8;
        uint32_t bh[4][2], bl[4][2];
#pragma unroll
        for (int p = 0; p < 2; p++) {
            uint32_t r[4];
            uint32_t off = (uint32_t)(((warpCol + p * 16 + L.rB) * TSH + base + L.kB) * 4);
            ldsm_x4(aWH + off, r);
            bh[2*p][0] = r[0]; bh[2*p][1] = r[1];
            bh[2*p+1][0] = r[2]; bh[2*p+1][1] = r[3];
            ldsm_x4(aWL + off, r);
            bl[2*p][0] = r[0]; bl[2*p][1] = r[1];
            bl[2*p+1][0] = r[2]; bl[2*p+1][1] = r[3];
        }
        uint32_t a[4][4];
#pragma unroll
        for (int mf = 0; mf < 4; mf++) {
            uint32_t off = (uint32_t)(((warpRow + mf * 16 + L.rA) * TSH + base + L.kA) * 4);
            ldsm_x4(aSA + off, a[mf]);
        }
#pragma unroll
        for (int mf = 0; mf < 4; mf++)
#pragma unroll
            for (int nf = 0; nf < 4; nf++) {
                mma_fp16(acc[mf][nf], a[mf], bh[nf]);
                mma_fp16(acc[mf][nf], a[mf], bl[nf]);
            }
    }
}

// async copy of one fp16 tile into padded smem rows
__device__ __forceinline__ void async_w_tile(
    uint32_t dstH, uint32_t dstL,
    const __half* __restrict__ srcH, const __half* __restrict__ srcL,
    int srcStride, int tid)
{
#pragma unroll
    for (int it = 0; it < 8; it++) {
        int lin = tid + it * THREADS;
        int n = lin >> 4, c = lin & 15;
        uint32_t off = (uint32_t)(n * (TSH * 4) + c * 16);
        asm volatile("cp.async.cg.shared.global [%0], [%1], 16;"
                     :: "r"(dstH + off), "l"(srcH + (size_t)n * srcStride + c * 8));
        asm volatile("cp.async.cg.shared.global [%0], [%1], 16;"
                     :: "r"(dstL + off), "l"(srcL + (size_t)n * srcStride + c * 8));
    }
    asm volatile("cp.async.commit_group;" ::: "memory");
}

// fp32 [128][128] input tile -> fp16 smem tile (2 threads/row)
__device__ __forceinline__ void load_in_tile(
    const float* __restrict__ In, int rowBase, uint32_t* sA, int tid)
{
    int r = tid >> 1, h = tid & 1;
    const float4* src = (const float4*)(In + (size_t)(rowBase + r) * HD + h * 64);
    uint32_t* dst = sA + r * TSH + h * 32;
#pragma unroll
    for (int j = 0; j < 8; j++) {
        float4 v0 = src[j * 2], v1 = src[j * 2 + 1];
        __half2 a = __floats2half2_rn(v0.x, v0.y);
        __half2 b = __floats2half2_rn(v0.z, v0.w);
        __half2 c = __floats2half2_rn(v1.x, v1.y);
        __half2 d = __floats2half2_rn(v1.z, v1.w);
        uint4 u = make_uint4(*(uint32_t*)&a, *(uint32_t*)&b,
                             *(uint32_t*)&c, *(uint32_t*)&d);
        *(uint4*)(dst + j * 4) = u;
    }
}

// ---------------- fused A/B node GEMM ----------------
__global__ __launch_bounds__(THREADS) void gemm_ab_kernel(
    const float* __restrict__ pos, const float* __restrict__ inx,
    const __half* __restrict__ WHA, const __half* __restrict__ WLA,
    const float* __restrict__ lb1,
    __half* __restrict__ Ah, __half* __restrict__ Bh)
{
    extern __shared__ char sm[];
    float* sBias = (float*)sm;
    uint32_t sb = smem_u32(sm);
    uint32_t aSA = sb + AB_SA;
    uint32_t aW0H = sb + AB_W0H, aW0L = sb + AB_W0L;
    uint32_t aW1H = sb + AB_W1H, aW1L = sb + AB_W1L;
    uint32_t* sA = (uint32_t*)(sm + AB_SA);

    int tid = threadIdx.x, lane = tid & 31, wid = tid >> 5;
    int rowBase = blockIdx.x * 128;

    async_w_tile(aW0H, aW0L, WHA + 128, WLA + 128, 256, tid);
    async_w_tile(aW1H, aW1L, WHA, WLA, 256, tid);

    if (tid < 128) sBias[tid] = lb1[tid];
    load_in_tile(pos, rowBase, sA, tid);

    asm volatile("cp.async.wait_group 1;" ::: "memory");
    __syncthreads();

    int warpRow = (wid & 1) * 64, warpCol = (wid >> 1) * 32;
    int g = lane >> 2, tg = lane & 3;
    LaneC L = lane_consts(lane);

    float acc[4][4][4];
#pragma unroll
    for (int i = 0; i < 4; i++)
#pragma unroll
        for (int j = 0; j < 4; j++)
#pragma unroll
            for (int q = 0; q < 4; q++) acc[i][j][q] = 0.f;

    mma_block_hl(aSA, aW0H, aW0L, acc, warpRow, warpCol, L);

#pragma unroll
    for (int mf = 0; mf < 4; mf++) {
        size_t r0 = (size_t)rowBase + warpRow + mf * 16 + g;
#pragma unroll
        for (int nf = 0; nf < 4; nf++) {
            int c0 = warpCol + nf * 8 + 2 * tg;
            __half2 p0 = __floats2half2_rn(acc[mf][nf][0], acc[mf][nf][1]);
            __half2 p1 = __floats2half2_rn(acc[mf][nf][2], acc[mf][nf][3]);
            *(uint32_t*)(Bh + r0 * HD + c0)       = *(uint32_t*)&p0;
            *(uint32_t*)(Bh + (r0 + 8) * HD + c0) = *(uint32_t*)&p1;
            acc[mf][nf][0] = __low2float(p0); acc[mf][nf][1] = __high2float(p0);
            acc[mf][nf][2] = __low2float(p1); acc[mf][nf][3] = __high2float(p1);
        }
    }

    __syncthreads();
    load_in_tile(inx, rowBase, sA, tid);
    asm volatile("cp.async.wait_group 0;" ::: "memory");
    __syncthreads();

    mma_block_hl(aSA, aW1H, aW1L, acc, warpRow, warpCol, L);

#pragma unroll
    for (int mf = 0; mf < 4; mf++) {
        size_t r0 = (size_t)rowBase + warpRow + mf * 16 + g;
#pragma unroll
        for (int nf = 0; nf < 4; nf++) {
            int c0 = warpCol + nf * 8 + 2 * tg;
            float b0 = sBias[c0], b1 = sBias[c0 + 1];
            __half2 p0 = __floats2half2_rn(acc[mf][nf][0] + b0, acc[mf][nf][1] + b1);
            __half2 p1 = __floats2half2_rn(acc[mf][nf][2] + b0, acc[mf][nf][3] + b1);
            *(uint32_t*)(Ah + r0 * HD + c0)       = *(uint32_t*)&p0;
            *(uint32_t*)(Ah + (r0 + 8) * HD + c0) = *(uint32_t*)&p1;
        }
    }
}

// ---------------- fused global_nn double GEMM ----------------
__global__ __launch_bounds__(THREADS) void gemm_gg_kernel(
    const float* __restrict__ AGG,
    const __half* __restrict__ WH1, const __half* __restrict__ WL1,
    const __half* __restrict__ WH2, const __half* __restrict__ WL2,
    const float* __restrict__ gb1, const float* __restrict__ gb2,
    float* __restrict__ Out)
{
    extern __shared__ char sm[];
    float* sBias1 = (float*)sm;
    float* sBias2 = (float*)(sm + 512);
    uint32_t sb = smem_u32(sm);
    uint32_t aSA = sb + AB_SA;
    uint32_t aW0H = sb + AB_W0H, aW0L = sb + AB_W0L;
    uint32_t aW1H = sb + AB_W1H, aW1L = sb + AB_W1L;
    uint32_t* sA = (uint32_t*)(sm + AB_SA);

    int tid = threadIdx.x, lane = tid & 31, wid = tid >> 5;
    int rowBase = blockIdx.x * 128;

    async_w_tile(aW0H, aW0L, WH1, WL1, HD, tid);
    async_w_tile(aW1H, aW1L, WH2, WL2, HD, tid);

    if (tid < 128) { sBias1[tid] = gb1[tid]; sBias2[tid] = gb2[tid]; }
    load_in_tile(AGG, rowBase, sA, tid);

    asm volatile("cp.async.wait_group 1;" ::: "memory");
    __syncthreads();

    int warpRow = (wid & 1) * 64, warpCol = (wid >> 1) * 32;
    int g = lane >> 2, tg = lane & 3;
    LaneC L = lane_consts(lane);

    float acc[4][4][4];
#pragma unroll
    for (int i = 0; i < 4; i++)
#pragma unroll
        for (int j = 0; j < 4; j++)
#pragma unroll
            for (int q = 0; q < 4; q++) acc[i][j][q] = 0.f;

    mma_block_hl(aSA, aW0H, aW0L, acc, warpRow, warpCol, L);

    __syncthreads();

#pragma unroll
    for (int mf = 0; mf < 4; mf++) {
        int r0 = warpRow + mf * 16 + g;
#pragma unroll
        for (int nf = 0; nf < 4; nf++) {
            int c0 = warpCol + nf * 8 + 2 * tg;
            float b0 = sBias1[c0], b1 = sBias1[c0 + 1];
            float o0 = fmaxf(acc[mf][nf][0] + b0, 0.f);
            float o1 = fmaxf(acc[mf][nf][1] + b1, 0.f);
            float o2 = fmaxf(acc[mf][nf][2] + b0, 0.f);
            float o3 = fmaxf(acc[mf][nf][3] + b1, 0.f);
            __half2 p0 = __floats2half2_rn(o0, o1);
            __half2 p1 = __floats2half2_rn(o2, o3);
            sA[r0 * TSH + (c0 >> 1)]       = *(uint32_t*)&p0;
            sA[(r0 + 8) * TSH + (c0 >> 1)] = *(uint32_t*)&p1;
            acc[mf][nf][0] = 0.f; acc[mf][nf][1] = 0.f;
            acc[mf][nf][2] = 0.f; acc[mf][nf][3] = 0.f;
        }
    }
    asm volatile("cp.async.wait_group 0;" ::: "memory");
    __syncthreads();

    mma_block_hl(aSA, aW1H, aW1L, acc, warpRow, warpCol, L);

#pragma unroll
    for (int mf = 0; mf < 4; mf++) {
        size_t r0 = (size_t)rowBase + warpRow + mf * 16 + g;
#pragma unroll
        for (int nf = 0; nf < 4; nf++) {
            int c0 = warpCol + nf * 8 + 2 * tg;
            float b0 = sBias2[c0], b1 = sBias2[c0 + 1];
            *(float2*)(Out + r0 * HD + c0) =
                make_float2(acc[mf][nf][0] + b0, acc[mf][nf][1] + b1);
            *(float2*)(Out + (r0 + 8) * HD + c0) =
                make_float2(acc[mf][nf][2] + b0, acc[mf][nf][3] + b1);
        }
    }
}

// ---------------- persistent edge kernel: 2 CTAs/SM, T-reuse staging ----------------
struct GReg {
    uint4 a[4], b[4];
    int d, r;
    bool valid;
};

__device__ __forceinline__ void gather_issue(
    int eBase, int pass, GReg& G,
    const int* __restrict__ ssrc, const int* __restrict__ sdst,
    const __half* __restrict__ A, const __half* __restrict__ B,
    int total, int tid)
{
    int r = pass * 64 + (tid >> 2);
    int q = tid & 3;
    int e = eBase + r;
    G.valid = (e < total);
    int s = 0, d = 0;
    if (G.valid) { s = ssrc[e]; d = sdst[e]; }
    G.d = d; G.r = r;
    const uint4* Ar = (const uint4*)(A + (size_t)s * HD) + q * 4;
    const uint4* Br = (const uint4*)(B + (size_t)d * HD) + q * 4;
#pragma unroll
    for (int i = 0; i < 4; i++) { G.a[i] = Ar[i]; G.b[i] = Br[i]; }
}

__device__ __forceinline__ uint32_t hsubrelu(uint32_t a, uint32_t b) {
    __half2 r = __hmax2(__hsub2(*(__half2*)&a, *(__half2*)&b),
                        __float2half2_rn(0.f));
    return *(uint32_t*)&r;
}

__device__ __forceinline__ void gather_commit(
    const GReg& G, uint32_t* __restrict__ sTn, int* __restrict__ sDn, int tid)
{
    int q = tid & 3;
    if (q == 0) sDn[G.r] = G.valid ? G.d : -1;
    uint32_t* Tr = sTn + G.r * TSH + q * 16;
#pragma unroll
    for (int i = 0; i < 4; i++) {
        uint4 t;
        if (G.valid) {
            t.x = hsubrelu(G.a[i].x, G.b[i].x);
            t.y = hsubrelu(G.a[i].y, G.b[i].y);
            t.z = hsubrelu(G.a[i].z, G.b[i].z);
            t.w = hsubrelu(G.a[i].w, G.b[i].w);
        } else {
            t = make_uint4(0, 0, 0, 0);
        }
        *(uint4*)(Tr + i * 4) = t;
    }
}

// one K-half (4 ksteps of k16), single W, ldmatrix fragments
__device__ __forceinline__ void mma_half(
    uint32_t aST, uint32_t aSW,
    int ks0, float acc[4][4][4], int rowBase, int colBase, const LaneC& L)
{
#pragma unroll
    for (int ks = 0; ks < 4; ks++) {
        int base = (ks0 + ks) * 8;
        uint32_t b[4][2];
#pragma unroll
        for (int p = 0; p < 2; p++) {
            uint32_t r[4];
            uint32_t off = (uint32_t)(((colBase + p * 16 + L.rB) * TSH + base + L.kB) * 4);
            ldsm_x4(aSW + off, r);
            b[2*p][0] = r[0]; b[2*p][1] = r[1];
            b[2*p+1][0] = r[2]; b[2*p+1][1] = r[3];
        }
        uint32_t a[4][4];
#pragma unroll
        for (int mf = 0; mf < 4; mf++) {
            uint32_t off = (uint32_t)(((rowBase + mf * 16 + L.rA) * TSH + base + L.kA) * 4);
            ldsm_x4(aST + off, a[mf]);
        }
#pragma unroll
        for (int mf = 0; mf < 4; mf++)
#pragma unroll
            for (int nf = 0; nf < 4; nf++)
                mma_fp16(acc[mf][nf], a[mf], b[nf]);
    }
}

// stage this warp's acc (rows local 0..63) + bias into fp32 buffer
__device__ __forceinline__ void stage_frag(
    float* __restrict__ sStage, float acc[4][4][4],
    int colBase, int g, int tg, const float* __restrict__ sBias)
{
#pragma unroll
    for (int mf = 0; mf < 4; mf++) {
        int r0 = mf * 16 + g;
#pragma unroll
        for (int nf = 0; nf < 4; nf++) {
            int c0 = colBase + nf * 8 + 2 * tg;
            float b0 = sBias[c0], b1 = sBias[c0 + 1];
            *(float2*)(sStage + r0 * STG + c0) =
                make_float2(acc[mf][nf][0] + b0, acc[mf][nf][1] + b1);
            *(float2*)(sStage + (r0 + 8) * STG + c0) =
                make_float2(acc[mf][nf][2] + b0, acc[mf][nf][3] + b1);
        }
    }
}

// scan 64 staged rows (global rows gbase..gbase+63), 2 row-halves x 128 cols
__device__ __forceinline__ void scan_pass(
    const float* __restrict__ sStage, const int* __restrict__ sDst,
    float* __restrict__ agg, int gbase, int tid)
{
    int c = tid & 127;
    int rh = tid >> 7;
    int rstart = rh * 32, rend = rstart + 32;
    int prev = sDst[gbase + rstart];
    float m = -FLT_MAX;
    for (int r = rstart; r < rend; r++) {
        int d = sDst[gbase + r];
        if (d != prev) {
            if (prev >= 0) atomic_fmax(agg + (size_t)prev * HD + c, m);
            m = -FLT_MAX;
            prev = d;
        }
        m = fmaxf(m, sStage[r * STG + c]);
    }
    if (prev >= 0) atomic_fmax(agg + (size_t)prev * HD + c, m);
}

__global__ __launch_bounds__(THREADS, 2) void edge_mma_kernel(
    const int* __restrict__ ssrc, const int* __restrict__ sdst,
    const __half* __restrict__ A, const __half* __restrict__ B,
    const __half* __restrict__ W2T, const float* __restrict__ b2,
    float* __restrict__ agg, int total)
{
    extern __shared__ char smem[];
    int* sDst = (int*)smem;                 // 128 ints
    float* sBias = (float*)(smem + 1024);
    uint32_t* sT = (uint32_t*)(smem + SM_T);
    float* sStage = (float*)(smem + SM_T);  // reuse T after MMA

    uint32_t sb = smem_u32(smem);
    uint32_t aT = sb + SM_T, aW = sb + SM_W;

    int tid = threadIdx.x;
    int lane = tid & 31, wid = tid >> 5;
    int ntiles = (total + 127) >> 7;

    // One-time: stream W2T (fp16, 32KB) into sW rows
    {
#pragma unroll
        for (int it = 0; it < 8; it++) {
            int linear = tid + it * THREADS;
            int n = linear >> 4, c = linear & 15;
            uint32_t dst = aW + (uint32_t)(n * (TSH * 4) + c * 16);
            const char* src = (const char*)W2T + n * 256 + c * 16;
            asm volatile("cp.async.cg.shared.global [%0], [%1], 16;"
                         :: "r"(dst), "l"(src));
        }
        asm volatile("cp.async.commit_group;" ::: "memory");
    }
    if (tid < 128) sBias[tid] = b2[tid];

    // Prologue: gather first tile
    if (blockIdx.x < ntiles) {
        GReg G;
        gather_issue(blockIdx.x * 128, 0, G, ssrc, sdst, A, B, total, tid);
        gather_commit(G, sT, sDst, tid);
        gather_issue(blockIdx.x * 128, 1, G, ssrc, sdst, A, B, total, tid);
        gather_commit(G, sT, sDst, tid);
    }
    asm volatile("cp.async.wait_group 0;" ::: "memory");
    __syncthreads();

    int rowBase = (wid & 1) * 64;
    int colBase = (wid >> 1) * 32;
    int g = lane >> 2, tg = lane & 3;
    LaneC L = lane_consts(lane);

    for (int ti = blockIdx.x; ti < ntiles; ti += GRID_EDGE) {
        int tn = ti + GRID_EDGE;
        bool hn = tn < ntiles;

        float acc[4][4][4];
#pragma unroll
        for (int i = 0; i < 4; i++)
#pragma unroll
            for (int j = 0; j < 4; j++)
#pragma unroll
                for (int q = 0; q < 4; q++) acc[i][j][q] = 0.f;

        mma_half(aT, aW, 0, acc, rowBase, colBase, L);
        mma_half(aT, aW, 4, acc, rowBase, colBase, L);

        GReg G;
        if (hn) gather_issue(tn * 128, 0, G, ssrc, sdst, A, B, total, tid);

        __syncthreads();   // S1: all MMA reads of sT done

        // pass 0: rows 0..63
        if (rowBase == 0) stage_frag(sStage, acc, colBase, g, tg, sBias);
        __syncthreads();   // S2
        scan_pass(sStage, sDst, agg, 0, tid);
        __syncthreads();   // S3

        // pass 1: rows 64..127
        if (rowBase == 64) stage_frag(sStage, acc, colBase, g, tg, sBias);
        __syncthreads();   // S4
        scan_pass(sStage, sDst, agg, 64, tid);
        __syncthreads();   // S5

        if (hn) {
            gather_commit(G, sT, sDst, tid);
            gather_issue(tn * 128, 1, G, ssrc, sdst, A, B, total, tid);
            gather_commit(G, sT, sDst, tid);
        }
        __syncthreads();   // S6
    }
}

// ---------------- launch ----------------
extern "C" void kernel_launch(void* const* d_in, const int* in_sizes, int n_in,
                              void* d_out, int out_size)
{
    (void)n_in; (void)out_size;
    const float* x   = (const float*)d_in[0];
    const float* pos = (const float*)d_in[1];
    const int* ei    = (const int*)d_in[2];
    const float* p[16];
    for (int i = 0; i < 16; i++) p[i] = (const float*)d_in[3 + i];

    int E = in_sizes[2] / 2;
    int total = E + NODES;

    float *AGG, *H0;
    __half *AH, *BH, *W2T, *WHA, *WLA, *WH1, *WL1, *WH2, *WL2;
    int *CNT, *NEXT, *SSRC, *SDST;
    cudaGetSymbolAddress((void**)&AH, g_Ah);
    cudaGetSymbolAddress((void**)&BH, g_Bh);
    cudaGetSymbolAddress((void**)&AGG, g_agg);
    cudaGetSymbolAddress((void**)&H0, g_h0);
    cudaGetSymbolAddress((void**)&W2T, g_w2t);
    cudaGetSymbolAddress((void**)&WHA, g_whA);
    cudaGetSymbolAddress((void**)&WLA, g_wlA);
    cudaGetSymbolAddress((void**)&WH1, g_wh1);
    cudaGetSymbolAddress((void**)&WL1, g_wl1);
    cudaGetSymbolAddress((void**)&WH2, g_wh2);
    cudaGetSymbolAddress((void**)&WL2, g_wl2);
    cudaGetSymbolAddress((void**)&CNT, g_cnt);
    cudaGetSymbolAddress((void**)&NEXT, g_next);
    cudaGetSymbolAddress((void**)&SSRC, g_ssrc);
    cudaGetSymbolAddress((void**)&SDST, g_sdst);

    cudaFuncSetAttribute(edge_mma_kernel, cudaFuncAttributeMaxDynamicSharedMemorySize, EDGE_SMEM);
    cudaFuncSetAttribute(gemm_ab_kernel, cudaFuncAttributeMaxDynamicSharedMemorySize, AB_SMEM);
    cudaFuncSetAttribute(gemm_gg_kernel, cudaFuncAttributeMaxDynamicSharedMemorySize, AB_SMEM);

    int gemmBlocks = NODES / 128;              // 512
    int fillBlocks = (NODES * HD / 4 + THREADS - 1) / THREADS;
    int eBlocks = (total + THREADS - 1) / THREADS;

    // Build dst-sorted edge list once (layer-invariant)
    zero_i32<<<(NODES + THREADS - 1) / THREADS, THREADS>>>(CNT, NODES);
    hist_kernel<<<eBlocks, THREADS>>>(ei, CNT, E, total);
    scan_kernel<<<1, SCAN_T>>>(CNT, NEXT);
    scatter_kernel<<<eBlocks, THREADS>>>(ei, NEXT, SSRC, SDST, E, total);

    for (int layer = 0; layer < 2; layer++) {
        const float* lw1 = p[layer * 8 + 0];
        const float* lb1 = p[layer * 8 + 1];
        const float* lw2 = p[layer * 8 + 2];
        const float* lb2 = p[layer * 8 + 3];
        const float* gw1 = p[layer * 8 + 4];
        const float* gb1 = p[layer * 8 + 5];
        const float* gw2 = p[layer * 8 + 6];
        const float* gb2 = p[layer * 8 + 7];
        const float* inx = (layer == 0) ? x : H0;
        float* outp = (layer == 0) ? H0 : (float*)d_out;

        prep_whA_kernel<<<2 * HD, HD>>>(lw1, WHA, WLA);
        prep_w2t_kernel<<<HD, HD>>>(lw2, W2T);
        prep_wh_kernel<<<HD, HD>>>(gw1, WH1, WL1);
        prep_wh_kernel<<<HD, HD>>>(gw2, WH2, WL2);

        gemm_ab_kernel<<<gemmBlocks, THREADS, AB_SMEM>>>(
            pos, inx, WHA, WLA, lb1, AH, BH);

        fill_kernel<<<fillBlocks, THREADS>>>((float4*)AGG, -FLT_MAX, NODES * HD / 4);
        edge_mma_kernel<<<GRID_EDGE, THREADS, EDGE_SMEM>>>(
            SSRC, SDST, AH, BH, W2T, lb2, AGG, total);

        gemm_gg_kernel<<<gemmBlocks, THREADS, AB_SMEM>>>(
            AGG, WH1, WL1, WH2, WL2, gb1, gb2, outp);
    }
}

// round 13
// speedup vs baseline: 2.0228x; 1.0091x over previous
#include <cuda_runtime.h>
#include <cuda_fp16.h>
#include <float.h>
#include <stdint.h>

#define NODES 65536
#define HD 128
#define THREADS 256
#define TSH 68                       // uint32 (half2) stride per 128-half row
#define STG 132                      // fp32 staging stride (edge epilogue)
#define MAXEDGES (1048576 + NODES)
#define GRID_EDGE 304

// edge kernel smem map (bytes): header 2048 | T (tile / stage reuse) | W
#define HBUF (128 * TSH * 4)         // 34816
#define SM_T 2048
#define SM_W (2048 + HBUF)
#define EDGE_SMEM (2048 + 2 * HBUF)  // 71680 -> 2 CTAs/SM

// node GEMM smem: header(1024) + sA + WH + WL   -> 2 CTAs/SM
#define AB_SA 1024
#define AB_WH (1024 + HBUF)
#define AB_WL (1024 + 2 * HBUF)
#define AB_SMEM (1024 + 3 * HBUF)    // 105472

// ---------------- scratch ----------------
__device__ __half g_Ah[(size_t)NODES * HD];
__device__ __half g_Bh[(size_t)NODES * HD];
__device__ float g_agg[(size_t)NODES * HD];
__device__ float g_h0[(size_t)NODES * HD];
__device__ __half g_w2t[HD * HD];
__device__ __half g_whA[HD * 256];
__device__ __half g_wlA[HD * 256];
__device__ __half g_wh1[HD * HD];
__device__ __half g_wl1[HD * HD];
__device__ __half g_wh2[HD * HD];
__device__ __half g_wl2[HD * HD];
__device__ int g_cnt[NODES];
__device__ int g_next[NODES];
__device__ int g_ssrc[MAXEDGES];
__device__ int g_sdst[MAXEDGES];

__global__ __launch_bounds__(THREADS) void fill_kernel(float4* p, float v, int n4) {
    int i = blockIdx.x * blockDim.x + threadIdx.x;
    if (i < n4) p[i] = make_float4(v, v, v, v);
}

__global__ __launch_bounds__(THREADS) void zero_i32(int* p, int n) {
    int i = blockIdx.x * blockDim.x + threadIdx.x;
    if (i < n) p[i] = 0;
}

// ---------------- counting sort by dst (once per launch) ----------------
__global__ __launch_bounds__(THREADS) void hist_kernel(
    const int* __restrict__ ei, int* __restrict__ cnt, int E, int total)
{
    int e = blockIdx.x * blockDim.x + threadIdx.x;
    if (e < total) {
        int d = (e < E) ? ei[E + e] : (e - E);
        atomicAdd(&cnt[d], 1);
    }
}

#define SCAN_T 1024
#define CHUNK (NODES / SCAN_T)   // 64
__global__ __launch_bounds__(SCAN_T) void scan_kernel(
    const int* __restrict__ cnt, int* __restrict__ next)
{
    __shared__ int part[SCAN_T];
    int t = threadIdx.x;
    int base = t * CHUNK;
    int sum = 0;
#pragma unroll 4
    for (int i = 0; i < CHUNK; i++) sum += cnt[base + i];
    part[t] = sum;
    __syncthreads();
    for (int off = 1; off < SCAN_T; off <<= 1) {
        int v = (t >= off) ? part[t - off] : 0;
        __syncthreads();
        part[t] += v;
        __syncthreads();
    }
    int off = part[t] - sum;   // exclusive
#pragma unroll 4
    for (int i = 0; i < CHUNK; i++) {
        next[base + i] = off;
        off += cnt[base + i];
    }
}

__global__ __launch_bounds__(THREADS) void scatter_kernel(
    const int* __restrict__ ei, int* __restrict__ next,
    int* __restrict__ ssrc, int* __restrict__ sdst, int E, int total)
{
    int e = blockIdx.x * blockDim.x + threadIdx.x;
    if (e < total) {
        int s, d;
        if (e < E) { s = ei[e]; d = ei[E + e]; }
        else       { s = e - E; d = s; }
        int pos = atomicAdd(&next[d], 1);
        ssrc[pos] = s;
        sdst[pos] = d;
    }
}

// ---------------- unified weight prep (one launch per layer) ----------------
// blocks 0..255: lw1 (256xk)->whA/wlA; 256..383: lw2->w2t; 384..511: gw1; 512..639: gw2
__global__ __launch_bounds__(HD) void prep_all_kernel(
    const float* __restrict__ lw1, const float* __restrict__ lw2,
    const float* __restrict__ gw1, const float* __restrict__ gw2,
    __half* __restrict__ whA, __half* __restrict__ wlA,
    __half* __restrict__ w2t,
    __half* __restrict__ wh1, __half* __restrict__ wl1,
    __half* __restrict__ wh2, __half* __restrict__ wl2)
{
    int b = blockIdx.x, n = threadIdx.x;
    if (b < 256) {
        int k = b;
        float v = lw1[k * HD + n];
        __half h = __float2half_rn(v);
        whA[n * 256 + k] = h;
        wlA[n * 256 + k] = __float2half_rn(v - __half2float(h));
    } else if (b < 384) {
        int nn = b - 256;  // output feature
        w2t[nn * HD + n] = __float2half(lw2[n * HD + nn]);
    } else if (b < 512) {
        int k = b - 384;
        float v = gw1[k * HD + n];
        __half h = __float2half_rn(v);
        wh1[n * HD + k] = h;
        wl1[n * HD + k] = __float2half_rn(v - __half2float(h));
    } else {
        int k = b - 512;
        float v = gw2[k * HD + n];
        __half h = __float2half_rn(v);
        wh2[n * HD + k] = h;
        wl2[n * HD + k] = __float2half_rn(v - __half2float(h));
    }
}

// ---------------- mma / ldmatrix helpers ----------------
__device__ __forceinline__ void mma_fp16(float* d, const uint32_t* a, const uint32_t* b) {
    asm volatile(
        "mma.sync.aligned.m16n8k16.row.col.f32.f16.f16.f32 "
        "{%0,%1,%2,%3}, {%4,%5,%6,%7}, {%8,%9}, {%0,%1,%2,%3};"
        : "+f"(d[0]), "+f"(d[1]), "+f"(d[2]), "+f"(d[3])
        : "r"(a[0]), "r"(a[1]), "r"(a[2]), "r"(a[3]), "r"(b[0]), "r"(b[1]));
}

__device__ __forceinline__ void ldsm_x4(uint32_t addr, uint32_t* r) {
    asm volatile(
        "ldmatrix.sync.aligned.m8n8.x4.shared.b16 {%0,%1,%2,%3}, [%4];"
        : "=r"(r[0]), "=r"(r[1]), "=r"(r[2]), "=r"(r[3]) : "r"(addr));
}

__device__ __forceinline__ void atomic_fmax(float* p, float v) {
    if (v >= 0.f) atomicMax((int*)p, __float_as_int(v));
    else          atomicMin((unsigned int*)p, __float_as_uint(v));
}

__device__ __forceinline__ uint32_t smem_u32(const void* p) {
    uint32_t a;
    asm("{ .reg .u64 t; cvta.to.shared.u64 t, %1; cvt.u32.u64 %0, t; }"
        : "=r"(a) : "l"(p));
    return a;
}

struct LaneC { int rA, kA, rB, kB; };
__device__ __forceinline__ LaneC lane_consts(int lane) {
    LaneC c;
    c.rA = lane & 15;
    c.kA = (lane >> 4) * 4;
    c.rB = (lane & 7) + ((lane >> 4) << 3);
    c.kB = ((lane >> 3) & 1) * 4;
    return c;
}

// 8-kstep MMA block with hi/lo split weights (node GEMMs)
__device__ __forceinline__ void mma_block_hl(
    uint32_t aSA, uint32_t aWH, uint32_t aWL,
    float acc[4][4][4], int warpRow, int warpCol, const LaneC& L)
{
#pragma unroll
    for (int ks = 0; ks < 8; ks++) {
        int base = ks * 8;
        uint32_t bh[4][2], bl[4][2];
#pragma unroll
        for (int p = 0; p < 2; p++) {
            uint32_t r[4];
            uint32_t off = (uint32_t)(((warpCol + p * 16 + L.rB) * TSH + base + L.kB) * 4);
            ldsm_x4(aWH + off, r);
            bh[2*p][0] = r[0]; bh[2*p][1] = r[1];
            bh[2*p+1][0] = r[2]; bh[2*p+1][1] = r[3];
            ldsm_x4(aWL + off, r);
            bl[2*p][0] = r[0]; bl[2*p][1] = r[1];
            bl[2*p+1][0] = r[2]; bl[2*p+1][1] = r[3];
        }
        uint32_t a[4][4];
#pragma unroll
        for (int mf = 0; mf < 4; mf++) {
            uint32_t off = (uint32_t)(((warpRow + mf * 16 + L.rA) * TSH + base + L.kA) * 4);
            ldsm_x4(aSA + off, a[mf]);
        }
#pragma unroll
        for (int mf = 0; mf < 4; mf++)
#pragma unroll
            for (int nf = 0; nf < 4; nf++) {
                mma_fp16(acc[mf][nf], a[mf], bh[nf]);
                mma_fp16(acc[mf][nf], a[mf], bl[nf]);
            }
    }
}

// async copy of one fp16 tile pair into padded smem rows
__device__ __forceinline__ void async_w_tile(
    uint32_t dstH, uint32_t dstL,
    const __half* __restrict__ srcH, const __half* __restrict__ srcL,
    int srcStride, int tid)
{
#pragma unroll
    for (int it = 0; it < 8; it++) {
        int lin = tid + it * THREADS;
        int n = lin >> 4, c = lin & 15;
        uint32_t off = (uint32_t)(n * (TSH * 4) + c * 16);
        asm volatile("cp.async.cg.shared.global [%0], [%1], 16;"
                     :: "r"(dstH + off), "l"(srcH + (size_t)n * srcStride + c * 8));
        asm volatile("cp.async.cg.shared.global [%0], [%1], 16;"
                     :: "r"(dstL + off), "l"(srcL + (size_t)n * srcStride + c * 8));
    }
    asm volatile("cp.async.commit_group;" ::: "memory");
}

// fp32 [128][128] input tile -> fp16 smem tile (2 threads/row)
__device__ __forceinline__ void load_in_tile(
    const float* __restrict__ In, int rowBase, uint32_t* sA, int tid)
{
    int r = tid >> 1, h = tid & 1;
    const float4* src = (const float4*)(In + (size_t)(rowBase + r) * HD + h * 64);
    uint32_t* dst = sA + r * TSH + h * 32;
#pragma unroll
    for (int j = 0; j < 8; j++) {
        float4 v0 = src[j * 2], v1 = src[j * 2 + 1];
        __half2 a = __floats2half2_rn(v0.x, v0.y);
        __half2 b = __floats2half2_rn(v0.z, v0.w);
        __half2 c = __floats2half2_rn(v1.x, v1.y);
        __half2 d = __floats2half2_rn(v1.z, v1.w);
        uint4 u = make_uint4(*(uint32_t*)&a, *(uint32_t*)&b,
                             *(uint32_t*)&c, *(uint32_t*)&d);
        *(uint4*)(dst + j * 4) = u;
    }
}

// ---------------- fused A/B node GEMM (2 CTAs/SM, sequential W) ----------------
__global__ __launch_bounds__(THREADS, 2) void gemm_ab_kernel(
    const float* __restrict__ pos, const float* __restrict__ inx,
    const __half* __restrict__ WHA, const __half* __restrict__ WLA,
    const float* __restrict__ lb1,
    __half* __restrict__ Ah, __half* __restrict__ Bh)
{
    extern __shared__ char sm[];
    float* sBias = (float*)sm;
    uint32_t sb = smem_u32(sm);
    uint32_t aSA = sb + AB_SA;
    uint32_t aWH = sb + AB_WH, aWL = sb + AB_WL;
    uint32_t* sA = (uint32_t*)(sm + AB_SA);

    int tid = threadIdx.x, lane = tid & 31, wid = tid >> 5;
    int rowBase = blockIdx.x * 128;

    async_w_tile(aWH, aWL, WHA + 128, WLA + 128, 256, tid);   // Wp

    if (tid < 128) sBias[tid] = lb1[tid];
    load_in_tile(pos, rowBase, sA, tid);

    asm volatile("cp.async.wait_group 0;" ::: "memory");
    __syncthreads();

    int warpRow = (wid & 1) * 64, warpCol = (wid >> 1) * 32;
    int g = lane >> 2, tg = lane & 3;
    LaneC L = lane_consts(lane);

    float acc[4][4][4];
#pragma unroll
    for (int i = 0; i < 4; i++)
#pragma unroll
        for (int j = 0; j < 4; j++)
#pragma unroll
            for (int q = 0; q < 4; q++) acc[i][j][q] = 0.f;

    mma_block_hl(aSA, aWH, aWL, acc, warpRow, warpCol, L);

#pragma unroll
    for (int mf = 0; mf < 4; mf++) {
        size_t r0 = (size_t)rowBase + warpRow + mf * 16 + g;
#pragma unroll
        for (int nf = 0; nf < 4; nf++) {
            int c0 = warpCol + nf * 8 + 2 * tg;
            __half2 p0 = __floats2half2_rn(acc[mf][nf][0], acc[mf][nf][1]);
            __half2 p1 = __floats2half2_rn(acc[mf][nf][2], acc[mf][nf][3]);
            *(uint32_t*)(Bh + r0 * HD + c0)       = *(uint32_t*)&p0;
            *(uint32_t*)(Bh + (r0 + 8) * HD + c0) = *(uint32_t*)&p1;
            acc[mf][nf][0] = __low2float(p0); acc[mf][nf][1] = __high2float(p0);
            acc[mf][nf][2] = __low2float(p1); acc[mf][nf][3] = __high2float(p1);
        }
    }

    __syncthreads();                                   // all reads of sA/W done
    async_w_tile(aWH, aWL, WHA, WLA, 256, tid);        // Wx
    load_in_tile(inx, rowBase, sA, tid);
    asm volatile("cp.async.wait_group 0;" ::: "memory");
    __syncthreads();

    mma_block_hl(aSA, aWH, aWL, acc, warpRow, warpCol, L);

#pragma unroll
    for (int mf = 0; mf < 4; mf++) {
        size_t r0 = (size_t)rowBase + warpRow + mf * 16 + g;
#pragma unroll
        for (int nf = 0; nf < 4; nf++) {
            int c0 = warpCol + nf * 8 + 2 * tg;
            float b0 = sBias[c0], b1 = sBias[c0 + 1];
            __half2 p0 = __floats2half2_rn(acc[mf][nf][0] + b0, acc[mf][nf][1] + b1);
            __half2 p1 = __floats2half2_rn(acc[mf][nf][2] + b0, acc[mf][nf][3] + b1);
            *(uint32_t*)(Ah + r0 * HD + c0)       = *(uint32_t*)&p0;
            *(uint32_t*)(Ah + (r0 + 8) * HD + c0) = *(uint32_t*)&p1;
        }
    }
}

// ---------------- fused global_nn double GEMM (2 CTAs/SM, sequential W) ----------------
__global__ __launch_bounds__(THREADS, 2) void gemm_gg_kernel(
    const float* __restrict__ AGG,
    const __half* __restrict__ WH1, const __half* __restrict__ WL1,
    const __half* __restrict__ WH2, const __half* __restrict__ WL2,
    const float* __restrict__ gb1, const float* __restrict__ gb2,
    float* __restrict__ Out)
{
    extern __shared__ char sm[];
    float* sBias1 = (float*)sm;
    float* sBias2 = (float*)(sm + 512);
    uint32_t sb = smem_u32(sm);
    uint32_t aSA = sb + AB_SA;
    uint32_t aWH = sb + AB_WH, aWL = sb + AB_WL;
    uint32_t* sA = (uint32_t*)(sm + AB_SA);

    int tid = threadIdx.x, lane = tid & 31, wid = tid >> 5;
    int rowBase = blockIdx.x * 128;

    async_w_tile(aWH, aWL, WH1, WL1, HD, tid);

    if (tid < 128) { sBias1[tid] = gb1[tid]; sBias2[tid] = gb2[tid]; }
    load_in_tile(AGG, rowBase, sA, tid);

    asm volatile("cp.async.wait_group 0;" ::: "memory");
    __syncthreads();

    int warpRow = (wid & 1) * 64, warpCol = (wid >> 1) * 32;
    int g = lane >> 2, tg = lane & 3;
    LaneC L = lane_consts(lane);

    float acc[4][4][4];
#pragma unroll
    for (int i = 0; i < 4; i++)
#pragma unroll
        for (int j = 0; j < 4; j++)
#pragma unroll
            for (int q = 0; q < 4; q++) acc[i][j][q] = 0.f;

    mma_block_hl(aSA, aWH, aWL, acc, warpRow, warpCol, L);

    __syncthreads();                           // all reads of sA/W done
    async_w_tile(aWH, aWL, WH2, WL2, HD, tid); // second weight pair

    // relu(acc + gb1) -> fp16 back into sA
#pragma unroll
    for (int mf = 0; mf < 4; mf++) {
        int r0 = warpRow + mf * 16 + g;
#pragma unroll
        for (int nf = 0; nf < 4; nf++) {
            int c0 = warpCol + nf * 8 + 2 * tg;
            float b0 = sBias1[c0], b1 = sBias1[c0 + 1];
            float o0 = fmaxf(acc[mf][nf][0] + b0, 0.f);
            float o1 = fmaxf(acc[mf][nf][1] + b1, 0.f);
            float o2 = fmaxf(acc[mf][nf][2] + b0, 0.f);
            float o3 = fmaxf(acc[mf][nf][3] + b1, 0.f);
            __half2 p0 = __floats2half2_rn(o0, o1);
            __half2 p1 = __floats2half2_rn(o2, o3);
            sA[r0 * TSH + (c0 >> 1)]       = *(uint32_t*)&p0;
            sA[(r0 + 8) * TSH + (c0 >> 1)] = *(uint32_t*)&p1;
            acc[mf][nf][0] = 0.f; acc[mf][nf][1] = 0.f;
            acc[mf][nf][2] = 0.f; acc[mf][nf][3] = 0.f;
        }
    }
    asm volatile("cp.async.wait_group 0;" ::: "memory");
    __syncthreads();

    mma_block_hl(aSA, aWH, aWL, acc, warpRow, warpCol, L);

#pragma unroll
    for (int mf = 0; mf < 4; mf++) {
        size_t r0 = (size_t)rowBase + warpRow + mf * 16 + g;
#pragma unroll
        for (int nf = 0; nf < 4; nf++) {
            int c0 = warpCol + nf * 8 + 2 * tg;
            float b0 = sBias2[c0], b1 = sBias2[c0 + 1];
            *(float2*)(Out + r0 * HD + c0) =
                make_float2(acc[mf][nf][0] + b0, acc[mf][nf][1] + b1);
            *(float2*)(Out + (r0 + 8) * HD + c0) =
                make_float2(acc[mf][nf][2] + b0, acc[mf][nf][3] + b1);
        }
    }
}

// ---------------- persistent edge kernel: 2 CTAs/SM, T-reuse staging ----------------
struct GReg {
    uint4 a[4], b[4];
    int d, r;
    bool valid;
};

__device__ __forceinline__ void gather_issue(
    int eBase, int pass, GReg& G,
    const int* __restrict__ ssrc, const int* __restrict__ sdst,
    const __half* __restrict__ A, const __half* __restrict__ B,
    int total, int tid)
{
    int r = pass * 64 + (tid >> 2);
    int q = tid & 3;
    int e = eBase + r;
    G.valid = (e < total);
    int s = 0, d = 0;
    if (G.valid) { s = ssrc[e]; d = sdst[e]; }
    G.d = d; G.r = r;
    const uint4* Ar = (const uint4*)(A + (size_t)s * HD) + q * 4;
    const uint4* Br = (const uint4*)(B + (size_t)d * HD) + q * 4;
#pragma unroll
    for (int i = 0; i < 4; i++) { G.a[i] = Ar[i]; G.b[i] = Br[i]; }
}

__device__ __forceinline__ uint32_t hsubrelu(uint32_t a, uint32_t b) {
    __half2 r = __hmax2(__hsub2(*(__half2*)&a, *(__half2*)&b),
                        __float2half2_rn(0.f));
    return *(uint32_t*)&r;
}

__device__ __forceinline__ void gather_commit(
    const GReg& G, uint32_t* __restrict__ sTn, int* __restrict__ sDn, int tid)
{
    int q = tid & 3;
    if (q == 0) sDn[G.r] = G.valid ? G.d : -1;
    uint32_t* Tr = sTn + G.r * TSH + q * 16;
#pragma unroll
    for (int i = 0; i < 4; i++) {
        uint4 t;
        if (G.valid) {
            t.x = hsubrelu(G.a[i].x, G.b[i].x);
            t.y = hsubrelu(G.a[i].y, G.b[i].y);
            t.z = hsubrelu(G.a[i].z, G.b[i].z);
            t.w = hsubrelu(G.a[i].w, G.b[i].w);
        } else {
            t = make_uint4(0, 0, 0, 0);
        }
        *(uint4*)(Tr + i * 4) = t;
    }
}

// one K-half (4 ksteps of k16), single W, ldmatrix fragments
__device__ __forceinline__ void mma_half(
    uint32_t aST, uint32_t aSW,
    int ks0, float acc[4][4][4], int rowBase, int colBase, const LaneC& L)
{
#pragma unroll
    for (int ks = 0; ks < 4; ks++) {
        int base = (ks0 + ks) * 8;
        uint32_t b[4][2];
#pragma unroll
        for (int p = 0; p < 2; p++) {
            uint32_t r[4];
            uint32_t off = (uint32_t)(((colBase + p * 16 + L.rB) * TSH + base + L.kB) * 4);
            ldsm_x4(aSW + off, r);
            b[2*p][0] = r[0]; b[2*p][1] = r[1];
            b[2*p+1][0] = r[2]; b[2*p+1][1] = r[3];
        }
        uint32_t a[4][4];
#pragma unroll
        for (int mf = 0; mf < 4; mf++) {
            uint32_t off = (uint32_t)(((rowBase + mf * 16 + L.rA) * TSH + base + L.kA) * 4);
            ldsm_x4(aST + off, a[mf]);
        }
#pragma unroll
        for (int mf = 0; mf < 4; mf++)
#pragma unroll
            for (int nf = 0; nf < 4; nf++)
                mma_fp16(acc[mf][nf], a[mf], b[nf]);
    }
}

__device__ __forceinline__ void stage_frag(
    float* __restrict__ sStage, float acc[4][4][4],
    int colBase, int g, int tg, const float* __restrict__ sBias)
{
#pragma unroll
    for (int mf = 0; mf < 4; mf++) {
        int r0 = mf * 16 + g;
#pragma unroll
        for (int nf = 0; nf < 4; nf++) {
            int c0 = colBase + nf * 8 + 2 * tg;
            float b0 = sBias[c0], b1 = sBias[c0 + 1];
            *(float2*)(sStage + r0 * STG + c0) =
                make_float2(acc[mf][nf][0] + b0, acc[mf][nf][1] + b1);
            *(float2*)(sStage + (r0 + 8) * STG + c0) =
                make_float2(acc[mf][nf][2] + b0, acc[mf][nf][3] + b1);
        }
    }
}

__device__ __forceinline__ void scan_pass(
    const float* __restrict__ sStage, const int* __restrict__ sDst,
    float* __restrict__ agg, int gbase, int tid)
{
    int c = tid & 127;
    int rh = tid >> 7;
    int rstart = rh * 32, rend = rstart + 32;
    int prev = sDst[gbase + rstart];
    float m = -FLT_MAX;
    for (int r = rstart; r < rend; r++) {
        int d = sDst[gbase + r];
        if (d != prev) {
            if (prev >= 0) atomic_fmax(agg + (size_t)prev * HD + c, m);
            m = -FLT_MAX;
            prev = d;
        }
        m = fmaxf(m, sStage[r * STG + c]);
    }
    if (prev >= 0) atomic_fmax(agg + (size_t)prev * HD + c, m);
}

__global__ __launch_bounds__(THREADS, 2) void edge_mma_kernel(
    const int* __restrict__ ssrc, const int* __restrict__ sdst,
    const __half* __restrict__ A, const __half* __restrict__ B,
    const __half* __restrict__ W2T, const float* __restrict__ b2,
    float* __restrict__ agg, int total)
{
    extern __shared__ char smem[];
    int* sDst = (int*)smem;
    float* sBias = (float*)(smem + 1024);
    uint32_t* sT = (uint32_t*)(smem + SM_T);
    float* sStage = (float*)(smem + SM_T);  // reuse T after MMA

    uint32_t sb = smem_u32(smem);
    uint32_t aT = sb + SM_T, aW = sb + SM_W;

    int tid = threadIdx.x;
    int lane = tid & 31, wid = tid >> 5;
    int ntiles = (total + 127) >> 7;

    // One-time: stream W2T (fp16, 32KB) into sW rows
    {
#pragma unroll
        for (int it = 0; it < 8; it++) {
            int linear = tid + it * THREADS;
            int n = linear >> 4, c = linear & 15;
            uint32_t dst = aW + (uint32_t)(n * (TSH * 4) + c * 16);
            const char* src = (const char*)W2T + n * 256 + c * 16;
            asm volatile("cp.async.cg.shared.global [%0], [%1], 16;"
                         :: "r"(dst), "l"(src));
        }
        asm volatile("cp.async.commit_group;" ::: "memory");
    }
    if (tid < 128) sBias[tid] = b2[tid];

    if (blockIdx.x < ntiles) {
        GReg G;
        gather_issue(blockIdx.x * 128, 0, G, ssrc, sdst, A, B, total, tid);
        gather_commit(G, sT, sDst, tid);
        gather_issue(blockIdx.x * 128, 1, G, ssrc, sdst, A, B, total, tid);
        gather_commit(G, sT, sDst, tid);
    }
    asm volatile("cp.async.wait_group 0;" ::: "memory");
    __syncthreads();

    int rowBase = (wid & 1) * 64;
    int colBase = (wid >> 1) * 32;
    int g = lane >> 2, tg = lane & 3;
    LaneC L = lane_consts(lane);

    for (int ti = blockIdx.x; ti < ntiles; ti += GRID_EDGE) {
        int tn = ti + GRID_EDGE;
        bool hn = tn < ntiles;

        float acc[4][4][4];
#pragma unroll
        for (int i = 0; i < 4; i++)
#pragma unroll
            for (int j = 0; j < 4; j++)
#pragma unroll
                for (int q = 0; q < 4; q++) acc[i][j][q] = 0.f;

        mma_half(aT, aW, 0, acc, rowBase, colBase, L);
        mma_half(aT, aW, 4, acc, rowBase, colBase, L);

        GReg G;
        if (hn) gather_issue(tn * 128, 0, G, ssrc, sdst, A, B, total, tid);

        __syncthreads();   // S1: all MMA reads of sT done

        if (rowBase == 0) stage_frag(sStage, acc, colBase, g, tg, sBias);
        __syncthreads();   // S2
        scan_pass(sStage, sDst, agg, 0, tid);
        __syncthreads();   // S3

        if (rowBase == 64) stage_frag(sStage, acc, colBase, g, tg, sBias);
        __syncthreads();   // S4
        scan_pass(sStage, sDst, agg, 64, tid);
        __syncthreads();   // S5

        if (hn) {
            gather_commit(G, sT, sDst, tid);
            gather_issue(tn * 128, 1, G, ssrc, sdst, A, B, total, tid);
            gather_commit(G, sT, sDst, tid);
        }
        __syncthreads();   // S6
    }
}

// ---------------- launch ----------------
extern "C" void kernel_launch(void* const* d_in, const int* in_sizes, int n_in,
                              void* d_out, int out_size)
{
    (void)n_in; (void)out_size;
    const float* x   = (const float*)d_in[0];
    const float* pos = (const float*)d_in[1];
    const int* ei    = (const int*)d_in[2];
    const float* p[16];
    for (int i = 0; i < 16; i++) p[i] = (const float*)d_in[3 + i];

    int E = in_sizes[2] / 2;
    int total = E + NODES;

    float *AGG, *H0;
    __half *AH, *BH, *W2T, *WHA, *WLA, *WH1, *WL1, *WH2, *WL2;
    int *CNT, *NEXT, *SSRC, *SDST;
    cudaGetSymbolAddress((void**)&AH, g_Ah);
    cudaGetSymbolAddress((void**)&BH, g_Bh);
    cudaGetSymbolAddress((void**)&AGG, g_agg);
    cudaGetSymbolAddress((void**)&H0, g_h0);
    cudaGetSymbolAddress((void**)&W2T, g_w2t);
    cudaGetSymbolAddress((void**)&WHA, g_whA);
    cudaGetSymbolAddress((void**)&WLA, g_wlA);
    cudaGetSymbolAddress((void**)&WH1, g_wh1);
    cudaGetSymbolAddress((void**)&WL1, g_wl1);
    cudaGetSymbolAddress((void**)&WH2, g_wh2);
    cudaGetSymbolAddress((void**)&WL2, g_wl2);
    cudaGetSymbolAddress((void**)&CNT, g_cnt);
    cudaGetSymbolAddress((void**)&NEXT, g_next);
    cudaGetSymbolAddress((void**)&SSRC, g_ssrc);
    cudaGetSymbolAddress((void**)&SDST, g_sdst);

    cudaFuncSetAttribute(edge_mma_kernel, cudaFuncAttributeMaxDynamicSharedMemorySize, EDGE_SMEM);
    cudaFuncSetAttribute(gemm_ab_kernel, cudaFuncAttributeMaxDynamicSharedMemorySize, AB_SMEM);
    cudaFuncSetAttribute(gemm_gg_kernel, cudaFuncAttributeMaxDynamicSharedMemorySize, AB_SMEM);

    int gemmBlocks = NODES / 128;              // 512
    int fillBlocks = (NODES * HD / 4 + THREADS - 1) / THREADS;
    int eBlocks = (total + THREADS - 1) / THREADS;

    // Build dst-sorted edge list once (layer-invariant)
    zero_i32<<<(NODES + THREADS - 1) / THREADS, THREADS>>>(CNT, NODES);
    hist_kernel<<<eBlocks, THREADS>>>(ei, CNT, E, total);
    scan_kernel<<<1, SCAN_T>>>(CNT, NEXT);
    scatter_kernel<<<eBlocks, THREADS>>>(ei, NEXT, SSRC, SDST, E, total);

    for (int layer = 0; layer < 2; layer++) {
        const float* lw1 = p[layer * 8 + 0];
        const float* lb1 = p[layer * 8 + 1];
        const float* lw2 = p[layer * 8 + 2];
        const float* lb2 = p[layer * 8 + 3];
        const float* gw1 = p[layer * 8 + 4];
        const float* gb1 = p[layer * 8 + 5];
        const float* gw2 = p[layer * 8 + 6];
        const float* gb2 = p[layer * 8 + 7];
        const float* inx = (layer == 0) ? x : H0;
        float* outp = (layer == 0) ? H0 : (float*)d_out;

        prep_all_kernel<<<640, HD>>>(lw1, lw2, gw1, gw2,
                                     WHA, WLA, W2T, WH1, WL1, WH2, WL2);

        gemm_ab_kernel<<<gemmBlocks, THREADS, AB_SMEM>>>(
            pos, inx, WHA, WLA, lb1, AH, BH);

        fill_kernel<<<fillBlocks, THREADS>>>((float4*)AGG, -FLT_MAX, NODES * HD / 4);
        edge_mma_kernel<<<GRID_EDGE, THREADS, EDGE_SMEM>>>(
            SSRC, SDST, AH, BH, W2T, lb2, AGG, total);

        gemm_gg_kernel<<<gemmBlocks, THREADS, AB_SMEM>>>(
            AGG, WH1, WL1, WH2, WL2, gb1, gb2, outp);
    }
}

// round 14
// speedup vs baseline: 2.0941x; 1.0353x over previous
#include <cuda_runtime.h>
#include <cuda_fp16.h>
#include <float.h>
#include <stdint.h>

#define NODES 65536
#define HD 128
#define THREADS 256
#define TSH 68                       // uint32 (half2) stride per 128-half row
#define STG 132                      // fp32 staging stride (edge epilogue)
#define MAXEDGES (1048576 + NODES)
#define GRID_EDGE 304

// edge kernel smem map (bytes)
#define HBUF (128 * TSH * 4)         // 34816
#define SM_T 2048
#define SM_W (2048 + HBUF)
#define SM_STG (2048 + 2 * HBUF)
#define EDGE_SMEM (SM_STG + 64 * STG * 4)   // 105472 -> 2 CTAs/SM

// node GEMM smem: header(1024) + sA + WH + WL   -> 2 CTAs/SM
#define AB_SA 1024
#define AB_WH (1024 + HBUF)
#define AB_WL (1024 + 2 * HBUF)
#define AB_SMEM (1024 + 3 * HBUF)    // 105472

// ---------------- scratch ----------------
__device__ __half g_Ah[(size_t)NODES * HD];
__device__ __half g_Bh[(size_t)NODES * HD];
__device__ float g_agg[(size_t)NODES * HD];
__device__ float g_h0[(size_t)NODES * HD];
__device__ __half g_w2t[HD * HD];
__device__ __half g_whA[HD * 256];
__device__ __half g_wlA[HD * 256];
__device__ __half g_wh1[HD * HD];
__device__ __half g_wl1[HD * HD];
__device__ __half g_wh2[HD * HD];
__device__ __half g_wl2[HD * HD];
__device__ int g_cnt[NODES];
__device__ int g_next[NODES];
__device__ int g_ssrc[MAXEDGES];
__device__ int g_sdst[MAXEDGES];

__global__ __launch_bounds__(THREADS) void fill_kernel(float4* p, float v, int n4) {
    int i = blockIdx.x * blockDim.x + threadIdx.x;
    if (i < n4) p[i] = make_float4(v, v, v, v);
}

__global__ __launch_bounds__(THREADS) void zero_i32(int* p, int n) {
    int i = blockIdx.x * blockDim.x + threadIdx.x;
    if (i < n) p[i] = 0;
}

// ---------------- counting sort by dst (once per launch) ----------------
__global__ __launch_bounds__(THREADS) void hist_kernel(
    const int* __restrict__ ei, int* __restrict__ cnt, int E, int total)
{
    int e = blockIdx.x * blockDim.x + threadIdx.x;
    if (e < total) {
        int d = (e < E) ? ei[E + e] : (e - E);
        atomicAdd(&cnt[d], 1);
    }
}

#define SCAN_T 1024
#define CHUNK (NODES / SCAN_T)   // 64
__global__ __launch_bounds__(SCAN_T) void scan_kernel(
    const int* __restrict__ cnt, int* __restrict__ next)
{
    __shared__ int part[SCAN_T];
    int t = threadIdx.x;
    int base = t * CHUNK;
    int sum = 0;
#pragma unroll 4
    for (int i = 0; i < CHUNK; i++) sum += cnt[base + i];
    part[t] = sum;
    __syncthreads();
    for (int off = 1; off < SCAN_T; off <<= 1) {
        int v = (t >= off) ? part[t - off] : 0;
        __syncthreads();
        part[t] += v;
        __syncthreads();
    }
    int off = part[t] - sum;   // exclusive
#pragma unroll 4
    for (int i = 0; i < CHUNK; i++) {
        next[base + i] = off;
        off += cnt[base + i];
    }
}

__global__ __launch_bounds__(THREADS) void scatter_kernel(
    const int* __restrict__ ei, int* __restrict__ next,
    int* __restrict__ ssrc, int* __restrict__ sdst, int E, int total)
{
    int e = blockIdx.x * blockDim.x + threadIdx.x;
    if (e < total) {
        int s, d;
        if (e < E) { s = ei[e]; d = ei[E + e]; }
        else       { s = e - E; d = s; }
        int pos = atomicAdd(&next[d], 1);
        ssrc[pos] = s;
        sdst[pos] = d;
    }
}

// ---------------- unified weight prep ----------------
__global__ __launch_bounds__(HD) void prep_all_kernel(
    const float* __restrict__ lw1, const float* __restrict__ lw2,
    const float* __restrict__ gw1, const float* __restrict__ gw2,
    __half* __restrict__ whA, __half* __restrict__ wlA,
    __half* __restrict__ w2t,
    __half* __restrict__ wh1, __half* __restrict__ wl1,
    __half* __restrict__ wh2, __half* __restrict__ wl2)
{
    int b = blockIdx.x, n = threadIdx.x;
    if (b < 256) {
        int k = b;
        float v = lw1[k * HD + n];
        __half h = __float2half_rn(v);
        whA[n * 256 + k] = h;
        wlA[n * 256 + k] = __float2half_rn(v - __half2float(h));
    } else if (b < 384) {
        int nn = b - 256;
        w2t[nn * HD + n] = __float2half(lw2[n * HD + nn]);
    } else if (b < 512) {
        int k = b - 384;
        float v = gw1[k * HD + n];
        __half h = __float2half_rn(v);
        wh1[n * HD + k] = h;
        wl1[n * HD + k] = __float2half_rn(v - __half2float(h));
    } else {
        int k = b - 512;
        float v = gw2[k * HD + n];
        __half h = __float2half_rn(v);
        wh2[n * HD + k] = h;
        wl2[n * HD + k] = __float2half_rn(v - __half2float(h));
    }
}

// ---------------- mma / ldmatrix helpers ----------------
__device__ __forceinline__ void mma_fp16(float* d, const uint32_t* a, const uint32_t* b) {
    asm volatile(
        "mma.sync.aligned.m16n8k16.row.col.f32.f16.f16.f32 "
        "{%0,%1,%2,%3}, {%4,%5,%6,%7}, {%8,%9}, {%0,%1,%2,%3};"
        : "+f"(d[0]), "+f"(d[1]), "+f"(d[2]), "+f"(d[3])
        : "r"(a[0]), "r"(a[1]), "r"(a[2]), "r"(a[3]), "r"(b[0]), "r"(b[1]));
}

__device__ __forceinline__ void ldsm_x4(uint32_t addr, uint32_t* r) {
    asm volatile(
        "ldmatrix.sync.aligned.m8n8.x4.shared.b16 {%0,%1,%2,%3}, [%4];"
        : "=r"(r[0]), "=r"(r[1]), "=r"(r[2]), "=r"(r[3]) : "r"(addr));
}

__device__ __forceinline__ void atomic_fmax(float* p, float v) {
    if (v >= 0.f) atomicMax((int*)p, __float_as_int(v));
    else          atomicMin((unsigned int*)p, __float_as_uint(v));
}

__device__ __forceinline__ uint32_t smem_u32(const void* p) {
    uint32_t a;
    asm("{ .reg .u64 t; cvta.to.shared.u64 t, %1; cvt.u32.u64 %0, t; }"
        : "=r"(a) : "l"(p));
    return a;
}

struct LaneC { int rA, kA, rB, kB; };
__device__ __forceinline__ LaneC lane_consts(int lane) {
    LaneC c;
    c.rA = lane & 15;
    c.kA = (lane >> 4) * 4;
    c.rB = (lane & 7) + ((lane >> 4) << 3);
    c.kB = ((lane >> 3) & 1) * 4;
    return c;
}

// 8-kstep MMA block with hi/lo split weights (node GEMMs)
__device__ __forceinline__ void mma_block_hl(
    uint32_t aSA, uint32_t aWH, uint32_t aWL,
    float acc[4][4][4], int warpRow, int warpCol, const LaneC& L)
{
#pragma unroll
    for (int ks = 0; ks < 8; ks++) {
        int base = ks * 8;
        uint32_t bh[4][2], bl[4][2];
#pragma unroll
        for (int p = 0; p < 2; p++) {
            uint32_t r[4];
            uint32_t off = (uint32_t)(((warpCol + p * 16 + L.rB) * TSH + base + L.kB) * 4);
            ldsm_x4(aWH + off, r);
            bh[2*p][0] = r[0]; bh[2*p][1] = r[1];
            bh[2*p+1][0] = r[2]; bh[2*p+1][1] = r[3];
            ldsm_x4(aWL + off, r);
            bl[2*p][0] = r[0]; bl[2*p][1] = r[1];
            bl[2*p+1][0] = r[2]; bl[2*p+1][1] = r[3];
        }
        uint32_t a[4][4];
#pragma unroll
        for (int mf = 0; mf < 4; mf++) {
            uint32_t off = (uint32_t)(((warpRow + mf * 16 + L.rA) * TSH + base + L.kA) * 4);
            ldsm_x4(aSA + off, a[mf]);
        }
#pragma unroll
        for (int mf = 0; mf < 4; mf++)
#pragma unroll
            for (int nf = 0; nf < 4; nf++) {
                mma_fp16(acc[mf][nf], a[mf], bh[nf]);
                mma_fp16(acc[mf][nf], a[mf], bl[nf]);
            }
    }
}

__device__ __forceinline__ void async_w_tile(
    uint32_t dstH, uint32_t dstL,
    const __half* __restrict__ srcH, const __half* __restrict__ srcL,
    int srcStride, int tid)
{
#pragma unroll
    for (int it = 0; it < 8; it++) {
        int lin = tid + it * THREADS;
        int n = lin >> 4, c = lin & 15;
        uint32_t off = (uint32_t)(n * (TSH * 4) + c * 16);
        asm volatile("cp.async.cg.shared.global [%0], [%1], 16;"
                     :: "r"(dstH + off), "l"(srcH + (size_t)n * srcStride + c * 8));
        asm volatile("cp.async.cg.shared.global [%0], [%1], 16;"
                     :: "r"(dstL + off), "l"(srcL + (size_t)n * srcStride + c * 8));
    }
    asm volatile("cp.async.commit_group;" ::: "memory");
}

__device__ __forceinline__ void load_in_tile(
    const float* __restrict__ In, int rowBase, uint32_t* sA, int tid)
{
    int r = tid >> 1, h = tid & 1;
    const float4* src = (const float4*)(In + (size_t)(rowBase + r) * HD + h * 64);
    uint32_t* dst = sA + r * TSH + h * 32;
#pragma unroll
    for (int j = 0; j < 8; j++) {
        float4 v0 = src[j * 2], v1 = src[j * 2 + 1];
        __half2 a = __floats2half2_rn(v0.x, v0.y);
        __half2 b = __floats2half2_rn(v0.z, v0.w);
        __half2 c = __floats2half2_rn(v1.x, v1.y);
        __half2 d = __floats2half2_rn(v1.z, v1.w);
        uint4 u = make_uint4(*(uint32_t*)&a, *(uint32_t*)&b,
                             *(uint32_t*)&c, *(uint32_t*)&d);
        *(uint4*)(dst + j * 4) = u;
    }
}

// ---------------- fused A/B node GEMM (2 CTAs/SM, sequential W) ----------------
__global__ __launch_bounds__(THREADS, 2) void gemm_ab_kernel(
    const float* __restrict__ pos, const float* __restrict__ inx,
    const __half* __restrict__ WHA, const __half* __restrict__ WLA,
    const float* __restrict__ lb1,
    __half* __restrict__ Ah, __half* __restrict__ Bh)
{
    extern __shared__ char sm[];
    float* sBias = (float*)sm;
    uint32_t sb = smem_u32(sm);
    uint32_t aSA = sb + AB_SA;
    uint32_t aWH = sb + AB_WH, aWL = sb + AB_WL;
    uint32_t* sA = (uint32_t*)(sm + AB_SA);

    int tid = threadIdx.x, lane = tid & 31, wid = tid >> 5;
    int rowBase = blockIdx.x * 128;

    async_w_tile(aWH, aWL, WHA + 128, WLA + 128, 256, tid);   // Wp

    if (tid < 128) sBias[tid] = lb1[tid];
    load_in_tile(pos, rowBase, sA, tid);

    asm volatile("cp.async.wait_group 0;" ::: "memory");
    __syncthreads();

    int warpRow = (wid & 1) * 64, warpCol = (wid >> 1) * 32;
    int g = lane >> 2, tg = lane & 3;
    LaneC L = lane_consts(lane);

    float acc[4][4][4];
#pragma unroll
    for (int i = 0; i < 4; i++)
#pragma unroll
        for (int j = 0; j < 4; j++)
#pragma unroll
            for (int q = 0; q < 4; q++) acc[i][j][q] = 0.f;

    mma_block_hl(aSA, aWH, aWL, acc, warpRow, warpCol, L);

#pragma unroll
    for (int mf = 0; mf < 4; mf++) {
        size_t r0 = (size_t)rowBase + warpRow + mf * 16 + g;
#pragma unroll
        for (int nf = 0; nf < 4; nf++) {
            int c0 = warpCol + nf * 8 + 2 * tg;
            __half2 p0 = __floats2half2_rn(acc[mf][nf][0], acc[mf][nf][1]);
            __half2 p1 = __floats2half2_rn(acc[mf][nf][2], acc[mf][nf][3]);
            *(uint32_t*)(Bh + r0 * HD + c0)       = *(uint32_t*)&p0;
            *(uint32_t*)(Bh + (r0 + 8) * HD + c0) = *(uint32_t*)&p1;
            acc[mf][nf][0] = __low2float(p0); acc[mf][nf][1] = __high2float(p0);
            acc[mf][nf][2] = __low2float(p1); acc[mf][nf][3] = __high2float(p1);
        }
    }

    __syncthreads();
    async_w_tile(aWH, aWL, WHA, WLA, 256, tid);        // Wx
    load_in_tile(inx, rowBase, sA, tid);
    asm volatile("cp.async.wait_group 0;" ::: "memory");
    __syncthreads();

    mma_block_hl(aSA, aWH, aWL, acc, warpRow, warpCol, L);

#pragma unroll
    for (int mf = 0; mf < 4; mf++) {
        size_t r0 = (size_t)rowBase + warpRow + mf * 16 + g;
#pragma unroll
        for (int nf = 0; nf < 4; nf++) {
            int c0 = warpCol + nf * 8 + 2 * tg;
            float b0 = sBias[c0], b1 = sBias[c0 + 1];
            __half2 p0 = __floats2half2_rn(acc[mf][nf][0] + b0, acc[mf][nf][1] + b1);
            __half2 p1 = __floats2half2_rn(acc[mf][nf][2] + b0, acc[mf][nf][3] + b1);
            *(uint32_t*)(Ah + r0 * HD + c0)       = *(uint32_t*)&p0;
            *(uint32_t*)(Ah + (r0 + 8) * HD + c0) = *(uint32_t*)&p1;
        }
    }
}

// ---------------- fused global_nn double GEMM ----------------
__global__ __launch_bounds__(THREADS, 2) void gemm_gg_kernel(
    const float* __restrict__ AGG,
    const __half* __restrict__ WH1, const __half* __restrict__ WL1,
    const __half* __restrict__ WH2, const __half* __restrict__ WL2,
    const float* __restrict__ gb1, const float* __restrict__ gb2,
    float* __restrict__ Out)
{
    extern __shared__ char sm[];
    float* sBias1 = (float*)sm;
    float* sBias2 = (float*)(sm + 512);
    uint32_t sb = smem_u32(sm);
    uint32_t aSA = sb + AB_SA;
    uint32_t aWH = sb + AB_WH, aWL = sb + AB_WL;
    uint32_t* sA = (uint32_t*)(sm + AB_SA);

    int tid = threadIdx.x, lane = tid & 31, wid = tid >> 5;
    int rowBase = blockIdx.x * 128;

    async_w_tile(aWH, aWL, WH1, WL1, HD, tid);

    if (tid < 128) { sBias1[tid] = gb1[tid]; sBias2[tid] = gb2[tid]; }
    load_in_tile(AGG, rowBase, sA, tid);

    asm volatile("cp.async.wait_group 0;" ::: "memory");
    __syncthreads();

    int warpRow = (wid & 1) * 64, warpCol = (wid >> 1) * 32;
    int g = lane >> 2, tg = lane & 3;
    LaneC L = lane_consts(lane);

    float acc[4][4][4];
#pragma unroll
    for (int i = 0; i < 4; i++)
#pragma unroll
        for (int j = 0; j < 4; j++)
#pragma unroll
            for (int q = 0; q < 4; q++) acc[i][j][q] = 0.f;

    mma_block_hl(aSA, aWH, aWL, acc, warpRow, warpCol, L);

    __syncthreads();
    async_w_tile(aWH, aWL, WH2, WL2, HD, tid);

#pragma unroll
    for (int mf = 0; mf < 4; mf++) {
        int r0 = warpRow + mf * 16 + g;
#pragma unroll
        for (int nf = 0; nf < 4; nf++) {
            int c0 = warpCol + nf * 8 + 2 * tg;
            float b0 = sBias1[c0], b1 = sBias1[c0 + 1];
            float o0 = fmaxf(acc[mf][nf][0] + b0, 0.f);
            float o1 = fmaxf(acc[mf][nf][1] + b1, 0.f);
            float o2 = fmaxf(acc[mf][nf][2] + b0, 0.f);
            float o3 = fmaxf(acc[mf][nf][3] + b1, 0.f);
            __half2 p0 = __floats2half2_rn(o0, o1);
            __half2 p1 = __floats2half2_rn(o2, o3);
            sA[r0 * TSH + (c0 >> 1)]       = *(uint32_t*)&p0;
            sA[(r0 + 8) * TSH + (c0 >> 1)] = *(uint32_t*)&p1;
            acc[mf][nf][0] = 0.f; acc[mf][nf][1] = 0.f;
            acc[mf][nf][2] = 0.f; acc[mf][nf][3] = 0.f;
        }
    }
    asm volatile("cp.async.wait_group 0;" ::: "memory");
    __syncthreads();

    mma_block_hl(aSA, aWH, aWL, acc, warpRow, warpCol, L);

#pragma unroll
    for (int mf = 0; mf < 4; mf++) {
        size_t r0 = (size_t)rowBase + warpRow + mf * 16 + g;
#pragma unroll
        for (int nf = 0; nf < 4; nf++) {
            int c0 = warpCol + nf * 8 + 2 * tg;
            float b0 = sBias2[c0], b1 = sBias2[c0 + 1];
            *(float2*)(Out + r0 * HD + c0) =
                make_float2(acc[mf][nf][0] + b0, acc[mf][nf][1] + b1);
            *(float2*)(Out + (r0 + 8) * HD + c0) =
                make_float2(acc[mf][nf][2] + b0, acc[mf][nf][3] + b1);
        }
    }
}

// ---------------- persistent edge kernel: 2 CTAs/SM, dedicated stage ----------------
struct GReg {
    uint4 a[4], b[4];
    int d, r;
    bool valid;
};

__device__ __forceinline__ void gather_issue(
    int eBase, int pass, GReg& G,
    const int* __restrict__ ssrc, const int* __restrict__ sdst,
    const __half* __restrict__ A, const __half* __restrict__ B,
    int total, int tid)
{
    int r = pass * 64 + (tid >> 2);
    int q = tid & 3;
    int e = eBase + r;
    G.valid = (e < total);
    int s = 0, d = 0;
    if (G.valid) { s = ssrc[e]; d = sdst[e]; }
    G.d = d; G.r = r;
    const uint4* Ar = (const uint4*)(A + (size_t)s * HD) + q * 4;
    const uint4* Br = (const uint4*)(B + (size_t)d * HD) + q * 4;
#pragma unroll
    for (int i = 0; i < 4; i++) { G.a[i] = Ar[i]; G.b[i] = Br[i]; }
}

__device__ __forceinline__ uint32_t hsubrelu(uint32_t a, uint32_t b) {
    __half2 r = __hmax2(__hsub2(*(__half2*)&a, *(__half2*)&b),
                        __float2half2_rn(0.f));
    return *(uint32_t*)&r;
}

__device__ __forceinline__ void gather_commit(
    const GReg& G, uint32_t* __restrict__ sTn, int* __restrict__ sDn, int tid)
{
    int q = tid & 3;
    if (q == 0) sDn[G.r] = G.valid ? G.d : -1;
    uint32_t* Tr = sTn + G.r * TSH + q * 16;
#pragma unroll
    for (int i = 0; i < 4; i++) {
        uint4 t;
        if (G.valid) {
            t.x = hsubrelu(G.a[i].x, G.b[i].x);
            t.y = hsubrelu(G.a[i].y, G.b[i].y);
            t.z = hsubrelu(G.a[i].z, G.b[i].z);
            t.w = hsubrelu(G.a[i].w, G.b[i].w);
        } else {
            t = make_uint4(0, 0, 0, 0);
        }
        *(uint4*)(Tr + i * 4) = t;
    }
}

__device__ __forceinline__ void mma_half(
    uint32_t aST, uint32_t aSW,
    int ks0, float acc[4][4][4], int rowBase, int colBase, const LaneC& L)
{
#pragma unroll
    for (int ks = 0; ks < 4; ks++) {
        int base = (ks0 + ks) * 8;
        uint32_t b[4][2];
#pragma unroll
        for (int p = 0; p < 2; p++) {
            uint32_t r[4];
            uint32_t off = (uint32_t)(((colBase + p * 16 + L.rB) * TSH + base + L.kB) * 4);
            ldsm_x4(aSW + off, r);
            b[2*p][0] = r[0]; b[2*p][1] = r[1];
            b[2*p+1][0] = r[2]; b[2*p+1][1] = r[3];
        }
        uint32_t a[4][4];
#pragma unroll
        for (int mf = 0; mf < 4; mf++) {
            uint32_t off = (uint32_t)(((rowBase + mf * 16 + L.rA) * TSH + base + L.kA) * 4);
            ldsm_x4(aST + off, a[mf]);
        }
#pragma unroll
        for (int mf = 0; mf < 4; mf++)
#pragma unroll
            for (int nf = 0; nf < 4; nf++)
                mma_fp16(acc[mf][nf], a[mf], b[nf]);
    }
}

__device__ __forceinline__ void stage_frag(
    float* __restrict__ sStage, float acc[4][4][4],
    int colBase, int g, int tg, const float* __restrict__ sBias)
{
#pragma unroll
    for (int mf = 0; mf < 4; mf++) {
        int r0 = mf * 16 + g;
#pragma unroll
        for (int nf = 0; nf < 4; nf++) {
            int c0 = colBase + nf * 8 + 2 * tg;
            float b0 = sBias[c0], b1 = sBias[c0 + 1];
            *(float2*)(sStage + r0 * STG + c0) =
                make_float2(acc[mf][nf][0] + b0, acc[mf][nf][1] + b1);
            *(float2*)(sStage + (r0 + 8) * STG + c0) =
                make_float2(acc[mf][nf][2] + b0, acc[mf][nf][3] + b1);
        }
    }
}

__device__ __forceinline__ void scan_pass(
    const float* __restrict__ sStage, const int* __restrict__ sDst,
    float* __restrict__ agg, int gbase, int tid)
{
    int c = tid & 127;
    int rh = tid >> 7;
    int rstart = rh * 32, rend = rstart + 32;
    int prev = sDst[gbase + rstart];
    float m = -FLT_MAX;
    for (int r = rstart; r < rend; r++) {
        int d = sDst[gbase + r];
        if (d != prev) {
            if (prev >= 0) atomic_fmax(agg + (size_t)prev * HD + c, m);
            m = -FLT_MAX;
            prev = d;
        }
        m = fmaxf(m, sStage[r * STG + c]);
    }
    if (prev >= 0) atomic_fmax(agg + (size_t)prev * HD + c, m);
}

__global__ __launch_bounds__(THREADS, 2) void edge_mma_kernel(
    const int* __restrict__ ssrc, const int* __restrict__ sdst,
    const __half* __restrict__ A, const __half* __restrict__ B,
    const __half* __restrict__ W2T, const float* __restrict__ b2,
    float* __restrict__ agg, int total)
{
    extern __shared__ char smem[];
    int* sDst0 = (int*)smem;                // 512 B
    int* sDst1 = (int*)(smem + 512);        // 512 B
    float* sBias = (float*)(smem + 1024);
    uint32_t* sT = (uint32_t*)(smem + SM_T);
    float* sStage = (float*)(smem + SM_STG);  // dedicated 64-row fp32 stage

    uint32_t sb = smem_u32(smem);
    uint32_t aT = sb + SM_T, aW = sb + SM_W;

    int tid = threadIdx.x;
    int lane = tid & 31, wid = tid >> 5;
    int ntiles = (total + 127) >> 7;

    // One-time: stream W2T (fp16, 32KB) into sW rows
    {
#pragma unroll
        for (int it = 0; it < 8; it++) {
            int linear = tid + it * THREADS;
            int n = linear >> 4, c = linear & 15;
            uint32_t dst = aW + (uint32_t)(n * (TSH * 4) + c * 16);
            const char* src = (const char*)W2T + n * 256 + c * 16;
            asm volatile("cp.async.cg.shared.global [%0], [%1], 16;"
                         :: "r"(dst), "l"(src));
        }
        asm volatile("cp.async.commit_group;" ::: "memory");
    }
    if (tid < 128) sBias[tid] = b2[tid];

    // Prologue: gather first tile into sT / sDst0
    if (blockIdx.x < ntiles) {
        GReg G;
        gather_issue(blockIdx.x * 128, 0, G, ssrc, sdst, A, B, total, tid);
        gather_commit(G, sT, sDst0, tid);
        gather_issue(blockIdx.x * 128, 1, G, ssrc, sdst, A, B, total, tid);
        gather_commit(G, sT, sDst0, tid);
    }
    asm volatile("cp.async.wait_group 0;" ::: "memory");
    __syncthreads();

    int rowBase = (wid & 1) * 64;
    int colBase = (wid >> 1) * 32;
    int g = lane >> 2, tg = lane & 3;
    LaneC L = lane_consts(lane);

    int* sDc = sDst0;
    int* sDn = sDst1;

    for (int ti = blockIdx.x; ti < ntiles; ti += GRID_EDGE) {
        int tn = ti + GRID_EDGE;
        bool hn = tn < ntiles;

        float acc[4][4][4];
#pragma unroll
        for (int i = 0; i < 4; i++)
#pragma unroll
            for (int j = 0; j < 4; j++)
#pragma unroll
                for (int q = 0; q < 4; q++) acc[i][j][q] = 0.f;

        mma_half(aT, aW, 0, acc, rowBase, colBase, L);
        mma_half(aT, aW, 4, acc, rowBase, colBase, L);

        GReg G;
        if (hn) gather_issue(tn * 128, 0, G, ssrc, sdst, A, B, total, tid);

        __syncthreads();   // S1: all MMA reads of sT done (also orders prev scan1)

        // commit next-tile rows 0..63 into sT (free now) while staging pass 0
        if (hn) gather_commit(G, sT, sDn, tid);
        if (rowBase == 0) stage_frag(sStage, acc, colBase, g, tg, sBias);
        if (hn) gather_issue(tn * 128, 1, G, ssrc, sdst, A, B, total, tid);

        __syncthreads();   // S2: stage0 visible

        scan_pass(sStage, sDc, agg, 0, tid);
        if (hn) gather_commit(G, sT, sDn, tid);   // rows 64..127, overlaps scan0

        __syncthreads();   // S3: scan0 done (sStage free), commits done

        if (rowBase == 64) stage_frag(sStage, acc, colBase, g, tg, sBias);

        __syncthreads();   // S4: stage1 visible

        scan_pass(sStage, sDc, agg, 64, tid);
        // scan1 overlaps next tile's MMA (no shared-buffer hazard; next S1 orders
        // scan1 before the next stage0 write to sStage)

        int* tmp = sDc; sDc = sDn; sDn = tmp;
    }
}

// ---------------- launch ----------------
extern "C" void kernel_launch(void* const* d_in, const int* in_sizes, int n_in,
                              void* d_out, int out_size)
{
    (void)n_in; (void)out_size;
    const float* x   = (const float*)d_in[0];
    const float* pos = (const float*)d_in[1];
    const int* ei    = (const int*)d_in[2];
    const float* p[16];
    for (int i = 0; i < 16; i++) p[i] = (const float*)d_in[3 + i];

    int E = in_sizes[2] / 2;
    int total = E + NODES;

    float *AGG, *H0;
    __half *AH, *BH, *W2T, *WHA, *WLA, *WH1, *WL1, *WH2, *WL2;
    int *CNT, *NEXT, *SSRC, *SDST;
    cudaGetSymbolAddress((void**)&AH, g_Ah);
    cudaGetSymbolAddress((void**)&BH, g_Bh);
    cudaGetSymbolAddress((void**)&AGG, g_agg);
    cudaGetSymbolAddress((void**)&H0, g_h0);
    cudaGetSymbolAddress((void**)&W2T, g_w2t);
    cudaGetSymbolAddress((void**)&WHA, g_whA);
    cudaGetSymbolAddress((void**)&WLA, g_wlA);
    cudaGetSymbolAddress((void**)&WH1, g_wh1);
    cudaGetSymbolAddress((void**)&WL1, g_wl1);
    cudaGetSymbolAddress((void**)&WH2, g_wh2);
    cudaGetSymbolAddress((void**)&WL2, g_wl2);
    cudaGetSymbolAddress((void**)&CNT, g_cnt);
    cudaGetSymbolAddress((void**)&NEXT, g_next);
    cudaGetSymbolAddress((void**)&SSRC, g_ssrc);
    cudaGetSymbolAddress((void**)&SDST, g_sdst);

    cudaFuncSetAttribute(edge_mma_kernel, cudaFuncAttributeMaxDynamicSharedMemorySize, EDGE_SMEM);
    cudaFuncSetAttribute(gemm_ab_kernel, cudaFuncAttributeMaxDynamicSharedMemorySize, AB_SMEM);
    cudaFuncSetAttribute(gemm_gg_kernel, cudaFuncAttributeMaxDynamicSharedMemorySize, AB_SMEM);

    int gemmBlocks = NODES / 128;              // 512
    int fillBlocks = (NODES * HD / 4 + THREADS - 1) / THREADS;
    int eBlocks = (total + THREADS - 1) / THREADS;

    // Build dst-sorted edge list once (layer-invariant)
    zero_i32<<<(NODES + THREADS - 1) / THREADS, THREADS>>>(CNT, NODES);
    hist_kernel<<<eBlocks, THREADS>>>(ei, CNT, E, total);
    scan_kernel<<<1, SCAN_T>>>(CNT, NEXT);
    scatter_kernel<<<eBlocks, THREADS>>>(ei, NEXT, SSRC, SDST, E, total);

    for (int layer = 0; layer < 2; layer++) {
        const float* lw1 = p[layer * 8 + 0];
        const float* lb1 = p[layer * 8 + 1];
        const float* lw2 = p[layer * 8 + 2];
        const float* lb2 = p[layer * 8 + 3];
        const float* gw1 = p[layer * 8 + 4];
        const float* gb1 = p[layer * 8 + 5];
        const float* gw2 = p[layer * 8 + 6];
        const float* gb2 = p[layer * 8 + 7];
        const float* inx = (layer == 0) ? x : H0;
        float* outp = (layer == 0) ? H0 : (float*)d_out;

        prep_all_kernel<<<640, HD>>>(lw1, lw2, gw1, gw2,
                                     WHA, WLA, W2T, WH1, WL1, WH2, WL2);

        gemm_ab_kernel<<<gemmBlocks, THREADS, AB_SMEM>>>(
            pos, inx, WHA, WLA, lb1, AH, BH);

        fill_kernel<<<fillBlocks, THREADS>>>((float4*)AGG, -FLT_MAX, NODES * HD / 4);
        edge_mma_kernel<<<GRID_EDGE, THREADS, EDGE_SMEM>>>(
            SSRC, SDST, AH, BH, W2T, lb2, AGG, total);

        gemm_gg_kernel<<<gemmBlocks, THREADS, AB_SMEM>>>(
            AGG, WH1, WL1, WH2, WL2, gb1, gb2, outp);
    }
}

// round 15
// speedup vs baseline: 2.1033x; 1.0044x over previous
#include <cuda_runtime.h>
#include <cuda_fp16.h>
#include <float.h>
#include <stdint.h>

#define NODES 65536
#define HD 128
#define THREADS 256
#define TSH 68                       // uint32 (half2) stride per 128-half row
#define STGH 132                     // fp16 staging stride (halves)
#define MAXEDGES (1048576 + NODES)
#define GRID_EDGE 304

// edge kernel smem map (bytes)
#define HBUF (128 * TSH * 4)         // 34816
#define SM_T 2048
#define SM_W (2048 + HBUF)
#define STG_BYTES (64 * STGH * 2)    // 16896
#define SM_STG0 (2048 + 2 * HBUF)
#define SM_STG1 (SM_STG0 + STG_BYTES)
#define EDGE_SMEM (SM_STG0 + 2 * STG_BYTES)   // 105472 -> 2 CTAs/SM

// node GEMM smem: header(1024) + sA + WH + WL   -> 2 CTAs/SM
#define AB_SA 1024
#define AB_WH (1024 + HBUF)
#define AB_WL (1024 + 2 * HBUF)
#define AB_SMEM (1024 + 3 * HBUF)    // 105472

// ---------------- scratch ----------------
__device__ __half g_Ah[(size_t)NODES * HD];
__device__ __half g_Bh[(size_t)NODES * HD];
__device__ float g_agg[(size_t)NODES * HD];
__device__ float g_h0[(size_t)NODES * HD];
__device__ __half g_w2t[HD * HD];
__device__ __half g_whA[HD * 256];
__device__ __half g_wlA[HD * 256];
__device__ __half g_wh1[HD * HD];
__device__ __half g_wl1[HD * HD];
__device__ __half g_wh2[HD * HD];
__device__ __half g_wl2[HD * HD];
__device__ int g_cnt[NODES];
__device__ int g_next[NODES];
__device__ int g_ssrc[MAXEDGES];
__device__ int g_sdst[MAXEDGES];

__global__ __launch_bounds__(THREADS) void fill_kernel(float4* p, float v, int n4) {
    int i = blockIdx.x * blockDim.x + threadIdx.x;
    if (i < n4) p[i] = make_float4(v, v, v, v);
}

__global__ __launch_bounds__(THREADS) void zero_i32(int* p, int n) {
    int i = blockIdx.x * blockDim.x + threadIdx.x;
    if (i < n) p[i] = 0;
}

// ---------------- counting sort by dst (once per launch) ----------------
__global__ __launch_bounds__(THREADS) void hist_kernel(
    const int* __restrict__ ei, int* __restrict__ cnt, int E, int total)
{
    int e = blockIdx.x * blockDim.x + threadIdx.x;
    if (e < total) {
        int d = (e < E) ? ei[E + e] : (e - E);
        atomicAdd(&cnt[d], 1);
    }
}

#define SCAN_T 1024
#define CHUNK (NODES / SCAN_T)   // 64
__global__ __launch_bounds__(SCAN_T) void scan_kernel(
    const int* __restrict__ cnt, int* __restrict__ next)
{
    __shared__ int part[SCAN_T];
    int t = threadIdx.x;
    int base = t * CHUNK;
    int sum = 0;
#pragma unroll 4
    for (int i = 0; i < CHUNK; i++) sum += cnt[base + i];
    part[t] = sum;
    __syncthreads();
    for (int off = 1; off < SCAN_T; off <<= 1) {
        int v = (t >= off) ? part[t - off] : 0;
        __syncthreads();
        part[t] += v;
        __syncthreads();
    }
    int off = part[t] - sum;   // exclusive
#pragma unroll 4
    for (int i = 0; i < CHUNK; i++) {
        next[base + i] = off;
        off += cnt[base + i];
    }
}

__global__ __launch_bounds__(THREADS) void scatter_kernel(
    const int* __restrict__ ei, int* __restrict__ next,
    int* __restrict__ ssrc, int* __restrict__ sdst, int E, int total)
{
    int e = blockIdx.x * blockDim.x + threadIdx.x;
    if (e < total) {
        int s, d;
        if (e < E) { s = ei[e]; d = ei[E + e]; }
        else       { s = e - E; d = s; }
        int pos = atomicAdd(&next[d], 1);
        ssrc[pos] = s;
        sdst[pos] = d;
    }
}

// ---------------- unified weight prep ----------------
__global__ __launch_bounds__(HD) void prep_all_kernel(
    const float* __restrict__ lw1, const float* __restrict__ lw2,
    const float* __restrict__ gw1, const float* __restrict__ gw2,
    __half* __restrict__ whA, __half* __restrict__ wlA,
    __half* __restrict__ w2t,
    __half* __restrict__ wh1, __half* __restrict__ wl1,
    __half* __restrict__ wh2, __half* __restrict__ wl2)
{
    int b = blockIdx.x, n = threadIdx.x;
    if (b < 256) {
        int k = b;
        float v = lw1[k * HD + n];
        __half h = __float2half_rn(v);
        whA[n * 256 + k] = h;
        wlA[n * 256 + k] = __float2half_rn(v - __half2float(h));
    } else if (b < 384) {
        int nn = b - 256;
        w2t[nn * HD + n] = __float2half(lw2[n * HD + nn]);
    } else if (b < 512) {
        int k = b - 384;
        float v = gw1[k * HD + n];
        __half h = __float2half_rn(v);
        wh1[n * HD + k] = h;
        wl1[n * HD + k] = __float2half_rn(v - __half2float(h));
    } else {
        int k = b - 512;
        float v = gw2[k * HD + n];
        __half h = __float2half_rn(v);
        wh2[n * HD + k] = h;
        wl2[n * HD + k] = __float2half_rn(v - __half2float(h));
    }
}

// ---------------- mma / ldmatrix helpers ----------------
__device__ __forceinline__ void mma_fp16(float* d, const uint32_t* a, const uint32_t* b) {
    asm volatile(
        "mma.sync.aligned.m16n8k16.row.col.f32.f16.f16.f32 "
        "{%0,%1,%2,%3}, {%4,%5,%6,%7}, {%8,%9}, {%0,%1,%2,%3};"
        : "+f"(d[0]), "+f"(d[1]), "+f"(d[2]), "+f"(d[3])
        : "r"(a[0]), "r"(a[1]), "r"(a[2]), "r"(a[3]), "r"(b[0]), "r"(b[1]));
}

__device__ __forceinline__ void ldsm_x4(uint32_t addr, uint32_t* r) {
    asm volatile(
        "ldmatrix.sync.aligned.m8n8.x4.shared.b16 {%0,%1,%2,%3}, [%4];"
        : "=r"(r[0]), "=r"(r[1]), "=r"(r[2]), "=r"(r[3]) : "r"(addr));
}

__device__ __forceinline__ void atomic_fmax(float* p, float v) {
    if (v >= 0.f) atomicMax((int*)p, __float_as_int(v));
    else          atomicMin((unsigned int*)p, __float_as_uint(v));
}

__device__ __forceinline__ uint32_t smem_u32(const void* p) {
    uint32_t a;
    asm("{ .reg .u64 t; cvta.to.shared.u64 t, %1; cvt.u32.u64 %0, t; }"
        : "=r"(a) : "l"(p));
    return a;
}

struct LaneC { int rA, kA, rB, kB; };
__device__ __forceinline__ LaneC lane_consts(int lane) {
    LaneC c;
    c.rA = lane & 15;
    c.kA = (lane >> 4) * 4;
    c.rB = (lane & 7) + ((lane >> 4) << 3);
    c.kB = ((lane >> 3) & 1) * 4;
    return c;
}

// 8-kstep MMA block with hi/lo split weights (node GEMMs)
__device__ __forceinline__ void mma_block_hl(
    uint32_t aSA, uint32_t aWH, uint32_t aWL,
    float acc[4][4][4], int warpRow, int warpCol, const LaneC& L)
{
#pragma unroll
    for (int ks = 0; ks < 8; ks++) {
        int base = ks * 8;
        uint32_t bh[4][2], bl[4][2];
#pragma unroll
        for (int p = 0; p < 2; p++) {
            uint32_t r[4];
            uint32_t off = (uint32_t)(((warpCol + p * 16 + L.rB) * TSH + base + L.kB) * 4);
            ldsm_x4(aWH + off, r);
            bh[2*p][0] = r[0]; bh[2*p][1] = r[1];
            bh[2*p+1][0] = r[2]; bh[2*p+1][1] = r[3];
            ldsm_x4(aWL + off, r);
            bl[2*p][0] = r[0]; bl[2*p][1] = r[1];
            bl[2*p+1][0] = r[2]; bl[2*p+1][1] = r[3];
        }
        uint32_t a[4][4];
#pragma unroll
        for (int mf = 0; mf < 4; mf++) {
            uint32_t off = (uint32_t)(((warpRow + mf * 16 + L.rA) * TSH + base + L.kA) * 4);
            ldsm_x4(aSA + off, a[mf]);
        }
#pragma unroll
        for (int mf = 0; mf < 4; mf++)
#pragma unroll
            for (int nf = 0; nf < 4; nf++) {
                mma_fp16(acc[mf][nf], a[mf], bh[nf]);
                mma_fp16(acc[mf][nf], a[mf], bl[nf]);
            }
    }
}

__device__ __forceinline__ void async_w_tile(
    uint32_t dstH, uint32_t dstL,
    const __half* __restrict__ srcH, const __half* __restrict__ srcL,
    int srcStride, int tid)
{
#pragma unroll
    for (int it = 0; it < 8; it++) {
        int lin = tid + it * THREADS;
        int n = lin >> 4, c = lin & 15;
        uint32_t off = (uint32_t)(n * (TSH * 4) + c * 16);
        asm volatile("cp.async.cg.shared.global [%0], [%1], 16;"
                     :: "r"(dstH + off), "l"(srcH + (size_t)n * srcStride + c * 8));
        asm volatile("cp.async.cg.shared.global [%0], [%1], 16;"
                     :: "r"(dstL + off), "l"(srcL + (size_t)n * srcStride + c * 8));
    }
    asm volatile("cp.async.commit_group;" ::: "memory");
}

__device__ __forceinline__ void load_in_tile(
    const float* __restrict__ In, int rowBase, uint32_t* sA, int tid)
{
    int r = tid >> 1, h = tid & 1;
    const float4* src = (const float4*)(In + (size_t)(rowBase + r) * HD + h * 64);
    uint32_t* dst = sA + r * TSH + h * 32;
#pragma unroll
    for (int j = 0; j < 8; j++) {
        float4 v0 = src[j * 2], v1 = src[j * 2 + 1];
        __half2 a = __floats2half2_rn(v0.x, v0.y);
        __half2 b = __floats2half2_rn(v0.z, v0.w);
        __half2 c = __floats2half2_rn(v1.x, v1.y);
        __half2 d = __floats2half2_rn(v1.z, v1.w);
        uint4 u = make_uint4(*(uint32_t*)&a, *(uint32_t*)&b,
                             *(uint32_t*)&c, *(uint32_t*)&d);
        *(uint4*)(dst + j * 4) = u;
    }
}

// ---------------- fused A/B node GEMM (2 CTAs/SM, sequential W) ----------------
__global__ __launch_bounds__(THREADS, 2) void gemm_ab_kernel(
    const float* __restrict__ pos, const float* __restrict__ inx,
    const __half* __restrict__ WHA, const __half* __restrict__ WLA,
    const float* __restrict__ lb1,
    __half* __restrict__ Ah, __half* __restrict__ Bh)
{
    extern __shared__ char sm[];
    float* sBias = (float*)sm;
    uint32_t sb = smem_u32(sm);
    uint32_t aSA = sb + AB_SA;
    uint32_t aWH = sb + AB_WH, aWL = sb + AB_WL;
    uint32_t* sA = (uint32_t*)(sm + AB_SA);

    int tid = threadIdx.x, lane = tid & 31, wid = tid >> 5;
    int rowBase = blockIdx.x * 128;

    async_w_tile(aWH, aWL, WHA + 128, WLA + 128, 256, tid);   // Wp

    if (tid < 128) sBias[tid] = lb1[tid];
    load_in_tile(pos, rowBase, sA, tid);

    asm volatile("cp.async.wait_group 0;" ::: "memory");
    __syncthreads();

    int warpRow = (wid & 1) * 64, warpCol = (wid >> 1) * 32;
    int g = lane >> 2, tg = lane & 3;
    LaneC L = lane_consts(lane);

    float acc[4][4][4];
#pragma unroll
    for (int i = 0; i < 4; i++)
#pragma unroll
        for (int j = 0; j < 4; j++)
#pragma unroll
            for (int q = 0; q < 4; q++) acc[i][j][q] = 0.f;

    mma_block_hl(aSA, aWH, aWL, acc, warpRow, warpCol, L);

#pragma unroll
    for (int mf = 0; mf < 4; mf++) {
        size_t r0 = (size_t)rowBase + warpRow + mf * 16 + g;
#pragma unroll
        for (int nf = 0; nf < 4; nf++) {
            int c0 = warpCol + nf * 8 + 2 * tg;
            __half2 p0 = __floats2half2_rn(acc[mf][nf][0], acc[mf][nf][1]);
            __half2 p1 = __floats2half2_rn(acc[mf][nf][2], acc[mf][nf][3]);
            *(uint32_t*)(Bh + r0 * HD + c0)       = *(uint32_t*)&p0;
            *(uint32_t*)(Bh + (r0 + 8) * HD + c0) = *(uint32_t*)&p1;
            acc[mf][nf][0] = __low2float(p0); acc[mf][nf][1] = __high2float(p0);
            acc[mf][nf][2] = __low2float(p1); acc[mf][nf][3] = __high2float(p1);
        }
    }

    __syncthreads();
    async_w_tile(aWH, aWL, WHA, WLA, 256, tid);        // Wx
    load_in_tile(inx, rowBase, sA, tid);
    asm volatile("cp.async.wait_group 0;" ::: "memory");
    __syncthreads();

    mma_block_hl(aSA, aWH, aWL, acc, warpRow, warpCol, L);

#pragma unroll
    for (int mf = 0; mf < 4; mf++) {
        size_t r0 = (size_t)rowBase + warpRow + mf * 16 + g;
#pragma unroll
        for (int nf = 0; nf < 4; nf++) {
            int c0 = warpCol + nf * 8 + 2 * tg;
            float b0 = sBias[c0], b1 = sBias[c0 + 1];
            __half2 p0 = __floats2half2_rn(acc[mf][nf][0] + b0, acc[mf][nf][1] + b1);
            __half2 p1 = __floats2half2_rn(acc[mf][nf][2] + b0, acc[mf][nf][3] + b1);
            *(uint32_t*)(Ah + r0 * HD + c0)       = *(uint32_t*)&p0;
            *(uint32_t*)(Ah + (r0 + 8) * HD + c0) = *(uint32_t*)&p1;
        }
    }
}

// ---------------- fused global_nn double GEMM ----------------
__global__ __launch_bounds__(THREADS, 2) void gemm_gg_kernel(
    const float* __restrict__ AGG,
    const __half* __restrict__ WH1, const __half* __restrict__ WL1,
    const __half* __restrict__ WH2, const __half* __restrict__ WL2,
    const float* __restrict__ gb1, const float* __restrict__ gb2,
    float* __restrict__ Out)
{
    extern __shared__ char sm[];
    float* sBias1 = (float*)sm;
    float* sBias2 = (float*)(sm + 512);
    uint32_t sb = smem_u32(sm);
    uint32_t aSA = sb + AB_SA;
    uint32_t aWH = sb + AB_WH, aWL = sb + AB_WL;
    uint32_t* sA = (uint32_t*)(sm + AB_SA);

    int tid = threadIdx.x, lane = tid & 31, wid = tid >> 5;
    int rowBase = blockIdx.x * 128;

    async_w_tile(aWH, aWL, WH1, WL1, HD, tid);

    if (tid < 128) { sBias1[tid] = gb1[tid]; sBias2[tid] = gb2[tid]; }
    load_in_tile(AGG, rowBase, sA, tid);

    asm volatile("cp.async.wait_group 0;" ::: "memory");
    __syncthreads();

    int warpRow = (wid & 1) * 64, warpCol = (wid >> 1) * 32;
    int g = lane >> 2, tg = lane & 3;
    LaneC L = lane_consts(lane);

    float acc[4][4][4];
#pragma unroll
    for (int i = 0; i < 4; i++)
#pragma unroll
        for (int j = 0; j < 4; j++)
#pragma unroll
            for (int q = 0; q < 4; q++) acc[i][j][q] = 0.f;

    mma_block_hl(aSA, aWH, aWL, acc, warpRow, warpCol, L);

    __syncthreads();
    async_w_tile(aWH, aWL, WH2, WL2, HD, tid);

#pragma unroll
    for (int mf = 0; mf < 4; mf++) {
        int r0 = warpRow + mf * 16 + g;
#pragma unroll
        for (int nf = 0; nf < 4; nf++) {
            int c0 = warpCol + nf * 8 + 2 * tg;
            float b0 = sBias1[c0], b1 = sBias1[c0 + 1];
            float o0 = fmaxf(acc[mf][nf][0] + b0, 0.f);
            float o1 = fmaxf(acc[mf][nf][1] + b1, 0.f);
            float o2 = fmaxf(acc[mf][nf][2] + b0, 0.f);
            float o3 = fmaxf(acc[mf][nf][3] + b1, 0.f);
            __half2 p0 = __floats2half2_rn(o0, o1);
            __half2 p1 = __floats2half2_rn(o2, o3);
            sA[r0 * TSH + (c0 >> 1)]       = *(uint32_t*)&p0;
            sA[(r0 + 8) * TSH + (c0 >> 1)] = *(uint32_t*)&p1;
            acc[mf][nf][0] = 0.f; acc[mf][nf][1] = 0.f;
            acc[mf][nf][2] = 0.f; acc[mf][nf][3] = 0.f;
        }
    }
    asm volatile("cp.async.wait_group 0;" ::: "memory");
    __syncthreads();

    mma_block_hl(aSA, aWH, aWL, acc, warpRow, warpCol, L);

#pragma unroll
    for (int mf = 0; mf < 4; mf++) {
        size_t r0 = (size_t)rowBase + warpRow + mf * 16 + g;
#pragma unroll
        for (int nf = 0; nf < 4; nf++) {
            int c0 = warpCol + nf * 8 + 2 * tg;
            float b0 = sBias2[c0], b1 = sBias2[c0 + 1];
            *(float2*)(Out + r0 * HD + c0) =
                make_float2(acc[mf][nf][0] + b0, acc[mf][nf][1] + b1);
            *(float2*)(Out + (r0 + 8) * HD + c0) =
                make_float2(acc[mf][nf][2] + b0, acc[mf][nf][3] + b1);
        }
    }
}

// ---------------- persistent edge kernel: 2 CTAs/SM, fp16 dual staging ----------------
struct GReg {
    uint4 a[4], b[4];
    int d, r;
    bool valid;
};

__device__ __forceinline__ void gather_issue(
    int eBase, int pass, GReg& G,
    const int* __restrict__ ssrc, const int* __restrict__ sdst,
    const __half* __restrict__ A, const __half* __restrict__ B,
    int total, int tid)
{
    int r = pass * 64 + (tid >> 2);
    int q = tid & 3;
    int e = eBase + r;
    G.valid = (e < total);
    int s = 0, d = 0;
    if (G.valid) { s = ssrc[e]; d = sdst[e]; }
    G.d = d; G.r = r;
    const uint4* Ar = (const uint4*)(A + (size_t)s * HD) + q * 4;
    const uint4* Br = (const uint4*)(B + (size_t)d * HD) + q * 4;
#pragma unroll
    for (int i = 0; i < 4; i++) { G.a[i] = Ar[i]; G.b[i] = Br[i]; }
}

__device__ __forceinline__ uint32_t hsubrelu(uint32_t a, uint32_t b) {
    __half2 r = __hmax2(__hsub2(*(__half2*)&a, *(__half2*)&b),
                        __float2half2_rn(0.f));
    return *(uint32_t*)&r;
}

__device__ __forceinline__ void gather_commit(
    const GReg& G, uint32_t* __restrict__ sTn, int* __restrict__ sDn, int tid)
{
    int q = tid & 3;
    if (q == 0) sDn[G.r] = G.valid ? G.d : -1;
    uint32_t* Tr = sTn + G.r * TSH + q * 16;
#pragma unroll
    for (int i = 0; i < 4; i++) {
        uint4 t;
        if (G.valid) {
            t.x = hsubrelu(G.a[i].x, G.b[i].x);
            t.y = hsubrelu(G.a[i].y, G.b[i].y);
            t.z = hsubrelu(G.a[i].z, G.b[i].z);
            t.w = hsubrelu(G.a[i].w, G.b[i].w);
        } else {
            t = make_uint4(0, 0, 0, 0);
        }
        *(uint4*)(Tr + i * 4) = t;
    }
}

__device__ __forceinline__ void mma_half(
    uint32_t aST, uint32_t aSW,
    int ks0, float acc[4][4][4], int rowBase, int colBase, const LaneC& L)
{
#pragma unroll
    for (int ks = 0; ks < 4; ks++) {
        int base = (ks0 + ks) * 8;
        uint32_t b[4][2];
#pragma unroll
        for (int p = 0; p < 2; p++) {
            uint32_t r[4];
            uint32_t off = (uint32_t)(((colBase + p * 16 + L.rB) * TSH + base + L.kB) * 4);
            ldsm_x4(aSW + off, r);
            b[2*p][0] = r[0]; b[2*p][1] = r[1];
            b[2*p+1][0] = r[2]; b[2*p+1][1] = r[3];
        }
        uint32_t a[4][4];
#pragma unroll
        for (int mf = 0; mf < 4; mf++) {
            uint32_t off = (uint32_t)(((rowBase + mf * 16 + L.rA) * TSH + base + L.kA) * 4);
            ldsm_x4(aST + off, a[mf]);
        }
#pragma unroll
        for (int mf = 0; mf < 4; mf++)
#pragma unroll
            for (int nf = 0; nf < 4; nf++)
                mma_fp16(acc[mf][nf], a[mf], b[nf]);
    }
}

// stage warp's 64x32 block (local rows 0..63) + bias into fp16 buffer.
// fp16 rounding here is numerically identical to the downstream gemm_gg input
// conversion (rounding is monotonic, so max(round(x)) == round(max(x))).
__device__ __forceinline__ void stage_frag_h(
    __half* __restrict__ sStage, float acc[4][4][4],
    int colBase, int g, int tg, const float* __restrict__ sBias)
{
#pragma unroll
    for (int mf = 0; mf < 4; mf++) {
        int r0 = mf * 16 + g;
#pragma unroll
        for (int nf = 0; nf < 4; nf++) {
            int c0 = colBase + nf * 8 + 2 * tg;
            float b0 = sBias[c0], b1 = sBias[c0 + 1];
            __half2 p0 = __floats2half2_rn(acc[mf][nf][0] + b0, acc[mf][nf][1] + b1);
            __half2 p1 = __floats2half2_rn(acc[mf][nf][2] + b0, acc[mf][nf][3] + b1);
            *(uint32_t*)(sStage + r0 * STGH + c0)       = *(uint32_t*)&p0;
            *(uint32_t*)(sStage + (r0 + 8) * STGH + c0) = *(uint32_t*)&p1;
        }
    }
}

// full 128-row segmented column-max: 2 threads/col, 64 serial rows each
__device__ __forceinline__ void scan_full(
    const __half* __restrict__ s0, const __half* __restrict__ s1,
    const int* __restrict__ sDst, float* __restrict__ agg, int tid)
{
    int c = tid & 127;
    int h = tid >> 7;
    const __half* buf = h ? s1 : s0;
    int gbase = h * 64;
    int prev = sDst[gbase];
    float m = -FLT_MAX;
    for (int r = 0; r < 64; r++) {
        int d = sDst[gbase + r];
        if (d != prev) {
            if (prev >= 0) atomic_fmax(agg + (size_t)prev * HD + c, m);
            m = -FLT_MAX;
            prev = d;
        }
        m = fmaxf(m, __half2float(buf[r * STGH + c]));
    }
    if (prev >= 0) atomic_fmax(agg + (size_t)prev * HD + c, m);
}

__global__ __launch_bounds__(THREADS, 2) void edge_mma_kernel(
    const int* __restrict__ ssrc, const int* __restrict__ sdst,
    const __half* __restrict__ A, const __half* __restrict__ B,
    const __half* __restrict__ W2T, const float* __restrict__ b2,
    float* __restrict__ agg, int total)
{
    extern __shared__ char smem[];
    int* sDst0 = (int*)smem;
    int* sDst1 = (int*)(smem + 512);
    float* sBias = (float*)(smem + 1024);
    uint32_t* sT = (uint32_t*)(smem + SM_T);
    __half* sStg0 = (__half*)(smem + SM_STG0);
    __half* sStg1 = (__half*)(smem + SM_STG1);

    uint32_t sb = smem_u32(smem);
    uint32_t aT = sb + SM_T, aW = sb + SM_W;

    int tid = threadIdx.x;
    int lane = tid & 31, wid = tid >> 5;
    int ntiles = (total + 127) >> 7;

    // One-time: stream W2T (fp16, 32KB) into sW rows
    {
#pragma unroll
        for (int it = 0; it < 8; it++) {
            int linear = tid + it * THREADS;
            int n = linear >> 4, c = linear & 15;
            uint32_t dst = aW + (uint32_t)(n * (TSH * 4) + c * 16);
            const char* src = (const char*)W2T + n * 256 + c * 16;
            asm volatile("cp.async.cg.shared.global [%0], [%1], 16;"
                         :: "r"(dst), "l"(src));
        }
        asm volatile("cp.async.commit_group;" ::: "memory");
    }
    if (tid < 128) sBias[tid] = b2[tid];

    // Prologue: gather first tile into sT / sDst0
    if (blockIdx.x < ntiles) {
        GReg G;
        gather_issue(blockIdx.x * 128, 0, G, ssrc, sdst, A, B, total, tid);
        gather_commit(G, sT, sDst0, tid);
        gather_issue(blockIdx.x * 128, 1, G, ssrc, sdst, A, B, total, tid);
        gather_commit(G, sT, sDst0, tid);
    }
    asm volatile("cp.async.wait_group 0;" ::: "memory");
    __syncthreads();

    int rowBase = (wid & 1) * 64;
    int colBase = (wid >> 1) * 32;
    int g = lane >> 2, tg = lane & 3;
    LaneC L = lane_consts(lane);

    int* sDc = sDst0;
    int* sDn = sDst1;
    __half* myStg = rowBase ? sStg1 : sStg0;

    for (int ti = blockIdx.x; ti < ntiles; ti += GRID_EDGE) {
        int tn = ti + GRID_EDGE;
        bool hn = tn < ntiles;

        float acc[4][4][4];
#pragma unroll
        for (int i = 0; i < 4; i++)
#pragma unroll
            for (int j = 0; j < 4; j++)
#pragma unroll
                for (int q = 0; q < 4; q++) acc[i][j][q] = 0.f;

        mma_half(aT, aW, 0, acc, rowBase, colBase, L);
        mma_half(aT, aW, 4, acc, rowBase, colBase, L);

        GReg G;
        if (hn) gather_issue(tn * 128, 0, G, ssrc, sdst, A, B, total, tid);

        __syncthreads();   // S1: MMA reads of sT done (also orders prev scan)

        if (hn) gather_commit(G, sT, sDn, tid);          // next rows 0..63
        stage_frag_h(myStg, acc, colBase, g, tg, sBias); // both halves concurrently
        if (hn) gather_issue(tn * 128, 1, G, ssrc, sdst, A, B, total, tid);

        __syncthreads();   // S2: stages visible

        scan_full(sStg0, sStg1, sDc, agg, tid);
        if (hn) gather_commit(G, sT, sDn, tid);          // rows 64..127, overlaps scan

        __syncthreads();   // S3: scan done (bufs free), commits done

        int* tmp = sDc; sDc = sDn; sDn = tmp;
    }
}

// ---------------- launch ----------------
extern "C" void kernel_launch(void* const* d_in, const int* in_sizes, int n_in,
                              void* d_out, int out_size)
{
    (void)n_in; (void)out_size;
    const float* x   = (const float*)d_in[0];
    const float* pos = (const float*)d_in[1];
    const int* ei    = (const int*)d_in[2];
    const float* p[16];
    for (int i = 0; i < 16; i++) p[i] = (const float*)d_in[3 + i];

    int E = in_sizes[2] / 2;
    int total = E + NODES;

    float *AGG, *H0;
    __half *AH, *BH, *W2T, *WHA, *WLA, *WH1, *WL1, *WH2, *WL2;
    int *CNT, *NEXT, *SSRC, *SDST;
    cudaGetSymbolAddress((void**)&AH, g_Ah);
    cudaGetSymbolAddress((void**)&BH, g_Bh);
    cudaGetSymbolAddress((void**)&AGG, g_agg);
    cudaGetSymbolAddress((void**)&H0, g_h0);
    cudaGetSymbolAddress((void**)&W2T, g_w2t);
    cudaGetSymbolAddress((void**)&WHA, g_whA);
    cudaGetSymbolAddress((void**)&WLA, g_wlA);
    cudaGetSymbolAddress((void**)&WH1, g_wh1);
    cudaGetSymbolAddress((void**)&WL1, g_wl1);
    cudaGetSymbolAddress((void**)&WH2, g_wh2);
    cudaGetSymbolAddress((void**)&WL2, g_wl2);
    cudaGetSymbolAddress((void**)&CNT, g_cnt);
    cudaGetSymbolAddress((void**)&NEXT, g_next);
    cudaGetSymbolAddress((void**)&SSRC, g_ssrc);
    cudaGetSymbolAddress((void**)&SDST, g_sdst);

    cudaFuncSetAttribute(edge_mma_kernel, cudaFuncAttributeMaxDynamicSharedMemorySize, EDGE_SMEM);
    cudaFuncSetAttribute(gemm_ab_kernel, cudaFuncAttributeMaxDynamicSharedMemorySize, AB_SMEM);
    cudaFuncSetAttribute(gemm_gg_kernel, cudaFuncAttributeMaxDynamicSharedMemorySize, AB_SMEM);

    int gemmBlocks = NODES / 128;              // 512
    int fillBlocks = (NODES * HD / 4 + THREADS - 1) / THREADS;
    int eBlocks = (total + THREADS - 1) / THREADS;

    // Build dst-sorted edge list once (layer-invariant)
    zero_i32<<<(NODES + THREADS - 1) / THREADS, THREADS>>>(CNT, NODES);
    hist_kernel<<<eBlocks, THREADS>>>(ei, CNT, E, total);
    scan_kernel<<<1, SCAN_T>>>(CNT, NEXT);
    scatter_kernel<<<eBlocks, THREADS>>>(ei, NEXT, SSRC, SDST, E, total);

    for (int layer = 0; layer < 2; layer++) {
        const float* lw1 = p[layer * 8 + 0];
        const float* lb1 = p[layer * 8 + 1];
        const float* lw2 = p[layer * 8 + 2];
        const float* lb2 = p[layer * 8 + 3];
        const float* gw1 = p[layer * 8 + 4];
        const float* gb1 = p[layer * 8 + 5];
        const float* gw2 = p[layer * 8 + 6];
        const float* gb2 = p[layer * 8 + 7];
        const float* inx = (layer == 0) ? x : H0;
        float* outp = (layer == 0) ? H0 : (float*)d_out;

        prep_all_kernel<<<640, HD>>>(lw1, lw2, gw1, gw2,
                                     WHA, WLA, W2T, WH1, WL1, WH2, WL2);

        gemm_ab_kernel<<<gemmBlocks, THREADS, AB_SMEM>>>(
            pos, inx, WHA, WLA, lb1, AH, BH);

        fill_kernel<<<fillBlocks, THREADS>>>((float4*)AGG, -FLT_MAX, NODES * HD / 4);
        edge_mma_kernel<<<GRID_EDGE, THREADS, EDGE_SMEM>>>(
            SSRC, SDST, AH, BH, W2T, lb2, AGG, total);

        gemm_gg_kernel<<<gemmBlocks, THREADS, AB_SMEM>>>(
            AGG, WH1, WL1, WH2, WL2, gb1, gb2, outp);
    }
}